// round 9
// baseline (speedup 1.0000x reference)
#include <cuda_runtime.h>
#include <cuda_fp16.h>
#include <math.h>
#include <stdint.h>

#define BB 8
#define SS 4096
#define EE 2048
#define DD 128
#define MM (BB*SS)   // 32768

#define LOG2E 1.44269504088896340736f

__device__ __half g_xh[MM*EE];
__device__ __half g_xl[MM*EE];
__device__ __half g_qh[MM*DD];    // q scaled by log2e
__device__ __half g_ql[MM*DD];
__device__ __half g_kh[MM*DD];
__device__ __half g_kl[MM*DD];
__device__ __half g_vth[MM*DD];   // v transposed [b][d][s]
__device__ __half g_wth[3*DD*EE]; // W transposed hi (Wq pre-scaled by log2e)
__device__ __half g_wtl[3*DD*EE];

typedef unsigned long long u64;

__device__ __forceinline__ uint32_t pack_h2(float a, float b) {
    __half ha = __float2half_rn(a), hb = __float2half_rn(b);
    return ((uint32_t)__half_as_ushort(hb) << 16) | (uint32_t)__half_as_ushort(ha);
}
__device__ __forceinline__ uint32_t cvt_h2(float a, float b) {
    uint32_t r;
    asm("cvt.rn.f16x2.f32 %0, %1, %2;" : "=r"(r) : "f"(b), "f"(a));
    return r;
}
__device__ __forceinline__ uint32_t smem_u32(const void* p) {
    uint32_t a;
    asm("{ .reg .u64 t; cvta.to.shared.u64 t, %1; cvt.u32.u64 %0, t; }" : "=r"(a) : "l"(p));
    return a;
}
__device__ __forceinline__ float ex2(float x) {
    float r; asm("ex2.approx.f32 %0, %1;" : "=f"(r) : "f"(x)); return r;
}

__device__ __forceinline__ void cp16(uint32_t dst, const void* src) {
    asm volatile("cp.async.cg.shared.global [%0], [%1], 16;" :: "r"(dst), "l"(src));
}
#define CP_COMMIT() asm volatile("cp.async.commit_group;" ::: "memory")
#define CP_WAIT0()  asm volatile("cp.async.wait_group 0;" ::: "memory")

__device__ __forceinline__ void ldsm4(uint32_t r[4], uint32_t addr) {
    asm volatile("ldmatrix.sync.aligned.m8n8.x4.shared.b16 {%0,%1,%2,%3}, [%4];"
        : "=r"(r[0]), "=r"(r[1]), "=r"(r[2]), "=r"(r[3]) : "r"(addr));
}
__device__ __forceinline__ void mma16816(float c[4], const uint32_t a[4],
                                          uint32_t b0, uint32_t b1) {
    asm volatile("mma.sync.aligned.m16n8k16.row.col.f32.f16.f16.f32 "
        "{%0,%1,%2,%3}, {%4,%5,%6,%7}, {%8,%9}, {%0,%1,%2,%3};"
        : "+f"(c[0]), "+f"(c[1]), "+f"(c[2]), "+f"(c[3])
        : "r"(a[0]), "r"(a[1]), "r"(a[2]), "r"(a[3]), "r"(b0), "r"(b1));
}

// ============================================================================
// Kernel 0a: split x into fp16 hi/lo.
// ============================================================================
__global__ __launch_bounds__(256) void split_x(const float* __restrict__ x)
{
    long long idx = ((long long)blockIdx.x * 256 + threadIdx.x) * 4;
    float4 v = *(const float4*)(x + idx);
    float h0 = __half2float(__float2half_rn(v.x));
    float h1 = __half2float(__float2half_rn(v.y));
    float h2 = __half2float(__float2half_rn(v.z));
    float h3 = __half2float(__float2half_rn(v.w));
    *(uint2*)&g_xh[idx] = make_uint2(pack_h2(h0, h1), pack_h2(h2, h3));
    *(uint2*)&g_xl[idx] = make_uint2(pack_h2(v.x - h0, v.y - h1),
                                     pack_h2(v.z - h2, v.w - h3));
}

// ============================================================================
// Kernel 0b: split W (transposed fp16 hi/lo). Wq pre-scaled by log2e.
// ============================================================================
__global__ __launch_bounds__(256) void split_w(
    const float* __restrict__ Wq, const float* __restrict__ Wk,
    const float* __restrict__ Wv)
{
    int idx = blockIdx.x * 256 + threadIdx.x;
    int y = idx >> 18;
    int rem = idx & ((DD*EE) - 1);
    int d = rem >> 11;
    int e = rem & (EE - 1);
    const float* W = (y == 0) ? Wq : (y == 1) ? Wk : Wv;
    float v = W[(long long)e * DD + d];
    if (y == 0) v *= LOG2E;
    __half h = __float2half_rn(v);
    g_wth[idx] = h;
    g_wtl[idx] = __float2half_rn(v - __half2float(h));
}

// ============================================================================
// Kernel 1: QKV projection via mma.sync.
//   q,k: 3 terms;  v: 1 term (xh*Wvh — v is consumed fp16 downstream).
// ============================================================================
#define BK 64
#define XSTR 72
#define SXH 0
#define SXL (64*XSTR*2)
#define SWH (2*64*XSTR*2)
#define SWL (SWH + 128*XSTR*2)
#define QBUF (SWL + 128*XSTR*2)     // 55296
#define QKV_SMEM (2*QBUF)           // 110592
#define NCHUNK (EE/BK)              // 32

__device__ __forceinline__ void qkv_ld(uint32_t smem, int bufoff, int y,
                                       int m0, int kt, int tid) {
    long long xbase = (long long)m0 * EE + (long long)kt * BK;
    #pragma unroll
    for (int j = 0; j < 4; j++) {
        int idx = tid + j * 256;
        int hl = idx >> 9;
        int rem = idx & 511;
        int row = rem >> 3, c = rem & 7;
        const __half* src = (hl ? g_xl : g_xh) + xbase + (long long)row * EE + c * 8;
        cp16(smem + bufoff + (hl ? SXL : SXH) + row * (XSTR*2) + c * 16, src);
    }
    long long wbase = (long long)y * DD * EE + (long long)kt * BK;
    #pragma unroll
    for (int j = 0; j < 8; j++) {
        int idx = tid + j * 256;
        int hl = idx >> 10;
        int rem = idx & 1023;
        int n = rem >> 3, c = rem & 7;
        const __half* src = (hl ? g_wtl : g_wth) + wbase + (long long)n * EE + c * 8;
        cp16(smem + bufoff + (hl ? SWL : SWH) + n * (XSTR*2) + c * 16, src);
    }
}

__global__ __launch_bounds__(256, 2) void qkv_mma(
    const float* __restrict__ bq, const float* __restrict__ bk,
    const float* __restrict__ bv)
{
    extern __shared__ char sm[];
    const uint32_t smem = smem_u32(sm);
    const int tid = threadIdx.x;
    const int w = tid >> 5;
    const int l = tid & 31;
    const int y = blockIdx.y;
    const int m0 = blockIdx.x * 64;

    const int wm = (w >> 1) * 16;
    const int wn = (w & 1) * 64;
    const uint32_t brow  = (l & 7) + ((l >> 4) & 1) * 8;
    const uint32_t bcsel = ((l >> 3) & 1) * 16;

    float of[8][4];
    #pragma unroll
    for (int n = 0; n < 8; n++)
        #pragma unroll
        for (int c = 0; c < 4; c++) of[n][c] = 0.f;

    qkv_ld(smem, 0, y, m0, 0, tid);
    CP_COMMIT();
    CP_WAIT0();
    __syncthreads();

    int buf = 0;
    for (int kt = 0; kt < NCHUNK; kt++) {
        const int nb = buf ^ 1;
        if (kt + 1 < NCHUNK) {
            qkv_ld(smem, nb * QBUF, y, m0, kt + 1, tid);
            CP_COMMIT();
        }

        const uint32_t aoff = smem + buf * QBUF + SXH
                            + (wm + (l & 15)) * (XSTR*2) + (l >> 4) * 16;
        const uint32_t wb = smem + buf * QBUF + SWH;
        #pragma unroll
        for (int kc = 0; kc < 4; kc++) {
            uint32_t ah[4];
            ldsm4(ah, aoff + kc * 32);
            uint32_t al[4];
            if (y != 2) ldsm4(al, aoff + (SXL - SXH) + kc * 32);
            #pragma unroll
            for (int jp = 0; jp < 4; jp++) {
                uint32_t baddr = wb + (wn + jp*16 + brow) * (XSTR*2) + kc * 32 + bcsel;
                uint32_t bh[4];
                ldsm4(bh, baddr);
                mma16816(of[2*jp],   ah, bh[0], bh[1]);
                mma16816(of[2*jp+1], ah, bh[2], bh[3]);
                if (y != 2) {
                    mma16816(of[2*jp],   al, bh[0], bh[1]);
                    mma16816(of[2*jp+1], al, bh[2], bh[3]);
                    uint32_t bl2[4];
                    ldsm4(bl2, baddr + (SWL - SWH));
                    mma16816(of[2*jp],   ah, bl2[0], bl2[1]);
                    mma16816(of[2*jp+1], ah, bl2[2], bl2[3]);
                }
            }
        }

        if (kt + 1 < NCHUNK) CP_WAIT0();
        __syncthreads();
        buf = nb;
    }

    const float* bias = (y == 0) ? bq : (y == 1) ? bk : bv;
    const float bscale = (y == 0) ? LOG2E : 1.0f;
    const int row0 = m0 + wm + (l >> 2);
    const int row1 = row0 + 8;

    #pragma unroll
    for (int np = 0; np < 8; np++) {
        int col = wn + np * 8 + (l & 3) * 2;
        float b0 = bias[col] * bscale, b1 = bias[col + 1] * bscale;
        float v00 = of[np][0] + b0, v01 = of[np][1] + b1;
        float v10 = of[np][2] + b0, v11 = of[np][3] + b1;
        float h00 = __half2float(__float2half_rn(v00));
        float h01 = __half2float(__float2half_rn(v01));
        float h10 = __half2float(__float2half_rn(v10));
        float h11 = __half2float(__float2half_rn(v11));

        if (y < 2) {
            __half* ph = (y == 0) ? g_qh : g_kh;
            __half* pl = (y == 0) ? g_ql : g_kl;
            *(uint32_t*)&ph[(long long)row0 * DD + col] = pack_h2(h00, h01);
            *(uint32_t*)&ph[(long long)row1 * DD + col] = pack_h2(h10, h11);
            *(uint32_t*)&pl[(long long)row0 * DD + col] = pack_h2(v00 - h00, v01 - h01);
            *(uint32_t*)&pl[(long long)row1 * DD + col] = pack_h2(v10 - h10, v11 - h11);
        } else {
            int bbx0 = row0 >> 12, s0 = row0 & 4095;
            int bbx1 = row1 >> 12, s1 = row1 & 4095;
            g_vth[((long long)bbx0 * DD + col) * SS + s0]     = __float2half_rn(h00);
            g_vth[((long long)bbx0 * DD + col + 1) * SS + s0] = __float2half_rn(h01);
            g_vth[((long long)bbx1 * DD + col) * SS + s1]     = __float2half_rn(h10);
            g_vth[((long long)bbx1 * DD + col + 1) * SS + s1] = __float2half_rn(h11);
        }
    }
}

// ============================================================================
// Kernel 2: flash attention, 512 threads / 16 warps (4 per SMSP).
// Warp (r = w>>1, c = w&1): rows 16r..16r+15.
//   S : keys [32c, 32c+32) (3 terms, 96 HMMA/warp/tile)
//   PV: d    [64c, 64c+64) — P exchanged via smem once per tile
// Row-max merged across the c-pair via smem; lazy rescale; l reduced at end.
// ============================================================================
#define QT 128
#define KT 64
#define NTILE (SS/KT)   // 64
#define QSTR2 272       // bytes per row (136 halfs)
#define KSTR2 272
#define VSTR2 144
#define PSTR2 144

#define OFF_QH 0
#define OFF_QL 34816
#define OFF_K  69632
#define KBUF   34816            // per buf (hi+lo)
#define KLOFF  17408
#define OFF_V  139264
#define VBUF   18432
#define OFF_P  176128           // 128 x 144B = 18432
#define OFF_RED 194560          // redm [2][128] f32 (1KB), redl at +1024
#define FLASH_SMEM 196608       // 192 KB

__device__ __forceinline__ void f_load_q(uint32_t smem, int b, int qi0, int tid) {
    long long tok0 = (long long)b * SS + qi0;
    #pragma unroll
    for (int it = 0; it < 8; it++) {
        int ci = tid + it * 512;            // 0..4095
        int hi = ci < 2048;
        int rem = ci & 2047;
        int row = rem >> 4, ch = rem & 15;
        const __half* src = (hi ? g_qh : g_ql) + (tok0 + row) * DD + ch * 8;
        cp16(smem + (hi ? OFF_QH : OFF_QL) + row * QSTR2 + ch * 16, src);
    }
}
__device__ __forceinline__ void f_load_k(uint32_t smem, int b, int kt, int buf, int tid) {
    long long tok0 = (long long)b * SS + (long long)kt * KT;
    #pragma unroll
    for (int it = 0; it < 4; it++) {
        int ci = tid + it * 512;            // 0..2047
        int hi = ci < 1024;
        int rem = ci & 1023;
        int row = rem >> 4, ch = rem & 15;
        const __half* src = (hi ? g_kh : g_kl) + (tok0 + row) * DD + ch * 8;
        cp16(smem + OFF_K + buf * KBUF + (hi ? 0 : KLOFF) + row * KSTR2 + ch * 16, src);
    }
}
__device__ __forceinline__ void f_load_v(uint32_t smem, int b, int kt, int buf, int tid) {
    long long vbase = (long long)b * DD * SS + (long long)kt * KT;
    #pragma unroll
    for (int it = 0; it < 2; it++) {
        int ci = tid + it * 512;            // 0..1023
        int ch = ci & 7;
        int d = ci >> 3;                    // 0..127
        const __half* src = g_vth + vbase + (long long)d * SS + ch * 8;
        cp16(smem + OFF_V + buf * VBUF + d * VSTR2 + ch * 16, src);
    }
}

__global__ void __launch_bounds__(512, 1) flash_attn(float* __restrict__ out)
{
    extern __shared__ char sm[];
    const uint32_t smem = smem_u32(sm);
    const int tid = threadIdx.x;
    const int w = tid >> 5;
    const int l = tid & 31;
    const int c = w & 1;            // key-half for S, d-half for PV
    const int wm = (w >> 1) * 16;   // row group base
    const int b = blockIdx.y;
    const int qi0 = blockIdx.x * QT;

    float* redm = (float*)(sm + OFF_RED);          // [2][128]
    float* redl = (float*)(sm + OFF_RED + 1024);   // [2][128]

    // prologue
    f_load_q(smem, b, qi0, tid);
    f_load_k(smem, b, 0, 0, tid);
    f_load_v(smem, b, 0, 0, tid);
    CP_COMMIT();
    CP_WAIT0();
    __syncthreads();

    float of[8][4];
    #pragma unroll
    for (int n = 0; n < 8; n++)
        #pragma unroll
        for (int k = 0; k < 4; k++) of[n][k] = 0.f;
    float m0 = -INFINITY, m1 = -INFINITY, l0 = 0.f, l1 = 0.f;

    const uint32_t qoff  = smem + (wm + (l & 15)) * QSTR2 + (l >> 4) * 16;
    const uint32_t poff  = smem + OFF_P + (wm + (l & 15)) * PSTR2 + (l >> 4) * 16;
    const uint32_t brow  = (l & 7) + ((l >> 4) & 1) * 8;
    const uint32_t bcsel = ((l >> 3) & 1) * 16;
    const int row0 = wm + (l >> 2);

    #pragma unroll 1
    for (int t = 0; t < NTILE; t++) {
        // issue next tile's loads
        if (t + 1 < NTILE) {
            f_load_k(smem, b, t + 1, (t + 1) & 1, tid);
            f_load_v(smem, b, t + 1, (t + 1) & 1, tid);
        }
        CP_COMMIT();

        // ---- S over this warp's 32-key strip (3 terms) ----
        const uint32_t kb = smem + OFF_K + (t & 1) * KBUF;
        float sf[4][4];
        #pragma unroll
        for (int j = 0; j < 4; j++)
            #pragma unroll
            for (int k = 0; k < 4; k++) sf[j][k] = 0.f;

        #pragma unroll
        for (int kc = 0; kc < 8; kc++) {
            uint32_t ah[4], al[4];
            ldsm4(ah, qoff + kc * 32);
            ldsm4(al, qoff + OFF_QL + kc * 32);
            #pragma unroll
            for (int jp = 0; jp < 2; jp++) {
                uint32_t baddr = kb + (c*32 + jp*16 + brow) * KSTR2 + kc * 32 + bcsel;
                uint32_t bh[4], blr[4];
                ldsm4(bh, baddr);
                ldsm4(blr, baddr + KLOFF);
                mma16816(sf[2*jp],   ah, bh[0], bh[1]);
                mma16816(sf[2*jp+1], ah, bh[2], bh[3]);
                mma16816(sf[2*jp],   al, bh[0], bh[1]);
                mma16816(sf[2*jp+1], al, bh[2], bh[3]);
                mma16816(sf[2*jp],   ah, blr[0], blr[1]);
                mma16816(sf[2*jp+1], ah, blr[2], blr[3]);
            }
        }

        // ---- intra-warp row max ----
        float mx0 = sf[0][0], mx1 = sf[0][2];
        #pragma unroll
        for (int j = 0; j < 4; j++) {
            mx0 = fmaxf(mx0, fmaxf(sf[j][0], sf[j][1]));
            mx1 = fmaxf(mx1, fmaxf(sf[j][2], sf[j][3]));
        }
        mx0 = fmaxf(mx0, __shfl_xor_sync(0xffffffffu, mx0, 1));
        mx0 = fmaxf(mx0, __shfl_xor_sync(0xffffffffu, mx0, 2));
        mx1 = fmaxf(mx1, __shfl_xor_sync(0xffffffffu, mx1, 1));
        mx1 = fmaxf(mx1, __shfl_xor_sync(0xffffffffu, mx1, 2));
        if ((l & 3) == 0) {
            redm[c * 128 + row0]     = mx0;
            redm[c * 128 + row0 + 8] = mx1;
        }
        __syncthreads();   // sync1: max exchange

        float gmx0 = fmaxf(redm[row0],     redm[128 + row0]);
        float gmx1 = fmaxf(redm[row0 + 8], redm[128 + row0 + 8]);

        if (gmx0 > m0) {
            float a = ex2(m0 - gmx0);
            m0 = gmx0; l0 *= a;
            #pragma unroll
            for (int n = 0; n < 8; n++) { of[n][0] *= a; of[n][1] *= a; }
        }
        if (gmx1 > m1) {
            float a = ex2(m1 - gmx1);
            m1 = gmx1; l1 *= a;
            #pragma unroll
            for (int n = 0; n < 8; n++) { of[n][2] *= a; of[n][3] *= a; }
        }

        #pragma unroll
        for (int j = 0; j < 4; j++) {
            sf[j][0] = ex2(sf[j][0] - m0); l0 += sf[j][0];
            sf[j][1] = ex2(sf[j][1] - m0); l0 += sf[j][1];
            sf[j][2] = ex2(sf[j][2] - m1); l1 += sf[j][2];
            sf[j][3] = ex2(sf[j][3] - m1); l1 += sf[j][3];
        }

        // ---- P -> smem (fp16, this warp's key strip) ----
        #pragma unroll
        for (int j = 0; j < 4; j++) {
            uint32_t p0 = cvt_h2(sf[j][0], sf[j][1]);
            uint32_t p1 = cvt_h2(sf[j][2], sf[j][3]);
            uint32_t a = smem + OFF_P + row0 * PSTR2 + (c*32 + j*8 + 2*(l & 3)) * 2;
            *(uint32_t*)(sm + (a - smem))           = p0;
            *(uint32_t*)(sm + (a - smem) + 8*PSTR2) = p1;
        }
        __syncthreads();   // sync2: P visible to partner warp

        // ---- PV: A = P (all 64 keys), B = V on this warp's d-half ----
        const uint32_t vb = smem + OFF_V + (t & 1) * VBUF;
        #pragma unroll
        for (int kchunk = 0; kchunk < 4; kchunk++) {
            uint32_t pa[4];
            ldsm4(pa, poff + kchunk * 32);
            #pragma unroll
            for (int np = 0; np < 4; np++) {
                uint32_t vaddr = vb + (c*64 + np*16 + brow) * VSTR2 + kchunk * 32 + bcsel;
                uint32_t vh[4];
                ldsm4(vh, vaddr);
                mma16816(of[2*np],   pa, vh[0], vh[1]);
                mma16816(of[2*np+1], pa, vh[2], vh[3]);
            }
        }

        CP_WAIT0();
        __syncthreads();   // sync3: buffers ready / retired
    }

    // ---- epilogue: merge l across lanes and c-pair, normalize, store ----
    l0 += __shfl_xor_sync(0xffffffffu, l0, 1);
    l0 += __shfl_xor_sync(0xffffffffu, l0, 2);
    l1 += __shfl_xor_sync(0xffffffffu, l1, 1);
    l1 += __shfl_xor_sync(0xffffffffu, l1, 2);
    if ((l & 3) == 0) {
        redl[c * 128 + row0]     = l0;
        redl[c * 128 + row0 + 8] = l1;
    }
    __syncthreads();
    float lt0 = redl[row0]     + redl[128 + row0];
    float lt1 = redl[row0 + 8] + redl[128 + row0 + 8];
    const float inv0 = 1.0f / lt0, inv1 = 1.0f / lt1;

    long long base0 = ((long long)b * SS + qi0 + row0) * DD + c * 64;
    long long base1 = base0 + 8LL * DD;
    #pragma unroll
    for (int k = 0; k < 8; k++) {
        int cc = k * 8 + 2 * (l & 3);
        *(float2*)(out + base0 + cc) = make_float2(of[k][0]*inv0, of[k][1]*inv0);
        *(float2*)(out + base1 + cc) = make_float2(of[k][2]*inv1, of[k][3]*inv1);
    }
}

// ============================================================================
// launch
// ============================================================================
extern "C" void kernel_launch(void* const* d_in, const int* in_sizes, int n_in,
                              void* d_out, int out_size)
{
    const float* x  = (const float*)d_in[0];
    const float* Wq = (const float*)d_in[1];
    const float* bq = (const float*)d_in[2];
    const float* Wk = (const float*)d_in[3];
    const float* bk = (const float*)d_in[4];
    const float* Wv = (const float*)d_in[5];
    const float* bv = (const float*)d_in[6];
    float* out = (float*)d_out;

    split_x<<<(long long)MM*EE/1024, 256>>>(x);
    split_w<<<(3*DD*EE)/256, 256>>>(Wq, Wk, Wv);

    cudaFuncSetAttribute(qkv_mma, cudaFuncAttributeMaxDynamicSharedMemorySize,
                         QKV_SMEM);
    qkv_mma<<<dim3(MM/64, 3), 256, QKV_SMEM>>>(bq, bk, bv);

    cudaFuncSetAttribute(flash_attn, cudaFuncAttributeMaxDynamicSharedMemorySize,
                         FLASH_SMEM);
    flash_attn<<<dim3(SS / QT, BB), 512, FLASH_SMEM>>>(out);
}

// round 10
// speedup vs baseline: 1.1372x; 1.1372x over previous
#include <cuda_runtime.h>
#include <cuda_fp16.h>
#include <math.h>
#include <stdint.h>

#define BB 8
#define SS 4096
#define EE 2048
#define DD 128
#define MM (BB*SS)   // 32768

#define LOG2E 1.44269504088896340736f

// fp16 scratch (allocation-free __device__ globals)
__device__ __half g_qh[MM*DD];    // q scaled by log2e
__device__ __half g_ql[MM*DD];
__device__ __half g_kh[MM*DD];
__device__ __half g_kl[MM*DD];
__device__ __half g_vth[MM*DD];   // v transposed [b][d][s]
__device__ __half g_wth[3*DD*EE]; // W transposed hi (Wq pre-scaled by log2e)
__device__ __half g_wtl[3*DD*EE];

typedef unsigned long long u64;

__device__ __forceinline__ uint32_t pack_h2(float a, float b) {
    __half ha = __float2half_rn(a), hb = __float2half_rn(b);
    return ((uint32_t)__half_as_ushort(hb) << 16) | (uint32_t)__half_as_ushort(ha);
}
__device__ __forceinline__ uint32_t cvt_h2(float a, float b) {
    uint32_t r;
    asm("cvt.rn.f16x2.f32 %0, %1, %2;" : "=r"(r) : "f"(b), "f"(a));
    return r;
}
__device__ __forceinline__ uint32_t smem_u32(const void* p) {
    uint32_t a;
    asm("{ .reg .u64 t; cvta.to.shared.u64 t, %1; cvt.u32.u64 %0, t; }" : "=r"(a) : "l"(p));
    return a;
}
__device__ __forceinline__ float ex2(float x) {
    float r; asm("ex2.approx.f32 %0, %1;" : "=f"(r) : "f"(x)); return r;
}

__device__ __forceinline__ void cp16(uint32_t dst, const void* src) {
    asm volatile("cp.async.cg.shared.global [%0], [%1], 16;" :: "r"(dst), "l"(src));
}
#define CP_COMMIT() asm volatile("cp.async.commit_group;" ::: "memory")
#define CP_WAIT0()  asm volatile("cp.async.wait_group 0;" ::: "memory")

__device__ __forceinline__ void ldsm4(uint32_t r[4], uint32_t addr) {
    asm volatile("ldmatrix.sync.aligned.m8n8.x4.shared.b16 {%0,%1,%2,%3}, [%4];"
        : "=r"(r[0]), "=r"(r[1]), "=r"(r[2]), "=r"(r[3]) : "r"(addr));
}
__device__ __forceinline__ void mma16816(float c[4], const uint32_t a[4],
                                          uint32_t b0, uint32_t b1) {
    asm volatile("mma.sync.aligned.m16n8k16.row.col.f32.f16.f16.f32 "
        "{%0,%1,%2,%3}, {%4,%5,%6,%7}, {%8,%9}, {%0,%1,%2,%3};"
        : "+f"(c[0]), "+f"(c[1]), "+f"(c[2]), "+f"(c[3])
        : "r"(a[0]), "r"(a[1]), "r"(a[2]), "r"(a[3]), "r"(b0), "r"(b1));
}

// ============================================================================
// Kernel 0: split W (transposed fp16 hi/lo). Wq pre-scaled by log2e.
// ============================================================================
__global__ __launch_bounds__(256) void split_w(
    const float* __restrict__ Wq, const float* __restrict__ Wk,
    const float* __restrict__ Wv)
{
    int idx = blockIdx.x * 256 + threadIdx.x;
    int y = idx >> 18;
    int rem = idx & ((DD*EE) - 1);
    int d = rem >> 11;
    int e = rem & (EE - 1);
    const float* W = (y == 0) ? Wq : (y == 1) ? Wk : Wv;
    float v = W[(long long)e * DD + d];
    if (y == 0) v *= LOG2E;
    __half h = __float2half_rn(v);
    g_wth[idx] = h;
    g_wtl[idx] = __float2half_rn(v - __half2float(h));
}

// ============================================================================
// Kernel 1: fused QKV projection. One CTA per 64-row m-block computes q,k,v.
// x read ONCE as fp32, split to hi/lo in-register, staged to smem.
//   q,k: 3 terms (xh*Wh + xl*Wh + xh*Wl);  v: 1 term (xh*Wvh).
// 256 threads, 8 warps (4M x 2N), double-buffered, 216KB smem, 1 CTA/SM.
// ============================================================================
#define BK 64
#define PLN 18432                   // one W plane: 128 rows x 144B
#define SXH 0                       // x hi: 64 x 144B = 9216
#define SXL 9216
#define SW  18432                   // planes: [qh,ql,kh,kl,vh]
#define QBUF (SW + 5*PLN)           // 110592
#define QKV_SMEM (2*QBUF)           // 221184
#define NCHUNK (EE/BK)              // 32

__device__ __forceinline__ void qkv_w_ld(uint32_t smem, int bufoff, int kt, int tid) {
    #pragma unroll
    for (int j = 0; j < 20; j++) {
        int idx = tid + j * 256;            // 0..5119
        int p = idx >> 10;                  // plane 0..4
        int rem = idx & 1023;
        int n = rem >> 3, ch = rem & 7;
        int y = (p < 4) ? (p >> 1) : 2;
        const __half* base = ((p < 4) && (p & 1)) ? g_wtl : g_wth;
        const __half* src = base + (long long)y * DD * EE + (long long)n * EE
                            + kt * BK + ch * 8;
        cp16(smem + bufoff + SW + p * PLN + n * 144 + ch * 16, src);
    }
}

__device__ __forceinline__ void qkv_stx(char* sm, int bufoff, const float4* xr, int tid) {
    int row = tid >> 2;
    int c0 = (tid & 3) * 4;
    #pragma unroll
    for (int i = 0; i < 4; i++) {
        float4 v = xr[i];
        float h0 = __half2float(__float2half_rn(v.x));
        float h1 = __half2float(__float2half_rn(v.y));
        float h2 = __half2float(__float2half_rn(v.z));
        float h3 = __half2float(__float2half_rn(v.w));
        uint2 uh = make_uint2(pack_h2(h0, h1), pack_h2(h2, h3));
        uint2 ul = make_uint2(pack_h2(v.x - h0, v.y - h1), pack_h2(v.z - h2, v.w - h3));
        int boff = row * 144 + (c0 + 16*i) * 2;
        *(uint2*)(sm + bufoff + SXH + boff) = uh;
        *(uint2*)(sm + bufoff + SXL + boff) = ul;
    }
}

__global__ void __launch_bounds__(256, 1) qkv_mma(
    const float* __restrict__ x,
    const float* __restrict__ bq, const float* __restrict__ bk,
    const float* __restrict__ bv)
{
    extern __shared__ char sm[];
    const uint32_t smem = smem_u32(sm);
    const int tid = threadIdx.x;
    const int w = tid >> 5;
    const int l = tid & 31;
    const int m0 = blockIdx.x * 64;

    const int wm = (w >> 1) * 16;
    const int wn = (w & 1) * 64;
    const uint32_t brow  = (l & 7) + ((l >> 4) & 1) * 8;
    const uint32_t bcsel = ((l >> 3) & 1) * 16;

    const float* xg = x + (long long)(m0 + (tid >> 2)) * EE + (tid & 3) * 4;

    float of[3][8][4];
    #pragma unroll
    for (int y = 0; y < 3; y++)
        #pragma unroll
        for (int n = 0; n < 8; n++)
            #pragma unroll
            for (int c = 0; c < 4; c++) of[y][n][c] = 0.f;

    // prologue: chunk 0
    float4 xr[4];
    #pragma unroll
    for (int i = 0; i < 4; i++) xr[i] = *(const float4*)(xg + 16*i);
    qkv_w_ld(smem, 0, 0, tid);
    CP_COMMIT();
    qkv_stx(sm, 0, xr, tid);
    CP_WAIT0();
    __syncthreads();

    int buf = 0;
    for (int kt = 0; kt < NCHUNK; kt++) {
        const int nb = buf ^ 1;
        if (kt + 1 < NCHUNK) {
            #pragma unroll
            for (int i = 0; i < 4; i++)
                xr[i] = *(const float4*)(xg + (kt + 1) * BK + 16*i);
            qkv_w_ld(smem, nb * QBUF, kt + 1, tid);
            CP_COMMIT();
        }

        const uint32_t aoff = smem + buf * QBUF + SXH
                            + (wm + (l & 15)) * 144 + (l >> 4) * 16;
        const uint32_t wb = smem + buf * QBUF + SW;
        #pragma unroll
        for (int kc = 0; kc < 4; kc++) {
            uint32_t ah[4], al[4];
            ldsm4(ah, aoff + kc * 32);
            ldsm4(al, aoff + (SXL - SXH) + kc * 32);
            #pragma unroll
            for (int y = 0; y < 3; y++) {
                const uint32_t wby = wb + ((y < 2) ? (y * 2) * PLN : 4 * PLN);
                #pragma unroll
                for (int jp = 0; jp < 4; jp++) {
                    uint32_t baddr = wby + (wn + jp*16 + brow) * 144 + kc * 32 + bcsel;
                    uint32_t bh[4];
                    ldsm4(bh, baddr);
                    mma16816(of[y][2*jp],   ah, bh[0], bh[1]);
                    mma16816(of[y][2*jp+1], ah, bh[2], bh[3]);
                    if (y < 2) {
                        mma16816(of[y][2*jp],   al, bh[0], bh[1]);
                        mma16816(of[y][2*jp+1], al, bh[2], bh[3]);
                        uint32_t bl2[4];
                        ldsm4(bl2, baddr + PLN);
                        mma16816(of[y][2*jp],   ah, bl2[0], bl2[1]);
                        mma16816(of[y][2*jp+1], ah, bl2[2], bl2[3]);
                    }
                }
            }
        }

        if (kt + 1 < NCHUNK) {
            qkv_stx(sm, nb * QBUF, xr, tid);
            CP_WAIT0();
        }
        __syncthreads();
        buf = nb;
    }

    // ---- epilogue: all three outputs ----
    const int row0 = m0 + wm + (l >> 2);
    const int row1 = row0 + 8;
    #pragma unroll
    for (int y = 0; y < 3; y++) {
        const float* bias = (y == 0) ? bq : (y == 1) ? bk : bv;
        const float bscale = (y == 0) ? LOG2E : 1.0f;
        #pragma unroll
        for (int np = 0; np < 8; np++) {
            int col = wn + np * 8 + (l & 3) * 2;
            float b0 = bias[col] * bscale, b1 = bias[col + 1] * bscale;
            float v00 = of[y][np][0] + b0, v01 = of[y][np][1] + b1;
            float v10 = of[y][np][2] + b0, v11 = of[y][np][3] + b1;
            float h00 = __half2float(__float2half_rn(v00));
            float h01 = __half2float(__float2half_rn(v01));
            float h10 = __half2float(__float2half_rn(v10));
            float h11 = __half2float(__float2half_rn(v11));

            if (y < 2) {
                __half* ph = (y == 0) ? g_qh : g_kh;
                __half* pl = (y == 0) ? g_ql : g_kl;
                *(uint32_t*)&ph[(long long)row0 * DD + col] = pack_h2(h00, h01);
                *(uint32_t*)&ph[(long long)row1 * DD + col] = pack_h2(h10, h11);
                *(uint32_t*)&pl[(long long)row0 * DD + col] = pack_h2(v00 - h00, v01 - h01);
                *(uint32_t*)&pl[(long long)row1 * DD + col] = pack_h2(v10 - h10, v11 - h11);
            } else {
                int bbx0 = row0 >> 12, s0 = row0 & 4095;
                int bbx1 = row1 >> 12, s1 = row1 & 4095;
                g_vth[((long long)bbx0 * DD + col) * SS + s0]     = __float2half_rn(h00);
                g_vth[((long long)bbx0 * DD + col + 1) * SS + s0] = __float2half_rn(h01);
                g_vth[((long long)bbx1 * DD + col) * SS + s1]     = __float2half_rn(h10);
                g_vth[((long long)bbx1 * DD + col + 1) * SS + s1] = __float2half_rn(h11);
            }
        }
    }
}

// ============================================================================
// Kernel 2: flash attention (round-8 version — fastest measured).
//   S  = Qh*Kh + Ql*Kh + Qh*Kl ; PV = P(fp16)*V(fp16)
// Lazy max, deferred l reduction, register double-buffered scores.
// ============================================================================
#define QT 128
#define KT 64
#define NTILE (SS/KT)   // 64
#define QSTR 136
#define KSTR 136
#define VSTR 72

#define OFF_QH 0
#define OFF_QL (128*QSTR*2)
#define OFF_K  (OFF_QL + 128*QSTR*2)
#define KBUF   (64*KSTR*2*2)
#define KLOFF  (64*KSTR*2)
#define OFF_V  (OFF_K + 2*KBUF)
#define VBUF   (128*VSTR*2)
#define FLASH_SMEM (OFF_V + 2*VBUF)     // 176128

__device__ __forceinline__ void load_k(uint32_t smem, int b, int kt, int buf, int tid) {
    long long tok0 = (long long)b * SS + (long long)kt * KT;
    #pragma unroll
    for (int it = 0; it < 8; it++) {
        int ci = tid + it * 256;
        int c = ci & 15;
        int row = (ci >> 4) & 63;
        const __half* src = ((ci < 1024) ? g_kh : g_kl) + (tok0 + row) * DD + c * 8;
        uint32_t dst = smem + OFF_K + buf * KBUF + ((ci < 1024) ? 0 : KLOFF)
                       + row * (KSTR*2) + c * 16;
        cp16(dst, src);
    }
}
__device__ __forceinline__ void load_v(uint32_t smem, int b, int kt, int buf, int tid) {
    long long vbase = (long long)b * DD * SS + (long long)kt * KT;
    #pragma unroll
    for (int it = 0; it < 4; it++) {
        int ci = tid + it * 256;
        int c = ci & 7;
        int d = (ci >> 3) & 127;
        const __half* src = g_vth + vbase + (long long)d * SS + c * 8;
        uint32_t dst = smem + OFF_V + buf * VBUF + d * (VSTR*2) + c * 16;
        cp16(dst, src);
    }
}

__device__ __forceinline__ void compute_S(float sf[8][4], uint32_t qoff, uint32_t kb,
                                          uint32_t brow, uint32_t bcsel) {
    #pragma unroll
    for (int j = 0; j < 8; j++)
        #pragma unroll
        for (int c = 0; c < 4; c++) sf[j][c] = 0.f;
    #pragma unroll
    for (int kc = 0; kc < 8; kc++) {
        uint32_t ah[4], al[4];
        ldsm4(ah, qoff + OFF_QH + kc * 32);
        ldsm4(al, qoff + OFF_QL + kc * 32);
        #pragma unroll
        for (int jp = 0; jp < 4; jp++) {
            uint32_t baddr = kb + (jp*16 + brow) * (KSTR*2) + kc * 32 + bcsel;
            uint32_t bh[4], blr[4];
            ldsm4(bh, baddr);
            ldsm4(blr, baddr + KLOFF);
            mma16816(sf[2*jp],   ah, bh[0], bh[1]);
            mma16816(sf[2*jp+1], ah, bh[2], bh[3]);
            mma16816(sf[2*jp],   al, bh[0], bh[1]);
            mma16816(sf[2*jp+1], al, bh[2], bh[3]);
            mma16816(sf[2*jp],   ah, blr[0], blr[1]);
            mma16816(sf[2*jp+1], ah, blr[2], blr[3]);
        }
    }
}

__device__ __forceinline__ void flash_iter(
    int t, float sfA[8][4], float sfB[8][4], float of[16][4],
    float& m0, float& m1, float& l0, float& l1,
    uint32_t smem, int b, int tid, uint32_t qoff, uint32_t brow, uint32_t bcsel)
{
    if (t + 2 < NTILE) load_k(smem, b, t + 2, t & 1, tid);
    if (t + 1 < NTILE) load_v(smem, b, t + 1, (t + 1) & 1, tid);
    CP_COMMIT();

    if (t + 1 < NTILE)
        compute_S(sfB, qoff, smem + OFF_K + ((t + 1) & 1) * KBUF, brow, bcsel);

    float mx0 = sfA[0][0], mx1 = sfA[0][2];
    #pragma unroll
    for (int j = 0; j < 8; j++) {
        mx0 = fmaxf(mx0, fmaxf(sfA[j][0], sfA[j][1]));
        mx1 = fmaxf(mx1, fmaxf(sfA[j][2], sfA[j][3]));
    }
    mx0 = fmaxf(mx0, __shfl_xor_sync(0xffffffffu, mx0, 1));
    mx0 = fmaxf(mx0, __shfl_xor_sync(0xffffffffu, mx0, 2));
    mx1 = fmaxf(mx1, __shfl_xor_sync(0xffffffffu, mx1, 1));
    mx1 = fmaxf(mx1, __shfl_xor_sync(0xffffffffu, mx1, 2));

    if (mx0 > m0) {
        float a = ex2(m0 - mx0);
        m0 = mx0; l0 *= a;
        #pragma unroll
        for (int n = 0; n < 16; n++) { of[n][0] *= a; of[n][1] *= a; }
    }
    if (mx1 > m1) {
        float a = ex2(m1 - mx1);
        m1 = mx1; l1 *= a;
        #pragma unroll
        for (int n = 0; n < 16; n++) { of[n][2] *= a; of[n][3] *= a; }
    }

    #pragma unroll
    for (int j = 0; j < 8; j++) {
        sfA[j][0] = ex2(sfA[j][0] - m0); l0 += sfA[j][0];
        sfA[j][1] = ex2(sfA[j][1] - m0); l0 += sfA[j][1];
        sfA[j][2] = ex2(sfA[j][2] - m1); l1 += sfA[j][2];
        sfA[j][3] = ex2(sfA[j][3] - m1); l1 += sfA[j][3];
    }

    const uint32_t vb = smem + OFF_V + (t & 1) * VBUF;
    #pragma unroll
    for (int jk = 0; jk < 4; jk++) {
        uint32_t ph[4];
        ph[0] = cvt_h2(sfA[2*jk][0],   sfA[2*jk][1]);
        ph[1] = cvt_h2(sfA[2*jk][2],   sfA[2*jk][3]);
        ph[2] = cvt_h2(sfA[2*jk+1][0], sfA[2*jk+1][1]);
        ph[3] = cvt_h2(sfA[2*jk+1][2], sfA[2*jk+1][3]);
        #pragma unroll
        for (int np = 0; np < 8; np++) {
            uint32_t vaddr = vb + (np*16 + brow) * (VSTR*2) + jk * 32 + bcsel;
            uint32_t vh[4];
            ldsm4(vh, vaddr);
            mma16816(of[2*np],   ph, vh[0], vh[1]);
            mma16816(of[2*np+1], ph, vh[2], vh[3]);
        }
    }

    CP_WAIT0();
    __syncthreads();
}

__global__ __launch_bounds__(256, 1) void flash_attn(float* __restrict__ out)
{
    extern __shared__ char sm[];
    const uint32_t smem = smem_u32(sm);
    const int tid = threadIdx.x;
    const int w = tid >> 5;
    const int l = tid & 31;
    const int b = blockIdx.y;
    const int qi0 = blockIdx.x * QT;

    {
        long long tok0 = (long long)b * SS + qi0;
        #pragma unroll
        for (int it = 0; it < 16; it++) {
            int ci = tid + it * 256;
            int c = ci & 15;
            int row = (ci >> 4) & 127;
            const __half* src = ((ci < 2048) ? g_qh : g_ql) + (tok0 + row) * DD + c * 8;
            uint32_t dst = smem + ((ci < 2048) ? OFF_QH : OFF_QL) + row * (QSTR*2) + c * 16;
            cp16(dst, src);
        }
    }
    load_k(smem, b, 0, 0, tid);
    load_v(smem, b, 0, 0, tid);
    load_k(smem, b, 1, 1, tid);
    CP_COMMIT();
    CP_WAIT0();
    __syncthreads();

    float of[16][4];
    #pragma unroll
    for (int n = 0; n < 16; n++)
        #pragma unroll
        for (int c = 0; c < 4; c++) of[n][c] = 0.f;
    float m0 = -INFINITY, m1 = -INFINITY, l0 = 0.f, l1 = 0.f;

    const uint32_t qoff  = smem + (w*16 + (l & 15)) * (QSTR*2) + ((l >> 4) * 16);
    const uint32_t brow  = (l & 7) + ((l >> 4) & 1) * 8;
    const uint32_t bcsel = ((l >> 3) & 1) * 16;

    float sfA[8][4], sfB[8][4];
    compute_S(sfA, qoff, smem + OFF_K, brow, bcsel);
    __syncthreads();

    #pragma unroll 1
    for (int t = 0; t < NTILE; t += 2) {
        flash_iter(t,     sfA, sfB, of, m0, m1, l0, l1, smem, b, tid, qoff, brow, bcsel);
        flash_iter(t + 1, sfB, sfA, of, m0, m1, l0, l1, smem, b, tid, qoff, brow, bcsel);
    }

    l0 += __shfl_xor_sync(0xffffffffu, l0, 1);
    l0 += __shfl_xor_sync(0xffffffffu, l0, 2);
    l1 += __shfl_xor_sync(0xffffffffu, l1, 1);
    l1 += __shfl_xor_sync(0xffffffffu, l1, 2);

    const int row0 = w*16 + (l >> 2);
    const float inv0 = 1.0f / l0, inv1 = 1.0f / l1;
    long long base0 = ((long long)b * SS + qi0 + row0) * DD;
    long long base1 = base0 + 8LL * DD;
    #pragma unroll
    for (int n = 0; n < 16; n++) {
        int cc = n*8 + (l & 3)*2;
        *(float2*)(out + base0 + cc) = make_float2(of[n][0]*inv0, of[n][1]*inv0);
        *(float2*)(out + base1 + cc) = make_float2(of[n][2]*inv1, of[n][3]*inv1);
    }
}

// ============================================================================
// launch
// ============================================================================
extern "C" void kernel_launch(void* const* d_in, const int* in_sizes, int n_in,
                              void* d_out, int out_size)
{
    const float* x  = (const float*)d_in[0];
    const float* Wq = (const float*)d_in[1];
    const float* bq = (const float*)d_in[2];
    const float* Wk = (const float*)d_in[3];
    const float* bk = (const float*)d_in[4];
    const float* Wv = (const float*)d_in[5];
    const float* bv = (const float*)d_in[6];
    float* out = (float*)d_out;

    split_w<<<(3*DD*EE)/256, 256>>>(Wq, Wk, Wv);

    cudaFuncSetAttribute(qkv_mma, cudaFuncAttributeMaxDynamicSharedMemorySize,
                         QKV_SMEM);
    qkv_mma<<<MM/64, 256, QKV_SMEM>>>(x, bq, bk, bv);

    cudaFuncSetAttribute(flash_attn, cudaFuncAttributeMaxDynamicSharedMemorySize,
                         FLASH_SMEM);
    flash_attn<<<dim3(SS / QT, BB), 256, FLASH_SMEM>>>(out);
}

// round 11
// speedup vs baseline: 1.1395x; 1.0020x over previous
#include <cuda_runtime.h>
#include <cuda_fp16.h>
#include <math.h>
#include <stdint.h>

#define BB 8
#define SS 4096
#define EE 2048
#define DD 128
#define MM (BB*SS)   // 32768

#define LOG2E 1.44269504088896340736f

// fp16 scratch (allocation-free __device__ globals)
__device__ __half g_qh[MM*DD];    // q scaled by log2e
__device__ __half g_ql[MM*DD];
__device__ __half g_kh[MM*DD];
__device__ __half g_kl[MM*DD];
__device__ __half g_vth[MM*DD];   // v transposed [b][d][s]
__device__ __half g_wth[3*DD*EE]; // W transposed hi (Wq pre-scaled by log2e)
__device__ __half g_wtl[3*DD*EE];

typedef unsigned long long u64;

__device__ __forceinline__ uint32_t pack_h2(float a, float b) {
    __half ha = __float2half_rn(a), hb = __float2half_rn(b);
    return ((uint32_t)__half_as_ushort(hb) << 16) | (uint32_t)__half_as_ushort(ha);
}
__device__ __forceinline__ uint32_t cvt_h2(float a, float b) {
    uint32_t r;
    asm("cvt.rn.f16x2.f32 %0, %1, %2;" : "=r"(r) : "f"(b), "f"(a));
    return r;
}
__device__ __forceinline__ uint32_t smem_u32(const void* p) {
    uint32_t a;
    asm("{ .reg .u64 t; cvta.to.shared.u64 t, %1; cvt.u32.u64 %0, t; }" : "=r"(a) : "l"(p));
    return a;
}
__device__ __forceinline__ float ex2(float x) {
    float r; asm("ex2.approx.f32 %0, %1;" : "=f"(r) : "f"(x)); return r;
}

__device__ __forceinline__ void cp16(uint32_t dst, const void* src) {
    asm volatile("cp.async.cg.shared.global [%0], [%1], 16;" :: "r"(dst), "l"(src));
}
#define CP_COMMIT() asm volatile("cp.async.commit_group;" ::: "memory")
#define CP_WAIT0()  asm volatile("cp.async.wait_group 0;" ::: "memory")

__device__ __forceinline__ void ldsm4(uint32_t r[4], uint32_t addr) {
    asm volatile("ldmatrix.sync.aligned.m8n8.x4.shared.b16 {%0,%1,%2,%3}, [%4];"
        : "=r"(r[0]), "=r"(r[1]), "=r"(r[2]), "=r"(r[3]) : "r"(addr));
}
__device__ __forceinline__ void mma16816(float c[4], const uint32_t a[4],
                                          uint32_t b0, uint32_t b1) {
    asm volatile("mma.sync.aligned.m16n8k16.row.col.f32.f16.f16.f32 "
        "{%0,%1,%2,%3}, {%4,%5,%6,%7}, {%8,%9}, {%0,%1,%2,%3};"
        : "+f"(c[0]), "+f"(c[1]), "+f"(c[2]), "+f"(c[3])
        : "r"(a[0]), "r"(a[1]), "r"(a[2]), "r"(a[3]), "r"(b0), "r"(b1));
}

// ============================================================================
// Kernel 0: split W (transposed fp16 hi/lo). Wq pre-scaled by log2e.
// ============================================================================
__global__ __launch_bounds__(256) void split_w(
    const float* __restrict__ Wq, const float* __restrict__ Wk,
    const float* __restrict__ Wv)
{
    int idx = blockIdx.x * 256 + threadIdx.x;
    int y = idx >> 18;
    int rem = idx & ((DD*EE) - 1);
    int d = rem >> 11;
    int e = rem & (EE - 1);
    const float* W = (y == 0) ? Wq : (y == 1) ? Wk : Wv;
    float v = W[(long long)e * DD + d];
    if (y == 0) v *= LOG2E;
    __half h = __float2half_rn(v);
    g_wth[idx] = h;
    g_wtl[idx] = __float2half_rn(v - __half2float(h));
}

// ============================================================================
// Kernel 1: fused QKV projection, SINGLE-buffered smem -> 2 CTAs/SM.
// CTA A's mma phase covers CTA B's load phase (CTA-interleaved pipeline).
//   q,k: 3 terms (xh*Wh + xl*Wh + xh*Wl);  v: 1 term (xh*Wvh).
// 256 threads, 8 warps (4M x 2N), 108KB smem/CTA.
// ============================================================================
#define BK 64
#define PLN 18432                   // one W plane: 128 rows x 144B
#define SXH 0                       // x hi: 64 x 144B = 9216
#define SXL 9216
#define SW  18432                   // planes: [qh,ql,kh,kl,vh]
#define QKV_SMEM (SW + 5*PLN)       // 110592
#define NCHUNK (EE/BK)              // 32

__device__ __forceinline__ void qkv_w_ld(uint32_t smem, int kt, int tid) {
    #pragma unroll
    for (int j = 0; j < 20; j++) {
        int idx = tid + j * 256;            // 0..5119
        int p = idx >> 10;                  // plane 0..4
        int rem = idx & 1023;
        int n = rem >> 3, ch = rem & 7;
        int y = (p < 4) ? (p >> 1) : 2;
        const __half* base = ((p < 4) && (p & 1)) ? g_wtl : g_wth;
        const __half* src = base + (long long)y * DD * EE + (long long)n * EE
                            + kt * BK + ch * 8;
        cp16(smem + SW + p * PLN + n * 144 + ch * 16, src);
    }
}

__global__ void __launch_bounds__(256, 2) qkv_mma(
    const float* __restrict__ x,
    const float* __restrict__ bq, const float* __restrict__ bk,
    const float* __restrict__ bv)
{
    extern __shared__ char sm[];
    const uint32_t smem = smem_u32(sm);
    const int tid = threadIdx.x;
    const int w = tid >> 5;
    const int l = tid & 31;
    const int m0 = blockIdx.x * 64;

    const int wm = (w >> 1) * 16;
    const int wn = (w & 1) * 64;
    const uint32_t brow  = (l & 7) + ((l >> 4) & 1) * 8;
    const uint32_t bcsel = ((l >> 3) & 1) * 16;

    // x loader geometry: row = tid>>2, float4 cols (tid&3)*4 + 16*i
    const float* xrow = x + (long long)(m0 + (tid >> 2)) * EE + (tid & 3) * 4;
    const int xboff = (tid >> 2) * 144 + (tid & 3) * 8;   // byte offset of first pair

    float of[3][8][4];
    #pragma unroll
    for (int y = 0; y < 3; y++)
        #pragma unroll
        for (int n = 0; n < 8; n++)
            #pragma unroll
            for (int c = 0; c < 4; c++) of[y][n][c] = 0.f;

    for (int kt = 0; kt < NCHUNK; kt++) {
        __syncthreads();   // previous chunk's mma done reading smem

        // ---- load phase: x LDG -> split -> STS ; W via cp.async ----
        qkv_w_ld(smem, kt, tid);
        CP_COMMIT();
        #pragma unroll
        for (int i = 0; i < 4; i++) {
            float4 v = *(const float4*)(xrow + kt * BK + 16 * i);
            float h0 = __half2float(__float2half_rn(v.x));
            float h1 = __half2float(__float2half_rn(v.y));
            float h2 = __half2float(__float2half_rn(v.z));
            float h3 = __half2float(__float2half_rn(v.w));
            uint2 uh = make_uint2(pack_h2(h0, h1), pack_h2(h2, h3));
            uint2 ul = make_uint2(pack_h2(v.x - h0, v.y - h1),
                                  pack_h2(v.z - h2, v.w - h3));
            *(uint2*)(sm + SXH + xboff + 32 * i) = uh;
            *(uint2*)(sm + SXL + xboff + 32 * i) = ul;
        }
        CP_WAIT0();
        __syncthreads();   // tile complete

        // ---- mma phase ----
        const uint32_t aoff = smem + SXH + (wm + (l & 15)) * 144 + (l >> 4) * 16;
        const uint32_t wb = smem + SW;
        #pragma unroll
        for (int kc = 0; kc < 4; kc++) {
            uint32_t ah[4], al[4];
            ldsm4(ah, aoff + kc * 32);
            ldsm4(al, aoff + (SXL - SXH) + kc * 32);
            #pragma unroll
            for (int y = 0; y < 3; y++) {
                const uint32_t wby = wb + ((y < 2) ? (y * 2) * PLN : 4 * PLN);
                #pragma unroll
                for (int jp = 0; jp < 4; jp++) {
                    uint32_t baddr = wby + (wn + jp*16 + brow) * 144 + kc * 32 + bcsel;
                    uint32_t bh[4];
                    ldsm4(bh, baddr);
                    mma16816(of[y][2*jp],   ah, bh[0], bh[1]);
                    mma16816(of[y][2*jp+1], ah, bh[2], bh[3]);
                    if (y < 2) {
                        mma16816(of[y][2*jp],   al, bh[0], bh[1]);
                        mma16816(of[y][2*jp+1], al, bh[2], bh[3]);
                        uint32_t bl2[4];
                        ldsm4(bl2, baddr + PLN);
                        mma16816(of[y][2*jp],   ah, bl2[0], bl2[1]);
                        mma16816(of[y][2*jp+1], ah, bl2[2], bl2[3]);
                    }
                }
            }
        }
    }

    // ---- epilogue: all three outputs ----
    const int row0 = m0 + wm + (l >> 2);
    const int row1 = row0 + 8;
    #pragma unroll
    for (int y = 0; y < 3; y++) {
        const float* bias = (y == 0) ? bq : (y == 1) ? bk : bv;
        const float bscale = (y == 0) ? LOG2E : 1.0f;
        #pragma unroll
        for (int np = 0; np < 8; np++) {
            int col = wn + np * 8 + (l & 3) * 2;
            float b0 = bias[col] * bscale, b1 = bias[col + 1] * bscale;
            float v00 = of[y][np][0] + b0, v01 = of[y][np][1] + b1;
            float v10 = of[y][np][2] + b0, v11 = of[y][np][3] + b1;
            float h00 = __half2float(__float2half_rn(v00));
            float h01 = __half2float(__float2half_rn(v01));
            float h10 = __half2float(__float2half_rn(v10));
            float h11 = __half2float(__float2half_rn(v11));

            if (y < 2) {
                __half* ph = (y == 0) ? g_qh : g_kh;
                __half* pl = (y == 0) ? g_ql : g_kl;
                *(uint32_t*)&ph[(long long)row0 * DD + col] = pack_h2(h00, h01);
                *(uint32_t*)&ph[(long long)row1 * DD + col] = pack_h2(h10, h11);
                *(uint32_t*)&pl[(long long)row0 * DD + col] = pack_h2(v00 - h00, v01 - h01);
                *(uint32_t*)&pl[(long long)row1 * DD + col] = pack_h2(v10 - h10, v11 - h11);
            } else {
                int bbx0 = row0 >> 12, s0 = row0 & 4095;
                int bbx1 = row1 >> 12, s1 = row1 & 4095;
                g_vth[((long long)bbx0 * DD + col) * SS + s0]     = __float2half_rn(h00);
                g_vth[((long long)bbx0 * DD + col + 1) * SS + s0] = __float2half_rn(h01);
                g_vth[((long long)bbx1 * DD + col) * SS + s1]     = __float2half_rn(h10);
                g_vth[((long long)bbx1 * DD + col + 1) * SS + s1] = __float2half_rn(h11);
            }
        }
    }
}

// ============================================================================
// Kernel 2: flash attention (round-8 version — fastest measured; unchanged).
// ============================================================================
#define QT 128
#define KT 64
#define NTILE (SS/KT)   // 64
#define QSTR 136
#define KSTR 136
#define VSTR 72

#define OFF_QH 0
#define OFF_QL (128*QSTR*2)
#define OFF_K  (OFF_QL + 128*QSTR*2)
#define KBUF   (64*KSTR*2*2)
#define KLOFF  (64*KSTR*2)
#define OFF_V  (OFF_K + 2*KBUF)
#define VBUF   (128*VSTR*2)
#define FLASH_SMEM (OFF_V + 2*VBUF)     // 176128

__device__ __forceinline__ void load_k(uint32_t smem, int b, int kt, int buf, int tid) {
    long long tok0 = (long long)b * SS + (long long)kt * KT;
    #pragma unroll
    for (int it = 0; it < 8; it++) {
        int ci = tid + it * 256;
        int c = ci & 15;
        int row = (ci >> 4) & 63;
        const __half* src = ((ci < 1024) ? g_kh : g_kl) + (tok0 + row) * DD + c * 8;
        uint32_t dst = smem + OFF_K + buf * KBUF + ((ci < 1024) ? 0 : KLOFF)
                       + row * (KSTR*2) + c * 16;
        cp16(dst, src);
    }
}
__device__ __forceinline__ void load_v(uint32_t smem, int b, int kt, int buf, int tid) {
    long long vbase = (long long)b * DD * SS + (long long)kt * KT;
    #pragma unroll
    for (int it = 0; it < 4; it++) {
        int ci = tid + it * 256;
        int c = ci & 7;
        int d = (ci >> 3) & 127;
        const __half* src = g_vth + vbase + (long long)d * SS + c * 8;
        uint32_t dst = smem + OFF_V + buf * VBUF + d * (VSTR*2) + c * 16;
        cp16(dst, src);
    }
}

__device__ __forceinline__ void compute_S(float sf[8][4], uint32_t qoff, uint32_t kb,
                                          uint32_t brow, uint32_t bcsel) {
    #pragma unroll
    for (int j = 0; j < 8; j++)
        #pragma unroll
        for (int c = 0; c < 4; c++) sf[j][c] = 0.f;
    #pragma unroll
    for (int kc = 0; kc < 8; kc++) {
        uint32_t ah[4], al[4];
        ldsm4(ah, qoff + OFF_QH + kc * 32);
        ldsm4(al, qoff + OFF_QL + kc * 32);
        #pragma unroll
        for (int jp = 0; jp < 4; jp++) {
            uint32_t baddr = kb + (jp*16 + brow) * (KSTR*2) + kc * 32 + bcsel;
            uint32_t bh[4], blr[4];
            ldsm4(bh, baddr);
            ldsm4(blr, baddr + KLOFF);
            mma16816(sf[2*jp],   ah, bh[0], bh[1]);
            mma16816(sf[2*jp+1], ah, bh[2], bh[3]);
            mma16816(sf[2*jp],   al, bh[0], bh[1]);
            mma16816(sf[2*jp+1], al, bh[2], bh[3]);
            mma16816(sf[2*jp],   ah, blr[0], blr[1]);
            mma16816(sf[2*jp+1], ah, blr[2], blr[3]);
        }
    }
}

__device__ __forceinline__ void flash_iter(
    int t, float sfA[8][4], float sfB[8][4], float of[16][4],
    float& m0, float& m1, float& l0, float& l1,
    uint32_t smem, int b, int tid, uint32_t qoff, uint32_t brow, uint32_t bcsel)
{
    if (t + 2 < NTILE) load_k(smem, b, t + 2, t & 1, tid);
    if (t + 1 < NTILE) load_v(smem, b, t + 1, (t + 1) & 1, tid);
    CP_COMMIT();

    if (t + 1 < NTILE)
        compute_S(sfB, qoff, smem + OFF_K + ((t + 1) & 1) * KBUF, brow, bcsel);

    float mx0 = sfA[0][0], mx1 = sfA[0][2];
    #pragma unroll
    for (int j = 0; j < 8; j++) {
        mx0 = fmaxf(mx0, fmaxf(sfA[j][0], sfA[j][1]));
        mx1 = fmaxf(mx1, fmaxf(sfA[j][2], sfA[j][3]));
    }
    mx0 = fmaxf(mx0, __shfl_xor_sync(0xffffffffu, mx0, 1));
    mx0 = fmaxf(mx0, __shfl_xor_sync(0xffffffffu, mx0, 2));
    mx1 = fmaxf(mx1, __shfl_xor_sync(0xffffffffu, mx1, 1));
    mx1 = fmaxf(mx1, __shfl_xor_sync(0xffffffffu, mx1, 2));

    if (mx0 > m0) {
        float a = ex2(m0 - mx0);
        m0 = mx0; l0 *= a;
        #pragma unroll
        for (int n = 0; n < 16; n++) { of[n][0] *= a; of[n][1] *= a; }
    }
    if (mx1 > m1) {
        float a = ex2(m1 - mx1);
        m1 = mx1; l1 *= a;
        #pragma unroll
        for (int n = 0; n < 16; n++) { of[n][2] *= a; of[n][3] *= a; }
    }

    #pragma unroll
    for (int j = 0; j < 8; j++) {
        sfA[j][0] = ex2(sfA[j][0] - m0); l0 += sfA[j][0];
        sfA[j][1] = ex2(sfA[j][1] - m0); l0 += sfA[j][1];
        sfA[j][2] = ex2(sfA[j][2] - m1); l1 += sfA[j][2];
        sfA[j][3] = ex2(sfA[j][3] - m1); l1 += sfA[j][3];
    }

    const uint32_t vb = smem + OFF_V + (t & 1) * VBUF;
    #pragma unroll
    for (int jk = 0; jk < 4; jk++) {
        uint32_t ph[4];
        ph[0] = cvt_h2(sfA[2*jk][0],   sfA[2*jk][1]);
        ph[1] = cvt_h2(sfA[2*jk][2],   sfA[2*jk][3]);
        ph[2] = cvt_h2(sfA[2*jk+1][0], sfA[2*jk+1][1]);
        ph[3] = cvt_h2(sfA[2*jk+1][2], sfA[2*jk+1][3]);
        #pragma unroll
        for (int np = 0; np < 8; np++) {
            uint32_t vaddr = vb + (np*16 + brow) * (VSTR*2) + jk * 32 + bcsel;
            uint32_t vh[4];
            ldsm4(vh, vaddr);
            mma16816(of[2*np],   ph, vh[0], vh[1]);
            mma16816(of[2*np+1], ph, vh[2], vh[3]);
        }
    }

    CP_WAIT0();
    __syncthreads();
}

__global__ __launch_bounds__(256, 1) void flash_attn(float* __restrict__ out)
{
    extern __shared__ char sm[];
    const uint32_t smem = smem_u32(sm);
    const int tid = threadIdx.x;
    const int w = tid >> 5;
    const int l = tid & 31;
    const int b = blockIdx.y;
    const int qi0 = blockIdx.x * QT;

    {
        long long tok0 = (long long)b * SS + qi0;
        #pragma unroll
        for (int it = 0; it < 16; it++) {
            int ci = tid + it * 256;
            int c = ci & 15;
            int row = (ci >> 4) & 127;
            const __half* src = ((ci < 2048) ? g_qh : g_ql) + (tok0 + row) * DD + c * 8;
            uint32_t dst = smem + ((ci < 2048) ? OFF_QH : OFF_QL) + row * (QSTR*2) + c * 16;
            cp16(dst, src);
        }
    }
    load_k(smem, b, 0, 0, tid);
    load_v(smem, b, 0, 0, tid);
    load_k(smem, b, 1, 1, tid);
    CP_COMMIT();
    CP_WAIT0();
    __syncthreads();

    float of[16][4];
    #pragma unroll
    for (int n = 0; n < 16; n++)
        #pragma unroll
        for (int c = 0; c < 4; c++) of[n][c] = 0.f;
    float m0 = -INFINITY, m1 = -INFINITY, l0 = 0.f, l1 = 0.f;

    const uint32_t qoff  = smem + (w*16 + (l & 15)) * (QSTR*2) + ((l >> 4) * 16);
    const uint32_t brow  = (l & 7) + ((l >> 4) & 1) * 8;
    const uint32_t bcsel = ((l >> 3) & 1) * 16;

    float sfA[8][4], sfB[8][4];
    compute_S(sfA, qoff, smem + OFF_K, brow, bcsel);
    __syncthreads();

    #pragma unroll 1
    for (int t = 0; t < NTILE; t += 2) {
        flash_iter(t,     sfA, sfB, of, m0, m1, l0, l1, smem, b, tid, qoff, brow, bcsel);
        flash_iter(t + 1, sfB, sfA, of, m0, m1, l0, l1, smem, b, tid, qoff, brow, bcsel);
    }

    l0 += __shfl_xor_sync(0xffffffffu, l0, 1);
    l0 += __shfl_xor_sync(0xffffffffu, l0, 2);
    l1 += __shfl_xor_sync(0xffffffffu, l1, 1);
    l1 += __shfl_xor_sync(0xffffffffu, l1, 2);

    const int row0 = w*16 + (l >> 2);
    const float inv0 = 1.0f / l0, inv1 = 1.0f / l1;
    long long base0 = ((long long)b * SS + qi0 + row0) * DD;
    long long base1 = base0 + 8LL * DD;
    #pragma unroll
    for (int n = 0; n < 16; n++) {
        int cc = n*8 + (l & 3)*2;
        *(float2*)(out + base0 + cc) = make_float2(of[n][0]*inv0, of[n][1]*inv0);
        *(float2*)(out + base1 + cc) = make_float2(of[n][2]*inv1, of[n][3]*inv1);
    }
}

// ============================================================================
// launch
// ============================================================================
extern "C" void kernel_launch(void* const* d_in, const int* in_sizes, int n_in,
                              void* d_out, int out_size)
{
    const float* x  = (const float*)d_in[0];
    const float* Wq = (const float*)d_in[1];
    const float* bq = (const float*)d_in[2];
    const float* Wk = (const float*)d_in[3];
    const float* bk = (const float*)d_in[4];
    const float* Wv = (const float*)d_in[5];
    const float* bv = (const float*)d_in[6];
    float* out = (float*)d_out;

    split_w<<<(3*DD*EE)/256, 256>>>(Wq, Wk, Wv);

    cudaFuncSetAttribute(qkv_mma, cudaFuncAttributeMaxDynamicSharedMemorySize,
                         QKV_SMEM);
    qkv_mma<<<MM/64, 256, QKV_SMEM>>>(x, bq, bk, bv);

    cudaFuncSetAttribute(flash_attn, cudaFuncAttributeMaxDynamicSharedMemorySize,
                         FLASH_SMEM);
    flash_attn<<<dim3(SS / QT, BB), 256, FLASH_SMEM>>>(out);
}

// round 12
// speedup vs baseline: 1.1699x; 1.0267x over previous
#include <cuda_runtime.h>
#include <cuda_fp16.h>
#include <math.h>
#include <stdint.h>

#define BB 8
#define SS 4096
#define EE 2048
#define DD 128
#define MM (BB*SS)   // 32768

#define LOG2E 1.44269504088896340736f

// fp16 scratch (allocation-free __device__ globals)
__device__ __half g_qh[MM*DD];    // q scaled by log2e
__device__ __half g_ql[MM*DD];
__device__ __half g_kh[MM*DD];
__device__ __half g_kl[MM*DD];
__device__ __half g_vth[MM*DD];   // v transposed [b][d][s]
__device__ __half g_wth[3*DD*EE]; // W transposed hi (Wq pre-scaled by log2e)
__device__ __half g_wtl[3*DD*EE];

typedef unsigned long long u64;

__device__ __forceinline__ uint32_t pack_h2(float a, float b) {
    __half ha = __float2half_rn(a), hb = __float2half_rn(b);
    return ((uint32_t)__half_as_ushort(hb) << 16) | (uint32_t)__half_as_ushort(ha);
}
__device__ __forceinline__ uint32_t cvt_h2(float a, float b) {
    uint32_t r;
    asm("cvt.rn.f16x2.f32 %0, %1, %2;" : "=r"(r) : "f"(b), "f"(a));
    return r;
}
__device__ __forceinline__ uint32_t smem_u32(const void* p) {
    uint32_t a;
    asm("{ .reg .u64 t; cvta.to.shared.u64 t, %1; cvt.u32.u64 %0, t; }" : "=r"(a) : "l"(p));
    return a;
}
__device__ __forceinline__ float ex2(float x) {
    float r; asm("ex2.approx.f32 %0, %1;" : "=f"(r) : "f"(x)); return r;
}

__device__ __forceinline__ void cp16(uint32_t dst, const void* src) {
    asm volatile("cp.async.cg.shared.global [%0], [%1], 16;" :: "r"(dst), "l"(src));
}
#define CP_COMMIT() asm volatile("cp.async.commit_group;" ::: "memory")
#define CP_WAIT0()  asm volatile("cp.async.wait_group 0;" ::: "memory")

__device__ __forceinline__ void ldsm4(uint32_t r[4], uint32_t addr) {
    asm volatile("ldmatrix.sync.aligned.m8n8.x4.shared.b16 {%0,%1,%2,%3}, [%4];"
        : "=r"(r[0]), "=r"(r[1]), "=r"(r[2]), "=r"(r[3]) : "r"(addr));
}
__device__ __forceinline__ void mma16816(float c[4], const uint32_t a[4],
                                          uint32_t b0, uint32_t b1) {
    asm volatile("mma.sync.aligned.m16n8k16.row.col.f32.f16.f16.f32 "
        "{%0,%1,%2,%3}, {%4,%5,%6,%7}, {%8,%9}, {%0,%1,%2,%3};"
        : "+f"(c[0]), "+f"(c[1]), "+f"(c[2]), "+f"(c[3])
        : "r"(a[0]), "r"(a[1]), "r"(a[2]), "r"(a[3]), "r"(b0), "r"(b1));
}

// ============================================================================
// Kernel 0: split W (transposed fp16 hi/lo). Wq pre-scaled by log2e.
// ============================================================================
__global__ __launch_bounds__(256) void split_w(
    const float* __restrict__ Wq, const float* __restrict__ Wk,
    const float* __restrict__ Wv)
{
    int idx = blockIdx.x * 256 + threadIdx.x;
    int y = idx >> 18;
    int rem = idx & ((DD*EE) - 1);
    int d = rem >> 11;
    int e = rem & (EE - 1);
    const float* W = (y == 0) ? Wq : (y == 1) ? Wk : Wv;
    float v = W[(long long)e * DD + d];
    if (y == 0) v *= LOG2E;
    __half h = __float2half_rn(v);
    g_wth[idx] = h;
    g_wtl[idx] = __float2half_rn(v - __half2float(h));
}

// ============================================================================
// Kernel 1: fused QKV projection, double-buffered, 1 CTA/SM.
// NEW warp layout 2M x 4N (warp tile 32M x 32N): cuts LDSM smem reads
// 360KB -> 229KB per chunk, under the 3584-cyc HMMA floor.
//   q,k: 3 terms (xh*Wh + xl*Wh + xh*Wl);  v: 1 term (xh*Wvh).
// ============================================================================
#define BK 64
#define PLN 18432                   // one W plane: 128 rows x 144B
#define SXH 0                       // x hi: 64 x 144B = 9216
#define SXL 9216
#define SW  18432                   // planes: [qh,ql,kh,kl,vh]
#define QBUF (SW + 5*PLN)           // 110592
#define QKV_SMEM (2*QBUF)           // 221184
#define NCHUNK (EE/BK)              // 32

__device__ __forceinline__ void qkv_w_ld(uint32_t smem, int bufoff, int kt, int tid) {
    #pragma unroll
    for (int j = 0; j < 20; j++) {
        int idx = tid + j * 256;            // 0..5119
        int p = idx >> 10;                  // plane 0..4
        int rem = idx & 1023;
        int n = rem >> 3, ch = rem & 7;
        int y = (p < 4) ? (p >> 1) : 2;
        const __half* base = ((p < 4) && (p & 1)) ? g_wtl : g_wth;
        const __half* src = base + (long long)y * DD * EE + (long long)n * EE
                            + kt * BK + ch * 8;
        cp16(smem + bufoff + SW + p * PLN + n * 144 + ch * 16, src);
    }
}

__device__ __forceinline__ void qkv_stx(char* sm, int bufoff, const float4* xr, int tid) {
    int row = tid >> 2;
    int c0 = (tid & 3) * 4;
    #pragma unroll
    for (int i = 0; i < 4; i++) {
        float4 v = xr[i];
        float h0 = __half2float(__float2half_rn(v.x));
        float h1 = __half2float(__float2half_rn(v.y));
        float h2 = __half2float(__float2half_rn(v.z));
        float h3 = __half2float(__float2half_rn(v.w));
        uint2 uh = make_uint2(pack_h2(h0, h1), pack_h2(h2, h3));
        uint2 ul = make_uint2(pack_h2(v.x - h0, v.y - h1), pack_h2(v.z - h2, v.w - h3));
        int boff = row * 144 + (c0 + 16*i) * 2;
        *(uint2*)(sm + bufoff + SXH + boff) = uh;
        *(uint2*)(sm + bufoff + SXL + boff) = ul;
    }
}

__global__ void __launch_bounds__(256, 1) qkv_mma(
    const float* __restrict__ x,
    const float* __restrict__ bq, const float* __restrict__ bk,
    const float* __restrict__ bv)
{
    extern __shared__ char sm[];
    const uint32_t smem = smem_u32(sm);
    const int tid = threadIdx.x;
    const int w = tid >> 5;
    const int l = tid & 31;
    const int m0 = blockIdx.x * 64;

    const int wm = (w >> 2) * 32;        // 2 M-groups of 32 rows
    const int wn = (w & 3) * 32;         // 4 N-groups of 32 cols
    const uint32_t brow  = (l & 7) + ((l >> 4) & 1) * 8;
    const uint32_t bcsel = ((l >> 3) & 1) * 16;

    const float* xg = x + (long long)(m0 + (tid >> 2)) * EE + (tid & 3) * 4;

    // of[y][mfrag][n8][acc4]
    float of[3][2][4][4];
    #pragma unroll
    for (int y = 0; y < 3; y++)
        #pragma unroll
        for (int m = 0; m < 2; m++)
            #pragma unroll
            for (int n = 0; n < 4; n++)
                #pragma unroll
                for (int c = 0; c < 4; c++) of[y][m][n][c] = 0.f;

    // prologue: chunk 0
    float4 xr[4];
    #pragma unroll
    for (int i = 0; i < 4; i++) xr[i] = *(const float4*)(xg + 16*i);
    qkv_w_ld(smem, 0, 0, tid);
    CP_COMMIT();
    qkv_stx(sm, 0, xr, tid);
    CP_WAIT0();
    __syncthreads();

    int buf = 0;
    for (int kt = 0; kt < NCHUNK; kt++) {
        const int nb = buf ^ 1;
        if (kt + 1 < NCHUNK) {
            #pragma unroll
            for (int i = 0; i < 4; i++)
                xr[i] = *(const float4*)(xg + (kt + 1) * BK + 16*i);
            qkv_w_ld(smem, nb * QBUF, kt + 1, tid);
            CP_COMMIT();
        }

        const uint32_t aoff = smem + buf * QBUF + SXH
                            + (wm + (l & 15)) * 144 + (l >> 4) * 16;
        const uint32_t wb = smem + buf * QBUF + SW;
        #pragma unroll
        for (int kc = 0; kc < 4; kc++) {
            uint32_t ah[2][4], al[2][4];
            ldsm4(ah[0], aoff + kc * 32);
            ldsm4(ah[1], aoff + 16 * 144 + kc * 32);
            ldsm4(al[0], aoff + (SXL - SXH) + kc * 32);
            ldsm4(al[1], aoff + (SXL - SXH) + 16 * 144 + kc * 32);
            #pragma unroll
            for (int y = 0; y < 3; y++) {
                const uint32_t wby = wb + ((y < 2) ? (y * 2) * PLN : 4 * PLN);
                #pragma unroll
                for (int nf = 0; nf < 2; nf++) {   // 16-col fragments
                    uint32_t baddr = wby + (wn + nf*16 + brow) * 144 + kc * 32 + bcsel;
                    uint32_t bh[4];
                    ldsm4(bh, baddr);
                    #pragma unroll
                    for (int m = 0; m < 2; m++) {
                        mma16816(of[y][m][2*nf],   ah[m], bh[0], bh[1]);
                        mma16816(of[y][m][2*nf+1], ah[m], bh[2], bh[3]);
                        if (y < 2) {
                            mma16816(of[y][m][2*nf],   al[m], bh[0], bh[1]);
                            mma16816(of[y][m][2*nf+1], al[m], bh[2], bh[3]);
                        }
                    }
                    if (y < 2) {
                        uint32_t bl2[4];
                        ldsm4(bl2, baddr + PLN);
                        #pragma unroll
                        for (int m = 0; m < 2; m++) {
                            mma16816(of[y][m][2*nf],   ah[m], bl2[0], bl2[1]);
                            mma16816(of[y][m][2*nf+1], ah[m], bl2[2], bl2[3]);
                        }
                    }
                }
            }
        }

        if (kt + 1 < NCHUNK) {
            qkv_stx(sm, nb * QBUF, xr, tid);
            CP_WAIT0();
        }
        __syncthreads();
        buf = nb;
    }

    // ---- epilogue: all three outputs ----
    #pragma unroll
    for (int y = 0; y < 3; y++) {
        const float* bias = (y == 0) ? bq : (y == 1) ? bk : bv;
        const float bscale = (y == 0) ? LOG2E : 1.0f;
        #pragma unroll
        for (int m = 0; m < 2; m++) {
            const int row0 = m0 + wm + m * 16 + (l >> 2);
            const int row1 = row0 + 8;
            #pragma unroll
            for (int nn = 0; nn < 4; nn++) {
                int col = wn + nn * 8 + (l & 3) * 2;
                float b0 = bias[col] * bscale, b1 = bias[col + 1] * bscale;
                float v00 = of[y][m][nn][0] + b0, v01 = of[y][m][nn][1] + b1;
                float v10 = of[y][m][nn][2] + b0, v11 = of[y][m][nn][3] + b1;
                float h00 = __half2float(__float2half_rn(v00));
                float h01 = __half2float(__float2half_rn(v01));
                float h10 = __half2float(__float2half_rn(v10));
                float h11 = __half2float(__float2half_rn(v11));

                if (y < 2) {
                    __half* ph = (y == 0) ? g_qh : g_kh;
                    __half* pl = (y == 0) ? g_ql : g_kl;
                    *(uint32_t*)&ph[(long long)row0 * DD + col] = pack_h2(h00, h01);
                    *(uint32_t*)&ph[(long long)row1 * DD + col] = pack_h2(h10, h11);
                    *(uint32_t*)&pl[(long long)row0 * DD + col] = pack_h2(v00 - h00, v01 - h01);
                    *(uint32_t*)&pl[(long long)row1 * DD + col] = pack_h2(v10 - h10, v11 - h11);
                } else {
                    int bbx0 = row0 >> 12, s0 = row0 & 4095;
                    int bbx1 = row1 >> 12, s1 = row1 & 4095;
                    g_vth[((long long)bbx0 * DD + col) * SS + s0]     = __float2half_rn(h00);
                    g_vth[((long long)bbx0 * DD + col + 1) * SS + s0] = __float2half_rn(h01);
                    g_vth[((long long)bbx1 * DD + col) * SS + s1]     = __float2half_rn(h10);
                    g_vth[((long long)bbx1 * DD + col + 1) * SS + s1] = __float2half_rn(h11);
                }
            }
        }
    }
}

// ============================================================================
// Kernel 2: flash attention (round-8 version — fastest measured; unchanged).
// ============================================================================
#define QT 128
#define KT 64
#define NTILE (SS/KT)   // 64
#define QSTR 136
#define KSTR 136
#define VSTR 72

#define OFF_QH 0
#define OFF_QL (128*QSTR*2)
#define OFF_K  (OFF_QL + 128*QSTR*2)
#define KBUF   (64*KSTR*2*2)
#define KLOFF  (64*KSTR*2)
#define OFF_V  (OFF_K + 2*KBUF)
#define VBUF   (128*VSTR*2)
#define FLASH_SMEM (OFF_V + 2*VBUF)     // 176128

__device__ __forceinline__ void load_k(uint32_t smem, int b, int kt, int buf, int tid) {
    long long tok0 = (long long)b * SS + (long long)kt * KT;
    #pragma unroll
    for (int it = 0; it < 8; it++) {
        int ci = tid + it * 256;
        int c = ci & 15;
        int row = (ci >> 4) & 63;
        const __half* src = ((ci < 1024) ? g_kh : g_kl) + (tok0 + row) * DD + c * 8;
        uint32_t dst = smem + OFF_K + buf * KBUF + ((ci < 1024) ? 0 : KLOFF)
                       + row * (KSTR*2) + c * 16;
        cp16(dst, src);
    }
}
__device__ __forceinline__ void load_v(uint32_t smem, int b, int kt, int buf, int tid) {
    long long vbase = (long long)b * DD * SS + (long long)kt * KT;
    #pragma unroll
    for (int it = 0; it < 4; it++) {
        int ci = tid + it * 256;
        int c = ci & 7;
        int d = (ci >> 3) & 127;
        const __half* src = g_vth + vbase + (long long)d * SS + c * 8;
        uint32_t dst = smem + OFF_V + buf * VBUF + d * (VSTR*2) + c * 16;
        cp16(dst, src);
    }
}

__device__ __forceinline__ void compute_S(float sf[8][4], uint32_t qoff, uint32_t kb,
                                          uint32_t brow, uint32_t bcsel) {
    #pragma unroll
    for (int j = 0; j < 8; j++)
        #pragma unroll
        for (int c = 0; c < 4; c++) sf[j][c] = 0.f;
    #pragma unroll
    for (int kc = 0; kc < 8; kc++) {
        uint32_t ah[4], al[4];
        ldsm4(ah, qoff + OFF_QH + kc * 32);
        ldsm4(al, qoff + OFF_QL + kc * 32);
        #pragma unroll
        for (int jp = 0; jp < 4; jp++) {
            uint32_t baddr = kb + (jp*16 + brow) * (KSTR*2) + kc * 32 + bcsel;
            uint32_t bh[4], blr[4];
            ldsm4(bh, baddr);
            ldsm4(blr, baddr + KLOFF);
            mma16816(sf[2*jp],   ah, bh[0], bh[1]);
            mma16816(sf[2*jp+1], ah, bh[2], bh[3]);
            mma16816(sf[2*jp],   al, bh[0], bh[1]);
            mma16816(sf[2*jp+1], al, bh[2], bh[3]);
            mma16816(sf[2*jp],   ah, blr[0], blr[1]);
            mma16816(sf[2*jp+1], ah, blr[2], blr[3]);
        }
    }
}

__device__ __forceinline__ void flash_iter(
    int t, float sfA[8][4], float sfB[8][4], float of[16][4],
    float& m0, float& m1, float& l0, float& l1,
    uint32_t smem, int b, int tid, uint32_t qoff, uint32_t brow, uint32_t bcsel)
{
    if (t + 2 < NTILE) load_k(smem, b, t + 2, t & 1, tid);
    if (t + 1 < NTILE) load_v(smem, b, t + 1, (t + 1) & 1, tid);
    CP_COMMIT();

    if (t + 1 < NTILE)
        compute_S(sfB, qoff, smem + OFF_K + ((t + 1) & 1) * KBUF, brow, bcsel);

    float mx0 = sfA[0][0], mx1 = sfA[0][2];
    #pragma unroll
    for (int j = 0; j < 8; j++) {
        mx0 = fmaxf(mx0, fmaxf(sfA[j][0], sfA[j][1]));
        mx1 = fmaxf(mx1, fmaxf(sfA[j][2], sfA[j][3]));
    }
    mx0 = fmaxf(mx0, __shfl_xor_sync(0xffffffffu, mx0, 1));
    mx0 = fmaxf(mx0, __shfl_xor_sync(0xffffffffu, mx0, 2));
    mx1 = fmaxf(mx1, __shfl_xor_sync(0xffffffffu, mx1, 1));
    mx1 = fmaxf(mx1, __shfl_xor_sync(0xffffffffu, mx1, 2));

    if (mx0 > m0) {
        float a = ex2(m0 - mx0);
        m0 = mx0; l0 *= a;
        #pragma unroll
        for (int n = 0; n < 16; n++) { of[n][0] *= a; of[n][1] *= a; }
    }
    if (mx1 > m1) {
        float a = ex2(m1 - mx1);
        m1 = mx1; l1 *= a;
        #pragma unroll
        for (int n = 0; n < 16; n++) { of[n][2] *= a; of[n][3] *= a; }
    }

    #pragma unroll
    for (int j = 0; j < 8; j++) {
        sfA[j][0] = ex2(sfA[j][0] - m0); l0 += sfA[j][0];
        sfA[j][1] = ex2(sfA[j][1] - m0); l0 += sfA[j][1];
        sfA[j][2] = ex2(sfA[j][2] - m1); l1 += sfA[j][2];
        sfA[j][3] = ex2(sfA[j][3] - m1); l1 += sfA[j][3];
    }

    const uint32_t vb = smem + OFF_V + (t & 1) * VBUF;
    #pragma unroll
    for (int jk = 0; jk < 4; jk++) {
        uint32_t ph[4];
        ph[0] = cvt_h2(sfA[2*jk][0],   sfA[2*jk][1]);
        ph[1] = cvt_h2(sfA[2*jk][2],   sfA[2*jk][3]);
        ph[2] = cvt_h2(sfA[2*jk+1][0], sfA[2*jk+1][1]);
        ph[3] = cvt_h2(sfA[2*jk+1][2], sfA[2*jk+1][3]);
        #pragma unroll
        for (int np = 0; np < 8; np++) {
            uint32_t vaddr = vb + (np*16 + brow) * (VSTR*2) + jk * 32 + bcsel;
            uint32_t vh[4];
            ldsm4(vh, vaddr);
            mma16816(of[2*np],   ph, vh[0], vh[1]);
            mma16816(of[2*np+1], ph, vh[2], vh[3]);
        }
    }

    CP_WAIT0();
    __syncthreads();
}

__global__ __launch_bounds__(256, 1) void flash_attn(float* __restrict__ out)
{
    extern __shared__ char sm[];
    const uint32_t smem = smem_u32(sm);
    const int tid = threadIdx.x;
    const int w = tid >> 5;
    const int l = tid & 31;
    const int b = blockIdx.y;
    const int qi0 = blockIdx.x * QT;

    {
        long long tok0 = (long long)b * SS + qi0;
        #pragma unroll
        for (int it = 0; it < 16; it++) {
            int ci = tid + it * 256;
            int c = ci & 15;
            int row = (ci >> 4) & 127;
            const __half* src = ((ci < 2048) ? g_qh : g_ql) + (tok0 + row) * DD + c * 8;
            uint32_t dst = smem + ((ci < 2048) ? OFF_QH : OFF_QL) + row * (QSTR*2) + c * 16;
            cp16(dst, src);
        }
    }
    load_k(smem, b, 0, 0, tid);
    load_v(smem, b, 0, 0, tid);
    load_k(smem, b, 1, 1, tid);
    CP_COMMIT();
    CP_WAIT0();
    __syncthreads();

    float of[16][4];
    #pragma unroll
    for (int n = 0; n < 16; n++)
        #pragma unroll
        for (int c = 0; c < 4; c++) of[n][c] = 0.f;
    float m0 = -INFINITY, m1 = -INFINITY, l0 = 0.f, l1 = 0.f;

    const uint32_t qoff  = smem + (w*16 + (l & 15)) * (QSTR*2) + ((l >> 4) * 16);
    const uint32_t brow  = (l & 7) + ((l >> 4) & 1) * 8;
    const uint32_t bcsel = ((l >> 3) & 1) * 16;

    float sfA[8][4], sfB[8][4];
    compute_S(sfA, qoff, smem + OFF_K, brow, bcsel);
    __syncthreads();

    #pragma unroll 1
    for (int t = 0; t < NTILE; t += 2) {
        flash_iter(t,     sfA, sfB, of, m0, m1, l0, l1, smem, b, tid, qoff, brow, bcsel);
        flash_iter(t + 1, sfB, sfA, of, m0, m1, l0, l1, smem, b, tid, qoff, brow, bcsel);
    }

    l0 += __shfl_xor_sync(0xffffffffu, l0, 1);
    l0 += __shfl_xor_sync(0xffffffffu, l0, 2);
    l1 += __shfl_xor_sync(0xffffffffu, l1, 1);
    l1 += __shfl_xor_sync(0xffffffffu, l1, 2);

    const int row0 = w*16 + (l >> 2);
    const float inv0 = 1.0f / l0, inv1 = 1.0f / l1;
    long long base0 = ((long long)b * SS + qi0 + row0) * DD;
    long long base1 = base0 + 8LL * DD;
    #pragma unroll
    for (int n = 0; n < 16; n++) {
        int cc = n*8 + (l & 3)*2;
        *(float2*)(out + base0 + cc) = make_float2(of[n][0]*inv0, of[n][1]*inv0);
        *(float2*)(out + base1 + cc) = make_float2(of[n][2]*inv1, of[n][3]*inv1);
    }
}

// ============================================================================
// launch
// ============================================================================
extern "C" void kernel_launch(void* const* d_in, const int* in_sizes, int n_in,
                              void* d_out, int out_size)
{
    const float* x  = (const float*)d_in[0];
    const float* Wq = (const float*)d_in[1];
    const float* bq = (const float*)d_in[2];
    const float* Wk = (const float*)d_in[3];
    const float* bk = (const float*)d_in[4];
    const float* Wv = (const float*)d_in[5];
    const float* bv = (const float*)d_in[6];
    float* out = (float*)d_out;

    split_w<<<(3*DD*EE)/256, 256>>>(Wq, Wk, Wv);

    cudaFuncSetAttribute(qkv_mma, cudaFuncAttributeMaxDynamicSharedMemorySize,
                         QKV_SMEM);
    qkv_mma<<<MM/64, 256, QKV_SMEM>>>(x, bq, bk, bv);

    cudaFuncSetAttribute(flash_attn, cudaFuncAttributeMaxDynamicSharedMemorySize,
                         FLASH_SMEM);
    flash_attn<<<dim3(SS / QT, BB), 256, FLASH_SMEM>>>(out);
}

// round 13
// speedup vs baseline: 1.1835x; 1.0116x over previous
#include <cuda_runtime.h>
#include <cuda_fp16.h>
#include <math.h>
#include <stdint.h>

#define BB 8
#define SS 4096
#define EE 2048
#define DD 128
#define MM (BB*SS)   // 32768

#define LOG2E 1.44269504088896340736f

// fp16 scratch (allocation-free __device__ globals)
__device__ __half g_qh[MM*DD];    // q scaled by log2e
__device__ __half g_ql[MM*DD];
__device__ __half g_kh[MM*DD];
__device__ __half g_kl[MM*DD];
__device__ __half g_vth[MM*DD];   // v transposed [b][d][s]
__device__ __half g_wth[3*DD*EE]; // W transposed hi (Wq pre-scaled by log2e)
__device__ __half g_wtl[3*DD*EE];

typedef unsigned long long u64;

__device__ __forceinline__ uint32_t pack_h2(float a, float b) {
    __half ha = __float2half_rn(a), hb = __float2half_rn(b);
    return ((uint32_t)__half_as_ushort(hb) << 16) | (uint32_t)__half_as_ushort(ha);
}
__device__ __forceinline__ uint32_t cvt_h2(float a, float b) {
    uint32_t r;
    asm("cvt.rn.f16x2.f32 %0, %1, %2;" : "=r"(r) : "f"(b), "f"(a));
    return r;
}
__device__ __forceinline__ uint32_t smem_u32(const void* p) {
    uint32_t a;
    asm("{ .reg .u64 t; cvta.to.shared.u64 t, %1; cvt.u32.u64 %0, t; }" : "=r"(a) : "l"(p));
    return a;
}
__device__ __forceinline__ float ex2(float x) {
    float r; asm("ex2.approx.f32 %0, %1;" : "=f"(r) : "f"(x)); return r;
}

__device__ __forceinline__ void cp16(uint32_t dst, const void* src) {
    asm volatile("cp.async.cg.shared.global [%0], [%1], 16;" :: "r"(dst), "l"(src));
}
#define CP_COMMIT() asm volatile("cp.async.commit_group;" ::: "memory")
#define CP_WAIT0()  asm volatile("cp.async.wait_group 0;" ::: "memory")

__device__ __forceinline__ void ldsm4(uint32_t r[4], uint32_t addr) {
    asm volatile("ldmatrix.sync.aligned.m8n8.x4.shared.b16 {%0,%1,%2,%3}, [%4];"
        : "=r"(r[0]), "=r"(r[1]), "=r"(r[2]), "=r"(r[3]) : "r"(addr));
}
__device__ __forceinline__ void mma16816(float c[4], const uint32_t a[4],
                                          uint32_t b0, uint32_t b1) {
    asm volatile("mma.sync.aligned.m16n8k16.row.col.f32.f16.f16.f32 "
        "{%0,%1,%2,%3}, {%4,%5,%6,%7}, {%8,%9}, {%0,%1,%2,%3};"
        : "+f"(c[0]), "+f"(c[1]), "+f"(c[2]), "+f"(c[3])
        : "r"(a[0]), "r"(a[1]), "r"(a[2]), "r"(a[3]), "r"(b0), "r"(b1));
}

// ============================================================================
// Kernel 0: split W (transposed fp16 hi/lo). Wq pre-scaled by log2e.
// ============================================================================
__global__ __launch_bounds__(256) void split_w(
    const float* __restrict__ Wq, const float* __restrict__ Wk,
    const float* __restrict__ Wv)
{
    int idx = blockIdx.x * 256 + threadIdx.x;
    int y = idx >> 18;
    int rem = idx & ((DD*EE) - 1);
    int d = rem >> 11;
    int e = rem & (EE - 1);
    const float* W = (y == 0) ? Wq : (y == 1) ? Wk : Wv;
    float v = W[(long long)e * DD + d];
    if (y == 0) v *= LOG2E;
    __half h = __float2half_rn(v);
    g_wth[idx] = h;
    g_wtl[idx] = __float2half_rn(v - __half2float(h));
}

// ============================================================================
// Kernel 1: fused QKV projection, double-buffered, 512 threads / 16 warps
// (4 warps per SMSP for latency hiding). Warp grid 4M x 4N, warp tile 16x32.
//   q,k: 3 terms (xh*Wh + xl*Wh + xh*Wl);  v: 1 term (xh*Wvh).
// ============================================================================
#define BK 64
#define PLN 18432                   // one W plane: 128 rows x 144B
#define SXH 0                       // x hi: 64 x 144B = 9216
#define SXL 9216
#define SW  18432                   // planes: [qh,ql,kh,kl,vh]
#define QBUF (SW + 5*PLN)           // 110592
#define QKV_SMEM (2*QBUF)           // 221184
#define NCHUNK (EE/BK)              // 32
#define QKV_THR 512

__device__ __forceinline__ void qkv_w_ld(uint32_t smem, int bufoff, int kt, int tid) {
    #pragma unroll
    for (int j = 0; j < 10; j++) {
        int idx = tid + j * QKV_THR;        // 0..5119
        int p = idx >> 10;                  // plane 0..4
        int rem = idx & 1023;
        int n = rem >> 3, ch = rem & 7;
        int y = (p < 4) ? (p >> 1) : 2;
        const __half* base = ((p < 4) && (p & 1)) ? g_wtl : g_wth;
        const __half* src = base + (long long)y * DD * EE + (long long)n * EE
                            + kt * BK + ch * 8;
        cp16(smem + bufoff + SW + p * PLN + n * 144 + ch * 16, src);
    }
}

// x loader: row = tid>>3 (8 thr/row), 8 floats per thread at col (tid&7)*8
__device__ __forceinline__ void qkv_stx(char* sm, int bufoff, const float4* xr, int tid) {
    int boff = (tid >> 3) * 144 + (tid & 7) * 16;
    #pragma unroll
    for (int i = 0; i < 2; i++) {
        float4 v = xr[i];
        float h0 = __half2float(__float2half_rn(v.x));
        float h1 = __half2float(__float2half_rn(v.y));
        float h2 = __half2float(__float2half_rn(v.z));
        float h3 = __half2float(__float2half_rn(v.w));
        uint2 uh = make_uint2(pack_h2(h0, h1), pack_h2(h2, h3));
        uint2 ul = make_uint2(pack_h2(v.x - h0, v.y - h1), pack_h2(v.z - h2, v.w - h3));
        *(uint2*)(sm + bufoff + SXH + boff + 8 * i) = uh;
        *(uint2*)(sm + bufoff + SXL + boff + 8 * i) = ul;
    }
}

__global__ void __launch_bounds__(QKV_THR, 1) qkv_mma(
    const float* __restrict__ x,
    const float* __restrict__ bq, const float* __restrict__ bk,
    const float* __restrict__ bv)
{
    extern __shared__ char sm[];
    const uint32_t smem = smem_u32(sm);
    const int tid = threadIdx.x;
    const int w = tid >> 5;
    const int l = tid & 31;
    const int m0 = blockIdx.x * 64;

    const int wm = (w >> 2) * 16;        // 4 M-groups of 16 rows
    const int wn = (w & 3) * 32;         // 4 N-groups of 32 cols
    const uint32_t brow  = (l & 7) + ((l >> 4) & 1) * 8;
    const uint32_t bcsel = ((l >> 3) & 1) * 16;

    const float* xg = x + (long long)(m0 + (tid >> 3)) * EE + (tid & 7) * 8;

    // of[y][nf2*2 n8-frags][acc4] = 48 floats
    float of[3][4][4];
    #pragma unroll
    for (int y = 0; y < 3; y++)
        #pragma unroll
        for (int n = 0; n < 4; n++)
            #pragma unroll
            for (int c = 0; c < 4; c++) of[y][n][c] = 0.f;

    // prologue: chunk 0
    float4 xr[2];
    xr[0] = *(const float4*)xg;
    xr[1] = *(const float4*)(xg + 4);
    qkv_w_ld(smem, 0, 0, tid);
    CP_COMMIT();
    qkv_stx(sm, 0, xr, tid);
    CP_WAIT0();
    __syncthreads();

    int buf = 0;
    for (int kt = 0; kt < NCHUNK; kt++) {
        const int nb = buf ^ 1;
        if (kt + 1 < NCHUNK) {
            xr[0] = *(const float4*)(xg + (kt + 1) * BK);
            xr[1] = *(const float4*)(xg + (kt + 1) * BK + 4);
            qkv_w_ld(smem, nb * QBUF, kt + 1, tid);
            CP_COMMIT();
        }

        const uint32_t aoff = smem + buf * QBUF + SXH
                            + (wm + (l & 15)) * 144 + (l >> 4) * 16;
        const uint32_t wb = smem + buf * QBUF + SW;
        #pragma unroll
        for (int kc = 0; kc < 4; kc++) {
            uint32_t ah[4], al[4];
            ldsm4(ah, aoff + kc * 32);
            ldsm4(al, aoff + (SXL - SXH) + kc * 32);
            #pragma unroll
            for (int y = 0; y < 3; y++) {
                const uint32_t wby = wb + ((y < 2) ? (y * 2) * PLN : 4 * PLN);
                #pragma unroll
                for (int nf = 0; nf < 2; nf++) {   // two 16-col fragments
                    uint32_t baddr = wby + (wn + nf*16 + brow) * 144 + kc * 32 + bcsel;
                    uint32_t bh[4];
                    ldsm4(bh, baddr);
                    mma16816(of[y][2*nf],   ah, bh[0], bh[1]);
                    mma16816(of[y][2*nf+1], ah, bh[2], bh[3]);
                    if (y < 2) {
                        mma16816(of[y][2*nf],   al, bh[0], bh[1]);
                        mma16816(of[y][2*nf+1], al, bh[2], bh[3]);
                        uint32_t bl2[4];
                        ldsm4(bl2, baddr + PLN);
                        mma16816(of[y][2*nf],   ah, bl2[0], bl2[1]);
                        mma16816(of[y][2*nf+1], ah, bl2[2], bl2[3]);
                    }
                }
            }
        }

        if (kt + 1 < NCHUNK) {
            qkv_stx(sm, nb * QBUF, xr, tid);
            CP_WAIT0();
        }
        __syncthreads();
        buf = nb;
    }

    // ---- epilogue: all three outputs ----
    const int row0 = m0 + wm + (l >> 2);
    const int row1 = row0 + 8;
    #pragma unroll
    for (int y = 0; y < 3; y++) {
        const float* bias = (y == 0) ? bq : (y == 1) ? bk : bv;
        const float bscale = (y == 0) ? LOG2E : 1.0f;
        #pragma unroll
        for (int nn = 0; nn < 4; nn++) {
            int col = wn + nn * 8 + (l & 3) * 2;
            float b0 = bias[col] * bscale, b1 = bias[col + 1] * bscale;
            float v00 = of[y][nn][0] + b0, v01 = of[y][nn][1] + b1;
            float v10 = of[y][nn][2] + b0, v11 = of[y][nn][3] + b1;
            float h00 = __half2float(__float2half_rn(v00));
            float h01 = __half2float(__float2half_rn(v01));
            float h10 = __half2float(__float2half_rn(v10));
            float h11 = __half2float(__float2half_rn(v11));

            if (y < 2) {
                __half* ph = (y == 0) ? g_qh : g_kh;
                __half* pl = (y == 0) ? g_ql : g_kl;
                *(uint32_t*)&ph[(long long)row0 * DD + col] = pack_h2(h00, h01);
                *(uint32_t*)&ph[(long long)row1 * DD + col] = pack_h2(h10, h11);
                *(uint32_t*)&pl[(long long)row0 * DD + col] = pack_h2(v00 - h00, v01 - h01);
                *(uint32_t*)&pl[(long long)row1 * DD + col] = pack_h2(v10 - h10, v11 - h11);
            } else {
                int bbx0 = row0 >> 12, s0 = row0 & 4095;
                int bbx1 = row1 >> 12, s1 = row1 & 4095;
                g_vth[((long long)bbx0 * DD + col) * SS + s0]     = __float2half_rn(h00);
                g_vth[((long long)bbx0 * DD + col + 1) * SS + s0] = __float2half_rn(h01);
                g_vth[((long long)bbx1 * DD + col) * SS + s1]     = __float2half_rn(h10);
                g_vth[((long long)bbx1 * DD + col + 1) * SS + s1] = __float2half_rn(h11);
            }
        }
    }
}

// ============================================================================
// Kernel 2: flash attention (round-8 version — fastest measured; unchanged).
// ============================================================================
#define QT 128
#define KT 64
#define NTILE (SS/KT)   // 64
#define QSTR 136
#define KSTR 136
#define VSTR 72

#define OFF_QH 0
#define OFF_QL (128*QSTR*2)
#define OFF_K  (OFF_QL + 128*QSTR*2)
#define KBUF   (64*KSTR*2*2)
#define KLOFF  (64*KSTR*2)
#define OFF_V  (OFF_K + 2*KBUF)
#define VBUF   (128*VSTR*2)
#define FLASH_SMEM (OFF_V + 2*VBUF)     // 176128

__device__ __forceinline__ void load_k(uint32_t smem, int b, int kt, int buf, int tid) {
    long long tok0 = (long long)b * SS + (long long)kt * KT;
    #pragma unroll
    for (int it = 0; it < 8; it++) {
        int ci = tid + it * 256;
        int c = ci & 15;
        int row = (ci >> 4) & 63;
        const __half* src = ((ci < 1024) ? g_kh : g_kl) + (tok0 + row) * DD + c * 8;
        uint32_t dst = smem + OFF_K + buf * KBUF + ((ci < 1024) ? 0 : KLOFF)
                       + row * (KSTR*2) + c * 16;
        cp16(dst, src);
    }
}
__device__ __forceinline__ void load_v(uint32_t smem, int b, int kt, int buf, int tid) {
    long long vbase = (long long)b * DD * SS + (long long)kt * KT;
    #pragma unroll
    for (int it = 0; it < 4; it++) {
        int ci = tid + it * 256;
        int c = ci & 7;
        int d = (ci >> 3) & 127;
        const __half* src = g_vth + vbase + (long long)d * SS + c * 8;
        uint32_t dst = smem + OFF_V + buf * VBUF + d * (VSTR*2) + c * 16;
        cp16(dst, src);
    }
}

__device__ __forceinline__ void compute_S(float sf[8][4], uint32_t qoff, uint32_t kb,
                                          uint32_t brow, uint32_t bcsel) {
    #pragma unroll
    for (int j = 0; j < 8; j++)
        #pragma unroll
        for (int c = 0; c < 4; c++) sf[j][c] = 0.f;
    #pragma unroll
    for (int kc = 0; kc < 8; kc++) {
        uint32_t ah[4], al[4];
        ldsm4(ah, qoff + OFF_QH + kc * 32);
        ldsm4(al, qoff + OFF_QL + kc * 32);
        #pragma unroll
        for (int jp = 0; jp < 4; jp++) {
            uint32_t baddr = kb + (jp*16 + brow) * (KSTR*2) + kc * 32 + bcsel;
            uint32_t bh[4], blr[4];
            ldsm4(bh, baddr);
            ldsm4(blr, baddr + KLOFF);
            mma16816(sf[2*jp],   ah, bh[0], bh[1]);
            mma16816(sf[2*jp+1], ah, bh[2], bh[3]);
            mma16816(sf[2*jp],   al, bh[0], bh[1]);
            mma16816(sf[2*jp+1], al, bh[2], bh[3]);
            mma16816(sf[2*jp],   ah, blr[0], blr[1]);
            mma16816(sf[2*jp+1], ah, blr[2], blr[3]);
        }
    }
}

__device__ __forceinline__ void flash_iter(
    int t, float sfA[8][4], float sfB[8][4], float of[16][4],
    float& m0, float& m1, float& l0, float& l1,
    uint32_t smem, int b, int tid, uint32_t qoff, uint32_t brow, uint32_t bcsel)
{
    if (t + 2 < NTILE) load_k(smem, b, t + 2, t & 1, tid);
    if (t + 1 < NTILE) load_v(smem, b, t + 1, (t + 1) & 1, tid);
    CP_COMMIT();

    if (t + 1 < NTILE)
        compute_S(sfB, qoff, smem + OFF_K + ((t + 1) & 1) * KBUF, brow, bcsel);

    float mx0 = sfA[0][0], mx1 = sfA[0][2];
    #pragma unroll
    for (int j = 0; j < 8; j++) {
        mx0 = fmaxf(mx0, fmaxf(sfA[j][0], sfA[j][1]));
        mx1 = fmaxf(mx1, fmaxf(sfA[j][2], sfA[j][3]));
    }
    mx0 = fmaxf(mx0, __shfl_xor_sync(0xffffffffu, mx0, 1));
    mx0 = fmaxf(mx0, __shfl_xor_sync(0xffffffffu, mx0, 2));
    mx1 = fmaxf(mx1, __shfl_xor_sync(0xffffffffu, mx1, 1));
    mx1 = fmaxf(mx1, __shfl_xor_sync(0xffffffffu, mx1, 2));

    if (mx0 > m0) {
        float a = ex2(m0 - mx0);
        m0 = mx0; l0 *= a;
        #pragma unroll
        for (int n = 0; n < 16; n++) { of[n][0] *= a; of[n][1] *= a; }
    }
    if (mx1 > m1) {
        float a = ex2(m1 - mx1);
        m1 = mx1; l1 *= a;
        #pragma unroll
        for (int n = 0; n < 16; n++) { of[n][2] *= a; of[n][3] *= a; }
    }

    #pragma unroll
    for (int j = 0; j < 8; j++) {
        sfA[j][0] = ex2(sfA[j][0] - m0); l0 += sfA[j][0];
        sfA[j][1] = ex2(sfA[j][1] - m0); l0 += sfA[j][1];
        sfA[j][2] = ex2(sfA[j][2] - m1); l1 += sfA[j][2];
        sfA[j][3] = ex2(sfA[j][3] - m1); l1 += sfA[j][3];
    }

    const uint32_t vb = smem + OFF_V + (t & 1) * VBUF;
    #pragma unroll
    for (int jk = 0; jk < 4; jk++) {
        uint32_t ph[4];
        ph[0] = cvt_h2(sfA[2*jk][0],   sfA[2*jk][1]);
        ph[1] = cvt_h2(sfA[2*jk][2],   sfA[2*jk][3]);
        ph[2] = cvt_h2(sfA[2*jk+1][0], sfA[2*jk+1][1]);
        ph[3] = cvt_h2(sfA[2*jk+1][2], sfA[2*jk+1][3]);
        #pragma unroll
        for (int np = 0; np < 8; np++) {
            uint32_t vaddr = vb + (np*16 + brow) * (VSTR*2) + jk * 32 + bcsel;
            uint32_t vh[4];
            ldsm4(vh, vaddr);
            mma16816(of[2*np],   ph, vh[0], vh[1]);
            mma16816(of[2*np+1], ph, vh[2], vh[3]);
        }
    }

    CP_WAIT0();
    __syncthreads();
}

__global__ __launch_bounds__(256, 1) void flash_attn(float* __restrict__ out)
{
    extern __shared__ char sm[];
    const uint32_t smem = smem_u32(sm);
    const int tid = threadIdx.x;
    const int w = tid >> 5;
    const int l = tid & 31;
    const int b = blockIdx.y;
    const int qi0 = blockIdx.x * QT;

    {
        long long tok0 = (long long)b * SS + qi0;
        #pragma unroll
        for (int it = 0; it < 16; it++) {
            int ci = tid + it * 256;
            int c = ci & 15;
            int row = (ci >> 4) & 127;
            const __half* src = ((ci < 2048) ? g_qh : g_ql) + (tok0 + row) * DD + c * 8;
            uint32_t dst = smem + ((ci < 2048) ? OFF_QH : OFF_QL) + row * (QSTR*2) + c * 16;
            cp16(dst, src);
        }
    }
    load_k(smem, b, 0, 0, tid);
    load_v(smem, b, 0, 0, tid);
    load_k(smem, b, 1, 1, tid);
    CP_COMMIT();
    CP_WAIT0();
    __syncthreads();

    float of[16][4];
    #pragma unroll
    for (int n = 0; n < 16; n++)
        #pragma unroll
        for (int c = 0; c < 4; c++) of[n][c] = 0.f;
    float m0 = -INFINITY, m1 = -INFINITY, l0 = 0.f, l1 = 0.f;

    const uint32_t qoff  = smem + (w*16 + (l & 15)) * (QSTR*2) + ((l >> 4) * 16);
    const uint32_t brow  = (l & 7) + ((l >> 4) & 1) * 8;
    const uint32_t bcsel = ((l >> 3) & 1) * 16;

    float sfA[8][4], sfB[8][4];
    compute_S(sfA, qoff, smem + OFF_K, brow, bcsel);
    __syncthreads();

    #pragma unroll 1
    for (int t = 0; t < NTILE; t += 2) {
        flash_iter(t,     sfA, sfB, of, m0, m1, l0, l1, smem, b, tid, qoff, brow, bcsel);
        flash_iter(t + 1, sfB, sfA, of, m0, m1, l0, l1, smem, b, tid, qoff, brow, bcsel);
    }

    l0 += __shfl_xor_sync(0xffffffffu, l0, 1);
    l0 += __shfl_xor_sync(0xffffffffu, l0, 2);
    l1 += __shfl_xor_sync(0xffffffffu, l1, 1);
    l1 += __shfl_xor_sync(0xffffffffu, l1, 2);

    const int row0 = w*16 + (l >> 2);
    const float inv0 = 1.0f / l0, inv1 = 1.0f / l1;
    long long base0 = ((long long)b * SS + qi0 + row0) * DD;
    long long base1 = base0 + 8LL * DD;
    #pragma unroll
    for (int n = 0; n < 16; n++) {
        int cc = n*8 + (l & 3)*2;
        *(float2*)(out + base0 + cc) = make_float2(of[n][0]*inv0, of[n][1]*inv0);
        *(float2*)(out + base1 + cc) = make_float2(of[n][2]*inv1, of[n][3]*inv1);
    }
}

// ============================================================================
// launch
// ============================================================================
extern "C" void kernel_launch(void* const* d_in, const int* in_sizes, int n_in,
                              void* d_out, int out_size)
{
    const float* x  = (const float*)d_in[0];
    const float* Wq = (const float*)d_in[1];
    const float* bq = (const float*)d_in[2];
    const float* Wk = (const float*)d_in[3];
    const float* bk = (const float*)d_in[4];
    const float* Wv = (const float*)d_in[5];
    const float* bv = (const float*)d_in[6];
    float* out = (float*)d_out;

    split_w<<<(3*DD*EE)/256, 256>>>(Wq, Wk, Wv);

    cudaFuncSetAttribute(qkv_mma, cudaFuncAttributeMaxDynamicSharedMemorySize,
                         QKV_SMEM);
    qkv_mma<<<MM/64, QKV_THR, QKV_SMEM>>>(x, bq, bk, bv);

    cudaFuncSetAttribute(flash_attn, cudaFuncAttributeMaxDynamicSharedMemorySize,
                         FLASH_SMEM);
    flash_attn<<<dim3(SS / QT, BB), 256, FLASH_SMEM>>>(out);
}

// round 14
// speedup vs baseline: 1.1875x; 1.0034x over previous
#include <cuda_runtime.h>
#include <cuda_fp16.h>
#include <math.h>
#include <stdint.h>

#define BB 8
#define SS 4096
#define EE 2048
#define DD 128
#define MM (BB*SS)   // 32768

#define LOG2E 1.44269504088896340736f

// fp16 scratch (allocation-free __device__ globals)
__device__ __half g_qh[MM*DD];    // q scaled by log2e
__device__ __half g_ql[MM*DD];
__device__ __half g_kh[MM*DD];
__device__ __half g_kl[MM*DD];
__device__ __half g_vth[MM*DD];   // v transposed [b][d][s]
__device__ __half g_wth[3*DD*EE]; // W transposed hi (Wq pre-scaled by log2e)
__device__ __half g_wtl[3*DD*EE];

typedef unsigned long long u64;

__device__ __forceinline__ uint32_t pack_h2(float a, float b) {
    __half ha = __float2half_rn(a), hb = __float2half_rn(b);
    return ((uint32_t)__half_as_ushort(hb) << 16) | (uint32_t)__half_as_ushort(ha);
}
__device__ __forceinline__ uint32_t cvt_h2(float a, float b) {
    uint32_t r;
    asm("cvt.rn.f16x2.f32 %0, %1, %2;" : "=r"(r) : "f"(b), "f"(a));
    return r;
}
__device__ __forceinline__ uint32_t smem_u32(const void* p) {
    uint32_t a;
    asm("{ .reg .u64 t; cvta.to.shared.u64 t, %1; cvt.u32.u64 %0, t; }" : "=r"(a) : "l"(p));
    return a;
}
__device__ __forceinline__ float ex2(float x) {
    float r; asm("ex2.approx.f32 %0, %1;" : "=f"(r) : "f"(x)); return r;
}

__device__ __forceinline__ void cp16(uint32_t dst, const void* src) {
    asm volatile("cp.async.cg.shared.global [%0], [%1], 16;" :: "r"(dst), "l"(src));
}
#define CP_COMMIT() asm volatile("cp.async.commit_group;" ::: "memory")
#define CP_WAIT0()  asm volatile("cp.async.wait_group 0;" ::: "memory")

__device__ __forceinline__ void ldsm4(uint32_t r[4], uint32_t addr) {
    asm volatile("ldmatrix.sync.aligned.m8n8.x4.shared.b16 {%0,%1,%2,%3}, [%4];"
        : "=r"(r[0]), "=r"(r[1]), "=r"(r[2]), "=r"(r[3]) : "r"(addr));
}
__device__ __forceinline__ void mma16816(float c[4], const uint32_t a[4],
                                          uint32_t b0, uint32_t b1) {
    asm volatile("mma.sync.aligned.m16n8k16.row.col.f32.f16.f16.f32 "
        "{%0,%1,%2,%3}, {%4,%5,%6,%7}, {%8,%9}, {%0,%1,%2,%3};"
        : "+f"(c[0]), "+f"(c[1]), "+f"(c[2]), "+f"(c[3])
        : "r"(a[0]), "r"(a[1]), "r"(a[2]), "r"(a[3]), "r"(b0), "r"(b1));
}

// ============================================================================
// Kernel 0: split W (transposed fp16 hi/lo). Wq pre-scaled by log2e.
// ============================================================================
__global__ __launch_bounds__(256) void split_w(
    const float* __restrict__ Wq, const float* __restrict__ Wk,
    const float* __restrict__ Wv)
{
    int idx = blockIdx.x * 256 + threadIdx.x;
    int y = idx >> 18;
    int rem = idx & ((DD*EE) - 1);
    int d = rem >> 11;
    int e = rem & (EE - 1);
    const float* W = (y == 0) ? Wq : (y == 1) ? Wk : Wv;
    float v = W[(long long)e * DD + d];
    if (y == 0) v *= LOG2E;
    __half h = __float2half_rn(v);
    g_wth[idx] = h;
    g_wtl[idx] = __float2half_rn(v - __half2float(h));
}

// ============================================================================
// Kernel 1: fused QKV projection (round-13 version, best measured).
// 512 threads / 16 warps, warp grid 4M x 4N, double-buffered.
//   q,k: 3 terms;  v: 1 term.
// ============================================================================
#define BK 64
#define PLN 18432
#define SXH 0
#define SXL 9216
#define SW  18432
#define QBUF (SW + 5*PLN)           // 110592
#define QKV_SMEM (2*QBUF)           // 221184
#define NCHUNK (EE/BK)              // 32
#define QKV_THR 512

__device__ __forceinline__ void qkv_w_ld(uint32_t smem, int bufoff, int kt, int tid) {
    #pragma unroll
    for (int j = 0; j < 10; j++) {
        int idx = tid + j * QKV_THR;
        int p = idx >> 10;
        int rem = idx & 1023;
        int n = rem >> 3, ch = rem & 7;
        int y = (p < 4) ? (p >> 1) : 2;
        const __half* base = ((p < 4) && (p & 1)) ? g_wtl : g_wth;
        const __half* src = base + (long long)y * DD * EE + (long long)n * EE
                            + kt * BK + ch * 8;
        cp16(smem + bufoff + SW + p * PLN + n * 144 + ch * 16, src);
    }
}

__device__ __forceinline__ void qkv_stx(char* sm, int bufoff, const float4* xr, int tid) {
    int boff = (tid >> 3) * 144 + (tid & 7) * 16;
    #pragma unroll
    for (int i = 0; i < 2; i++) {
        float4 v = xr[i];
        float h0 = __half2float(__float2half_rn(v.x));
        float h1 = __half2float(__float2half_rn(v.y));
        float h2 = __half2float(__float2half_rn(v.z));
        float h3 = __half2float(__float2half_rn(v.w));
        uint2 uh = make_uint2(pack_h2(h0, h1), pack_h2(h2, h3));
        uint2 ul = make_uint2(pack_h2(v.x - h0, v.y - h1), pack_h2(v.z - h2, v.w - h3));
        *(uint2*)(sm + bufoff + SXH + boff + 8 * i) = uh;
        *(uint2*)(sm + bufoff + SXL + boff + 8 * i) = ul;
    }
}

__global__ void __launch_bounds__(QKV_THR, 1) qkv_mma(
    const float* __restrict__ x,
    const float* __restrict__ bq, const float* __restrict__ bk,
    const float* __restrict__ bv)
{
    extern __shared__ char sm[];
    const uint32_t smem = smem_u32(sm);
    const int tid = threadIdx.x;
    const int w = tid >> 5;
    const int l = tid & 31;
    const int m0 = blockIdx.x * 64;

    const int wm = (w >> 2) * 16;
    const int wn = (w & 3) * 32;
    const uint32_t brow  = (l & 7) + ((l >> 4) & 1) * 8;
    const uint32_t bcsel = ((l >> 3) & 1) * 16;

    const float* xg = x + (long long)(m0 + (tid >> 3)) * EE + (tid & 7) * 8;

    float of[3][4][4];
    #pragma unroll
    for (int y = 0; y < 3; y++)
        #pragma unroll
        for (int n = 0; n < 4; n++)
            #pragma unroll
            for (int c = 0; c < 4; c++) of[y][n][c] = 0.f;

    float4 xr[2];
    xr[0] = *(const float4*)xg;
    xr[1] = *(const float4*)(xg + 4);
    qkv_w_ld(smem, 0, 0, tid);
    CP_COMMIT();
    qkv_stx(sm, 0, xr, tid);
    CP_WAIT0();
    __syncthreads();

    int buf = 0;
    for (int kt = 0; kt < NCHUNK; kt++) {
        const int nb = buf ^ 1;
        if (kt + 1 < NCHUNK) {
            xr[0] = *(const float4*)(xg + (kt + 1) * BK);
            xr[1] = *(const float4*)(xg + (kt + 1) * BK + 4);
            qkv_w_ld(smem, nb * QBUF, kt + 1, tid);
            CP_COMMIT();
        }

        const uint32_t aoff = smem + buf * QBUF + SXH
                            + (wm + (l & 15)) * 144 + (l >> 4) * 16;
        const uint32_t wb = smem + buf * QBUF + SW;
        #pragma unroll
        for (int kc = 0; kc < 4; kc++) {
            uint32_t ah[4], al[4];
            ldsm4(ah, aoff + kc * 32);
            ldsm4(al, aoff + (SXL - SXH) + kc * 32);
            #pragma unroll
            for (int y = 0; y < 3; y++) {
                const uint32_t wby = wb + ((y < 2) ? (y * 2) * PLN : 4 * PLN);
                #pragma unroll
                for (int nf = 0; nf < 2; nf++) {
                    uint32_t baddr = wby + (wn + nf*16 + brow) * 144 + kc * 32 + bcsel;
                    uint32_t bh[4];
                    ldsm4(bh, baddr);
                    mma16816(of[y][2*nf],   ah, bh[0], bh[1]);
                    mma16816(of[y][2*nf+1], ah, bh[2], bh[3]);
                    if (y < 2) {
                        mma16816(of[y][2*nf],   al, bh[0], bh[1]);
                        mma16816(of[y][2*nf+1], al, bh[2], bh[3]);
                        uint32_t bl2[4];
                        ldsm4(bl2, baddr + PLN);
                        mma16816(of[y][2*nf],   ah, bl2[0], bl2[1]);
                        mma16816(of[y][2*nf+1], ah, bl2[2], bl2[3]);
                    }
                }
            }
        }

        if (kt + 1 < NCHUNK) {
            qkv_stx(sm, nb * QBUF, xr, tid);
            CP_WAIT0();
        }
        __syncthreads();
        buf = nb;
    }

    const int row0 = m0 + wm + (l >> 2);
    const int row1 = row0 + 8;
    #pragma unroll
    for (int y = 0; y < 3; y++) {
        const float* bias = (y == 0) ? bq : (y == 1) ? bk : bv;
        const float bscale = (y == 0) ? LOG2E : 1.0f;
        #pragma unroll
        for (int nn = 0; nn < 4; nn++) {
            int col = wn + nn * 8 + (l & 3) * 2;
            float b0 = bias[col] * bscale, b1 = bias[col + 1] * bscale;
            float v00 = of[y][nn][0] + b0, v01 = of[y][nn][1] + b1;
            float v10 = of[y][nn][2] + b0, v11 = of[y][nn][3] + b1;
            float h00 = __half2float(__float2half_rn(v00));
            float h01 = __half2float(__float2half_rn(v01));
            float h10 = __half2float(__float2half_rn(v10));
            float h11 = __half2float(__float2half_rn(v11));

            if (y < 2) {
                __half* ph = (y == 0) ? g_qh : g_kh;
                __half* pl = (y == 0) ? g_ql : g_kl;
                *(uint32_t*)&ph[(long long)row0 * DD + col] = pack_h2(h00, h01);
                *(uint32_t*)&ph[(long long)row1 * DD + col] = pack_h2(h10, h11);
                *(uint32_t*)&pl[(long long)row0 * DD + col] = pack_h2(v00 - h00, v01 - h01);
                *(uint32_t*)&pl[(long long)row1 * DD + col] = pack_h2(v10 - h10, v11 - h11);
            } else {
                int bbx0 = row0 >> 12, s0 = row0 & 4095;
                int bbx1 = row1 >> 12, s1 = row1 & 4095;
                g_vth[((long long)bbx0 * DD + col) * SS + s0]     = __float2half_rn(h00);
                g_vth[((long long)bbx0 * DD + col + 1) * SS + s0] = __float2half_rn(h01);
                g_vth[((long long)bbx1 * DD + col) * SS + s1]     = __float2half_rn(h10);
                g_vth[((long long)bbx1 * DD + col + 1) * SS + s1] = __float2half_rn(h11);
            }
        }
    }
}

// ============================================================================
// Kernel 2: flash attention with Q fragments HOISTED TO REGISTERS.
// Removes 16 LDSM.x4/warp/tile (64KB/SM/tile of crossbar traffic).
//   S  = Qh*Kh + Ql*Kh + Qh*Kl ; PV = P(fp16)*V(fp16)
// ============================================================================
#define QT 128
#define KT 64
#define NTILE (SS/KT)   // 64
#define QSTR 136
#define KSTR 136
#define VSTR 72

#define OFF_QH 0
#define OFF_QL (128*QSTR*2)
#define OFF_K  (OFF_QL + 128*QSTR*2)
#define KBUF   (64*KSTR*2*2)
#define KLOFF  (64*KSTR*2)
#define OFF_V  (OFF_K + 2*KBUF)
#define VBUF   (128*VSTR*2)
#define FLASH_SMEM (OFF_V + 2*VBUF)     // 176128

__device__ __forceinline__ void load_k(uint32_t smem, int b, int kt, int buf, int tid) {
    long long tok0 = (long long)b * SS + (long long)kt * KT;
    #pragma unroll
    for (int it = 0; it < 8; it++) {
        int ci = tid + it * 256;
        int c = ci & 15;
        int row = (ci >> 4) & 63;
        const __half* src = ((ci < 1024) ? g_kh : g_kl) + (tok0 + row) * DD + c * 8;
        uint32_t dst = smem + OFF_K + buf * KBUF + ((ci < 1024) ? 0 : KLOFF)
                       + row * (KSTR*2) + c * 16;
        cp16(dst, src);
    }
}
__device__ __forceinline__ void load_v(uint32_t smem, int b, int kt, int buf, int tid) {
    long long vbase = (long long)b * DD * SS + (long long)kt * KT;
    #pragma unroll
    for (int it = 0; it < 4; it++) {
        int ci = tid + it * 256;
        int c = ci & 7;
        int d = (ci >> 3) & 127;
        const __half* src = g_vth + vbase + (long long)d * SS + c * 8;
        uint32_t dst = smem + OFF_V + buf * VBUF + d * (VSTR*2) + c * 16;
        cp16(dst, src);
    }
}

// S from register-resident Q fragments; only K comes from smem.
__device__ __forceinline__ void compute_S(float sf[8][4],
                                          const uint32_t qfh[8][4],
                                          const uint32_t qfl[8][4],
                                          uint32_t kb,
                                          uint32_t brow, uint32_t bcsel) {
    #pragma unroll
    for (int j = 0; j < 8; j++)
        #pragma unroll
        for (int c = 0; c < 4; c++) sf[j][c] = 0.f;
    #pragma unroll
    for (int kc = 0; kc < 8; kc++) {
        #pragma unroll
        for (int jp = 0; jp < 4; jp++) {
            uint32_t baddr = kb + (jp*16 + brow) * (KSTR*2) + kc * 32 + bcsel;
            uint32_t bh[4], blr[4];
            ldsm4(bh, baddr);
            ldsm4(blr, baddr + KLOFF);
            mma16816(sf[2*jp],   qfh[kc], bh[0], bh[1]);
            mma16816(sf[2*jp+1], qfh[kc], bh[2], bh[3]);
            mma16816(sf[2*jp],   qfl[kc], bh[0], bh[1]);
            mma16816(sf[2*jp+1], qfl[kc], bh[2], bh[3]);
            mma16816(sf[2*jp],   qfh[kc], blr[0], blr[1]);
            mma16816(sf[2*jp+1], qfh[kc], blr[2], blr[3]);
        }
    }
}

__device__ __forceinline__ void flash_iter(
    int t, float sfA[8][4], float sfB[8][4], float of[16][4],
    const uint32_t qfh[8][4], const uint32_t qfl[8][4],
    float& m0, float& m1, float& l0, float& l1,
    uint32_t smem, int b, int tid, uint32_t brow, uint32_t bcsel)
{
    if (t + 2 < NTILE) load_k(smem, b, t + 2, t & 1, tid);
    if (t + 1 < NTILE) load_v(smem, b, t + 1, (t + 1) & 1, tid);
    CP_COMMIT();

    if (t + 1 < NTILE)
        compute_S(sfB, qfh, qfl, smem + OFF_K + ((t + 1) & 1) * KBUF, brow, bcsel);

    float mx0 = sfA[0][0], mx1 = sfA[0][2];
    #pragma unroll
    for (int j = 0; j < 8; j++) {
        mx0 = fmaxf(mx0, fmaxf(sfA[j][0], sfA[j][1]));
        mx1 = fmaxf(mx1, fmaxf(sfA[j][2], sfA[j][3]));
    }
    mx0 = fmaxf(mx0, __shfl_xor_sync(0xffffffffu, mx0, 1));
    mx0 = fmaxf(mx0, __shfl_xor_sync(0xffffffffu, mx0, 2));
    mx1 = fmaxf(mx1, __shfl_xor_sync(0xffffffffu, mx1, 1));
    mx1 = fmaxf(mx1, __shfl_xor_sync(0xffffffffu, mx1, 2));

    if (mx0 > m0) {
        float a = ex2(m0 - mx0);
        m0 = mx0; l0 *= a;
        #pragma unroll
        for (int n = 0; n < 16; n++) { of[n][0] *= a; of[n][1] *= a; }
    }
    if (mx1 > m1) {
        float a = ex2(m1 - mx1);
        m1 = mx1; l1 *= a;
        #pragma unroll
        for (int n = 0; n < 16; n++) { of[n][2] *= a; of[n][3] *= a; }
    }

    #pragma unroll
    for (int j = 0; j < 8; j++) {
        sfA[j][0] = ex2(sfA[j][0] - m0); l0 += sfA[j][0];
        sfA[j][1] = ex2(sfA[j][1] - m0); l0 += sfA[j][1];
        sfA[j][2] = ex2(sfA[j][2] - m1); l1 += sfA[j][2];
        sfA[j][3] = ex2(sfA[j][3] - m1); l1 += sfA[j][3];
    }

    const uint32_t vb = smem + OFF_V + (t & 1) * VBUF;
    #pragma unroll
    for (int jk = 0; jk < 4; jk++) {
        uint32_t ph[4];
        ph[0] = cvt_h2(sfA[2*jk][0],   sfA[2*jk][1]);
        ph[1] = cvt_h2(sfA[2*jk][2],   sfA[2*jk][3]);
        ph[2] = cvt_h2(sfA[2*jk+1][0], sfA[2*jk+1][1]);
        ph[3] = cvt_h2(sfA[2*jk+1][2], sfA[2*jk+1][3]);
        #pragma unroll
        for (int np = 0; np < 8; np++) {
            uint32_t vaddr = vb + (np*16 + brow) * (VSTR*2) + jk * 32 + bcsel;
            uint32_t vh[4];
            ldsm4(vh, vaddr);
            mma16816(of[2*np],   ph, vh[0], vh[1]);
            mma16816(of[2*np+1], ph, vh[2], vh[3]);
        }
    }

    CP_WAIT0();
    __syncthreads();
}

__global__ __launch_bounds__(256, 1) void flash_attn(float* __restrict__ out)
{
    extern __shared__ char sm[];
    const uint32_t smem = smem_u32(sm);
    const int tid = threadIdx.x;
    const int w = tid >> 5;
    const int l = tid & 31;
    const int b = blockIdx.y;
    const int qi0 = blockIdx.x * QT;

    {
        long long tok0 = (long long)b * SS + qi0;
        #pragma unroll
        for (int it = 0; it < 16; it++) {
            int ci = tid + it * 256;
            int c = ci & 15;
            int row = (ci >> 4) & 127;
            const __half* src = ((ci < 2048) ? g_qh : g_ql) + (tok0 + row) * DD + c * 8;
            uint32_t dst = smem + ((ci < 2048) ? OFF_QH : OFF_QL) + row * (QSTR*2) + c * 16;
            cp16(dst, src);
        }
    }
    load_k(smem, b, 0, 0, tid);
    load_v(smem, b, 0, 0, tid);
    load_k(smem, b, 1, 1, tid);
    CP_COMMIT();
    CP_WAIT0();
    __syncthreads();

    float of[16][4];
    #pragma unroll
    for (int n = 0; n < 16; n++)
        #pragma unroll
        for (int c = 0; c < 4; c++) of[n][c] = 0.f;
    float m0 = -INFINITY, m1 = -INFINITY, l0 = 0.f, l1 = 0.f;

    const uint32_t qoff  = smem + (w*16 + (l & 15)) * (QSTR*2) + ((l >> 4) * 16);
    const uint32_t brow  = (l & 7) + ((l >> 4) & 1) * 8;
    const uint32_t bcsel = ((l >> 3) & 1) * 16;

    // ---- hoist Q fragments to registers (once) ----
    uint32_t qfh[8][4], qfl[8][4];
    #pragma unroll
    for (int kc = 0; kc < 8; kc++) {
        ldsm4(qfh[kc], qoff + OFF_QH + kc * 32);
        ldsm4(qfl[kc], qoff + OFF_QL + kc * 32);
    }

    float sfA[8][4], sfB[8][4];
    compute_S(sfA, qfh, qfl, smem + OFF_K, brow, bcsel);
    __syncthreads();

    #pragma unroll 1
    for (int t = 0; t < NTILE; t += 2) {
        flash_iter(t,     sfA, sfB, of, qfh, qfl, m0, m1, l0, l1, smem, b, tid, brow, bcsel);
        flash_iter(t + 1, sfB, sfA, of, qfh, qfl, m0, m1, l0, l1, smem, b, tid, brow, bcsel);
    }

    l0 += __shfl_xor_sync(0xffffffffu, l0, 1);
    l0 += __shfl_xor_sync(0xffffffffu, l0, 2);
    l1 += __shfl_xor_sync(0xffffffffu, l1, 1);
    l1 += __shfl_xor_sync(0xffffffffu, l1, 2);

    const int row0 = w*16 + (l >> 2);
    const float inv0 = 1.0f / l0, inv1 = 1.0f / l1;
    long long base0 = ((long long)b * SS + qi0 + row0) * DD;
    long long base1 = base0 + 8LL * DD;
    #pragma unroll
    for (int n = 0; n < 16; n++) {
        int cc = n*8 + (l & 3)*2;
        *(float2*)(out + base0 + cc) = make_float2(of[n][0]*inv0, of[n][1]*inv0);
        *(float2*)(out + base1 + cc) = make_float2(of[n][2]*inv1, of[n][3]*inv1);
    }
}

// ============================================================================
// launch
// ============================================================================
extern "C" void kernel_launch(void* const* d_in, const int* in_sizes, int n_in,
                              void* d_out, int out_size)
{
    const float* x  = (const float*)d_in[0];
    const float* Wq = (const float*)d_in[1];
    const float* bq = (const float*)d_in[2];
    const float* Wk = (const float*)d_in[3];
    const float* bk = (const float*)d_in[4];
    const float* Wv = (const float*)d_in[5];
    const float* bv = (const float*)d_in[6];
    float* out = (float*)d_out;

    split_w<<<(3*DD*EE)/256, 256>>>(Wq, Wk, Wv);

    cudaFuncSetAttribute(qkv_mma, cudaFuncAttributeMaxDynamicSharedMemorySize,
                         QKV_SMEM);
    qkv_mma<<<MM/64, QKV_THR, QKV_SMEM>>>(x, bq, bk, bv);

    cudaFuncSetAttribute(flash_attn, cudaFuncAttributeMaxDynamicSharedMemorySize,
                         FLASH_SMEM);
    flash_attn<<<dim3(SS / QT, BB), 256, FLASH_SMEM>>>(out);
}

// round 15
// speedup vs baseline: 1.1914x; 1.0033x over previous
#include <cuda_runtime.h>
#include <cuda_fp16.h>
#include <math.h>
#include <stdint.h>

#define BB 8
#define SS 4096
#define EE 2048
#define DD 128
#define MM (BB*SS)   // 32768

#define LOG2E 1.44269504088896340736f

// fp16 scratch (allocation-free __device__ globals)
__device__ __half g_qh[MM*DD];    // q scaled by log2e
__device__ __half g_ql[MM*DD];
__device__ __half g_kh[MM*DD];
__device__ __half g_kl[MM*DD];
__device__ __half g_vth[MM*DD];   // v transposed [b][d][s]
__device__ __half g_wth[3*DD*EE]; // W transposed hi (Wq pre-scaled by log2e)
__device__ __half g_wtl[3*DD*EE];

typedef unsigned long long u64;

__device__ __forceinline__ uint32_t pack_h2(float a, float b) {
    __half ha = __float2half_rn(a), hb = __float2half_rn(b);
    return ((uint32_t)__half_as_ushort(hb) << 16) | (uint32_t)__half_as_ushort(ha);
}
__device__ __forceinline__ uint32_t cvt_h2(float a, float b) {
    uint32_t r;
    asm("cvt.rn.f16x2.f32 %0, %1, %2;" : "=r"(r) : "f"(b), "f"(a));
    return r;
}
__device__ __forceinline__ uint32_t ex2h2(uint32_t a) {
    uint32_t d;
    asm("ex2.approx.f16x2 %0, %1;" : "=r"(d) : "r"(a));
    return d;
}
__device__ __forceinline__ uint32_t smem_u32(const void* p) {
    uint32_t a;
    asm("{ .reg .u64 t; cvta.to.shared.u64 t, %1; cvt.u32.u64 %0, t; }" : "=r"(a) : "l"(p));
    return a;
}
__device__ __forceinline__ float ex2(float x) {
    float r; asm("ex2.approx.f32 %0, %1;" : "=f"(r) : "f"(x)); return r;
}

__device__ __forceinline__ void cp16(uint32_t dst, const void* src) {
    asm volatile("cp.async.cg.shared.global [%0], [%1], 16;" :: "r"(dst), "l"(src));
}
#define CP_COMMIT() asm volatile("cp.async.commit_group;" ::: "memory")
#define CP_WAIT0()  asm volatile("cp.async.wait_group 0;" ::: "memory")

__device__ __forceinline__ void ldsm4(uint32_t r[4], uint32_t addr) {
    asm volatile("ldmatrix.sync.aligned.m8n8.x4.shared.b16 {%0,%1,%2,%3}, [%4];"
        : "=r"(r[0]), "=r"(r[1]), "=r"(r[2]), "=r"(r[3]) : "r"(addr));
}
__device__ __forceinline__ void mma16816(float c[4], const uint32_t a[4],
                                          uint32_t b0, uint32_t b1) {
    asm volatile("mma.sync.aligned.m16n8k16.row.col.f32.f16.f16.f32 "
        "{%0,%1,%2,%3}, {%4,%5,%6,%7}, {%8,%9}, {%0,%1,%2,%3};"
        : "+f"(c[0]), "+f"(c[1]), "+f"(c[2]), "+f"(c[3])
        : "r"(a[0]), "r"(a[1]), "r"(a[2]), "r"(a[3]), "r"(b0), "r"(b1));
}

// ============================================================================
// Kernel 0: split W (transposed fp16 hi/lo). Wq pre-scaled by log2e.
// ============================================================================
__global__ __launch_bounds__(256) void split_w(
    const float* __restrict__ Wq, const float* __restrict__ Wk,
    const float* __restrict__ Wv)
{
    int idx = blockIdx.x * 256 + threadIdx.x;
    int y = idx >> 18;
    int rem = idx & ((DD*EE) - 1);
    int d = rem >> 11;
    int e = rem & (EE - 1);
    const float* W = (y == 0) ? Wq : (y == 1) ? Wk : Wv;
    float v = W[(long long)e * DD + d];
    if (y == 0) v *= LOG2E;
    __half h = __float2half_rn(v);
    g_wth[idx] = h;
    g_wtl[idx] = __float2half_rn(v - __half2float(h));
}

// ============================================================================
// Kernel 1: fused QKV projection (round-13/14 version, best measured).
// ============================================================================
#define BK 64
#define PLN 18432
#define SXH 0
#define SXL 9216
#define SW  18432
#define QBUF (SW + 5*PLN)           // 110592
#define QKV_SMEM (2*QBUF)           // 221184
#define NCHUNK (EE/BK)              // 32
#define QKV_THR 512

__device__ __forceinline__ void qkv_w_ld(uint32_t smem, int bufoff, int kt, int tid) {
    #pragma unroll
    for (int j = 0; j < 10; j++) {
        int idx = tid + j * QKV_THR;
        int p = idx >> 10;
        int rem = idx & 1023;
        int n = rem >> 3, ch = rem & 7;
        int y = (p < 4) ? (p >> 1) : 2;
        const __half* base = ((p < 4) && (p & 1)) ? g_wtl : g_wth;
        const __half* src = base + (long long)y * DD * EE + (long long)n * EE
                            + kt * BK + ch * 8;
        cp16(smem + bufoff + SW + p * PLN + n * 144 + ch * 16, src);
    }
}

__device__ __forceinline__ void qkv_stx(char* sm, int bufoff, const float4* xr, int tid) {
    int boff = (tid >> 3) * 144 + (tid & 7) * 16;
    #pragma unroll
    for (int i = 0; i < 2; i++) {
        float4 v = xr[i];
        float h0 = __half2float(__float2half_rn(v.x));
        float h1 = __half2float(__float2half_rn(v.y));
        float h2 = __half2float(__float2half_rn(v.z));
        float h3 = __half2float(__float2half_rn(v.w));
        uint2 uh = make_uint2(pack_h2(h0, h1), pack_h2(h2, h3));
        uint2 ul = make_uint2(pack_h2(v.x - h0, v.y - h1), pack_h2(v.z - h2, v.w - h3));
        *(uint2*)(sm + bufoff + SXH + boff + 8 * i) = uh;
        *(uint2*)(sm + bufoff + SXL + boff + 8 * i) = ul;
    }
}

__global__ void __launch_bounds__(QKV_THR, 1) qkv_mma(
    const float* __restrict__ x,
    const float* __restrict__ bq, const float* __restrict__ bk,
    const float* __restrict__ bv)
{
    extern __shared__ char sm[];
    const uint32_t smem = smem_u32(sm);
    const int tid = threadIdx.x;
    const int w = tid >> 5;
    const int l = tid & 31;
    const int m0 = blockIdx.x * 64;

    const int wm = (w >> 2) * 16;
    const int wn = (w & 3) * 32;
    const uint32_t brow  = (l & 7) + ((l >> 4) & 1) * 8;
    const uint32_t bcsel = ((l >> 3) & 1) * 16;

    const float* xg = x + (long long)(m0 + (tid >> 3)) * EE + (tid & 7) * 8;

    float of[3][4][4];
    #pragma unroll
    for (int y = 0; y < 3; y++)
        #pragma unroll
        for (int n = 0; n < 4; n++)
            #pragma unroll
            for (int c = 0; c < 4; c++) of[y][n][c] = 0.f;

    float4 xr[2];
    xr[0] = *(const float4*)xg;
    xr[1] = *(const float4*)(xg + 4);
    qkv_w_ld(smem, 0, 0, tid);
    CP_COMMIT();
    qkv_stx(sm, 0, xr, tid);
    CP_WAIT0();
    __syncthreads();

    int buf = 0;
    for (int kt = 0; kt < NCHUNK; kt++) {
        const int nb = buf ^ 1;
        if (kt + 1 < NCHUNK) {
            xr[0] = *(const float4*)(xg + (kt + 1) * BK);
            xr[1] = *(const float4*)(xg + (kt + 1) * BK + 4);
            qkv_w_ld(smem, nb * QBUF, kt + 1, tid);
            CP_COMMIT();
        }

        const uint32_t aoff = smem + buf * QBUF + SXH
                            + (wm + (l & 15)) * 144 + (l >> 4) * 16;
        const uint32_t wb = smem + buf * QBUF + SW;
        #pragma unroll
        for (int kc = 0; kc < 4; kc++) {
            uint32_t ah[4], al[4];
            ldsm4(ah, aoff + kc * 32);
            ldsm4(al, aoff + (SXL - SXH) + kc * 32);
            #pragma unroll
            for (int y = 0; y < 3; y++) {
                const uint32_t wby = wb + ((y < 2) ? (y * 2) * PLN : 4 * PLN);
                #pragma unroll
                for (int nf = 0; nf < 2; nf++) {
                    uint32_t baddr = wby + (wn + nf*16 + brow) * 144 + kc * 32 + bcsel;
                    uint32_t bh[4];
                    ldsm4(bh, baddr);
                    mma16816(of[y][2*nf],   ah, bh[0], bh[1]);
                    mma16816(of[y][2*nf+1], ah, bh[2], bh[3]);
                    if (y < 2) {
                        mma16816(of[y][2*nf],   al, bh[0], bh[1]);
                        mma16816(of[y][2*nf+1], al, bh[2], bh[3]);
                        uint32_t bl2[4];
                        ldsm4(bl2, baddr + PLN);
                        mma16816(of[y][2*nf],   ah, bl2[0], bl2[1]);
                        mma16816(of[y][2*nf+1], ah, bl2[2], bl2[3]);
                    }
                }
            }
        }

        if (kt + 1 < NCHUNK) {
            qkv_stx(sm, nb * QBUF, xr, tid);
            CP_WAIT0();
        }
        __syncthreads();
        buf = nb;
    }

    const int row0 = m0 + wm + (l >> 2);
    const int row1 = row0 + 8;
    #pragma unroll
    for (int y = 0; y < 3; y++) {
        const float* bias = (y == 0) ? bq : (y == 1) ? bk : bv;
        const float bscale = (y == 0) ? LOG2E : 1.0f;
        #pragma unroll
        for (int nn = 0; nn < 4; nn++) {
            int col = wn + nn * 8 + (l & 3) * 2;
            float b0 = bias[col] * bscale, b1 = bias[col + 1] * bscale;
            float v00 = of[y][nn][0] + b0, v01 = of[y][nn][1] + b1;
            float v10 = of[y][nn][2] + b0, v11 = of[y][nn][3] + b1;
            float h00 = __half2float(__float2half_rn(v00));
            float h01 = __half2float(__float2half_rn(v01));
            float h10 = __half2float(__float2half_rn(v10));
            float h11 = __half2float(__float2half_rn(v11));

            if (y < 2) {
                __half* ph = (y == 0) ? g_qh : g_kh;
                __half* pl = (y == 0) ? g_ql : g_kl;
                *(uint32_t*)&ph[(long long)row0 * DD + col] = pack_h2(h00, h01);
                *(uint32_t*)&ph[(long long)row1 * DD + col] = pack_h2(h10, h11);
                *(uint32_t*)&pl[(long long)row0 * DD + col] = pack_h2(v00 - h00, v01 - h01);
                *(uint32_t*)&pl[(long long)row1 * DD + col] = pack_h2(v10 - h10, v11 - h11);
            } else {
                int bbx0 = row0 >> 12, s0 = row0 & 4095;
                int bbx1 = row1 >> 12, s1 = row1 & 4095;
                g_vth[((long long)bbx0 * DD + col) * SS + s0]     = __float2half_rn(h00);
                g_vth[((long long)bbx0 * DD + col + 1) * SS + s0] = __float2half_rn(h01);
                g_vth[((long long)bbx1 * DD + col) * SS + s1]     = __float2half_rn(h10);
                g_vth[((long long)bbx1 * DD + col + 1) * SS + s1] = __float2half_rn(h11);
            }
        }
    }
}

// ============================================================================
// Kernel 2: flash attention.
//   - Q fragments register-resident.
//   - P = ex2.approx.f16x2 of packed (s - m): MUFU ops halved.
//   - l computed by the TENSOR CORE: V tile extended with a ones-row at
//     d=128 (rows 129..143 zero); accumulator col 128 = row-sum of fp16 P,
//     rescaled for free by the lazy-alpha multiplies.
// ============================================================================
#define QT 128
#define KT 64
#define NTILE (SS/KT)   // 64
#define QSTR 136
#define KSTR 136
#define VROWS 144       // 128 data + ones row (128) + zeros (129..143)

#define OFF_QH 0
#define OFF_QL (128*QSTR*2)
#define OFF_K  (OFF_QL + 128*QSTR*2)
#define KBUF   (64*KSTR*2*2)
#define KLOFF  (64*KSTR*2)
#define OFF_V  (OFF_K + 2*KBUF)
#define VBUF   (VROWS*144)               // 20736
#define FLASH_SMEM (OFF_V + 2*VBUF)      // 180736

__device__ __forceinline__ void load_k(uint32_t smem, int b, int kt, int buf, int tid) {
    long long tok0 = (long long)b * SS + (long long)kt * KT;
    #pragma unroll
    for (int it = 0; it < 8; it++) {
        int ci = tid + it * 256;
        int c = ci & 15;
        int row = (ci >> 4) & 63;
        const __half* src = ((ci < 1024) ? g_kh : g_kl) + (tok0 + row) * DD + c * 8;
        uint32_t dst = smem + OFF_K + buf * KBUF + ((ci < 1024) ? 0 : KLOFF)
                       + row * (KSTR*2) + c * 16;
        cp16(dst, src);
    }
}
__device__ __forceinline__ void load_v(uint32_t smem, int b, int kt, int buf, int tid) {
    long long vbase = (long long)b * DD * SS + (long long)kt * KT;
    #pragma unroll
    for (int it = 0; it < 4; it++) {
        int ci = tid + it * 256;
        int c = ci & 7;
        int d = (ci >> 3) & 127;
        const __half* src = g_vth + vbase + (long long)d * SS + c * 8;
        uint32_t dst = smem + OFF_V + buf * VBUF + d * 144 + c * 16;
        cp16(dst, src);
    }
}

__device__ __forceinline__ void compute_S(float sf[8][4],
                                          const uint32_t qfh[8][4],
                                          const uint32_t qfl[8][4],
                                          uint32_t kb,
                                          uint32_t brow, uint32_t bcsel) {
    #pragma unroll
    for (int j = 0; j < 8; j++)
        #pragma unroll
        for (int c = 0; c < 4; c++) sf[j][c] = 0.f;
    #pragma unroll
    for (int kc = 0; kc < 8; kc++) {
        #pragma unroll
        for (int jp = 0; jp < 4; jp++) {
            uint32_t baddr = kb + (jp*16 + brow) * (KSTR*2) + kc * 32 + bcsel;
            uint32_t bh[4], blr[4];
            ldsm4(bh, baddr);
            ldsm4(blr, baddr + KLOFF);
            mma16816(sf[2*jp],   qfh[kc], bh[0], bh[1]);
            mma16816(sf[2*jp+1], qfh[kc], bh[2], bh[3]);
            mma16816(sf[2*jp],   qfl[kc], bh[0], bh[1]);
            mma16816(sf[2*jp+1], qfl[kc], bh[2], bh[3]);
            mma16816(sf[2*jp],   qfh[kc], blr[0], blr[1]);
            mma16816(sf[2*jp+1], qfh[kc], blr[2], blr[3]);
        }
    }
}

__device__ __forceinline__ void flash_iter(
    int t, float sfA[8][4], float sfB[8][4], float of[16][4], float ofl[4],
    const uint32_t qfh[8][4], const uint32_t qfl[8][4],
    float& m0, float& m1,
    uint32_t smem, int b, int tid, uint32_t brow, uint32_t bcsel)
{
    if (t + 2 < NTILE) load_k(smem, b, t + 2, t & 1, tid);
    if (t + 1 < NTILE) load_v(smem, b, t + 1, (t + 1) & 1, tid);
    CP_COMMIT();

    if (t + 1 < NTILE)
        compute_S(sfB, qfh, qfl, smem + OFF_K + ((t + 1) & 1) * KBUF, brow, bcsel);

    // ---- lazy max ----
    float mx0 = sfA[0][0], mx1 = sfA[0][2];
    #pragma unroll
    for (int j = 0; j < 8; j++) {
        mx0 = fmaxf(mx0, fmaxf(sfA[j][0], sfA[j][1]));
        mx1 = fmaxf(mx1, fmaxf(sfA[j][2], sfA[j][3]));
    }
    mx0 = fmaxf(mx0, __shfl_xor_sync(0xffffffffu, mx0, 1));
    mx0 = fmaxf(mx0, __shfl_xor_sync(0xffffffffu, mx0, 2));
    mx1 = fmaxf(mx1, __shfl_xor_sync(0xffffffffu, mx1, 1));
    mx1 = fmaxf(mx1, __shfl_xor_sync(0xffffffffu, mx1, 2));

    if (mx0 > m0) {
        float a = ex2(m0 - mx0);
        m0 = mx0;
        #pragma unroll
        for (int n = 0; n < 16; n++) { of[n][0] *= a; of[n][1] *= a; }
        ofl[0] *= a; ofl[1] *= a;
    }
    if (mx1 > m1) {
        float a = ex2(m1 - mx1);
        m1 = mx1;
        #pragma unroll
        for (int n = 0; n < 16; n++) { of[n][2] *= a; of[n][3] *= a; }
        ofl[2] *= a; ofl[3] *= a;
    }

    // ---- PV(t): P built inline via packed fp16 ex2; l via ones-column ----
    const uint32_t vb = smem + OFF_V + (t & 1) * VBUF;
    #pragma unroll
    for (int jk = 0; jk < 4; jk++) {
        uint32_t ph[4];
        ph[0] = ex2h2(cvt_h2(sfA[2*jk][0]   - m0, sfA[2*jk][1]   - m0));
        ph[1] = ex2h2(cvt_h2(sfA[2*jk][2]   - m1, sfA[2*jk][3]   - m1));
        ph[2] = ex2h2(cvt_h2(sfA[2*jk+1][0] - m0, sfA[2*jk+1][1] - m0));
        ph[3] = ex2h2(cvt_h2(sfA[2*jk+1][2] - m1, sfA[2*jk+1][3] - m1));
        // l column (V rows 128..143: ones at 128, zeros above)
        {
            uint32_t vl[4];
            ldsm4(vl, vb + (128 + brow) * 144 + jk * 32 + bcsel);
            mma16816(ofl, ph, vl[0], vl[1]);
        }
        #pragma unroll
        for (int np = 0; np < 8; np++) {
            uint32_t vaddr = vb + (np*16 + brow) * 144 + jk * 32 + bcsel;
            uint32_t vh[4];
            ldsm4(vh, vaddr);
            mma16816(of[2*np],   ph, vh[0], vh[1]);
            mma16816(of[2*np+1], ph, vh[2], vh[3]);
        }
    }

    CP_WAIT0();
    __syncthreads();
}

__global__ __launch_bounds__(256, 1) void flash_attn(float* __restrict__ out)
{
    extern __shared__ char sm[];
    const uint32_t smem = smem_u32(sm);
    const int tid = threadIdx.x;
    const int w = tid >> 5;
    const int l = tid & 31;
    const int b = blockIdx.y;
    const int qi0 = blockIdx.x * QT;

    // prologue: Q, K(0), V(0), K(1); init ones/zeros rows of both V buffers
    {
        long long tok0 = (long long)b * SS + qi0;
        #pragma unroll
        for (int it = 0; it < 16; it++) {
            int ci = tid + it * 256;
            int c = ci & 15;
            int row = (ci >> 4) & 127;
            const __half* src = ((ci < 2048) ? g_qh : g_ql) + (tok0 + row) * DD + c * 8;
            uint32_t dst = smem + ((ci < 2048) ? OFF_QH : OFF_QL) + row * (QSTR*2) + c * 16;
            cp16(dst, src);
        }
    }
    for (int i = tid; i < 16 * 72; i += 256) {
        int r = 128 + i / 72, c = i % 72;
        __half v = (r == 128) ? __float2half_rn(1.0f) : __ushort_as_half(0);
        *(__half*)(sm + OFF_V + r * 144 + c * 2) = v;
        *(__half*)(sm + OFF_V + VBUF + r * 144 + c * 2) = v;
    }
    load_k(smem, b, 0, 0, tid);
    load_v(smem, b, 0, 0, tid);
    load_k(smem, b, 1, 1, tid);
    CP_COMMIT();
    CP_WAIT0();
    __syncthreads();

    float of[16][4], ofl[4];
    #pragma unroll
    for (int n = 0; n < 16; n++)
        #pragma unroll
        for (int c = 0; c < 4; c++) of[n][c] = 0.f;
    #pragma unroll
    for (int c = 0; c < 4; c++) ofl[c] = 0.f;
    float m0 = -INFINITY, m1 = -INFINITY;

    const uint32_t qoff  = smem + (w*16 + (l & 15)) * (QSTR*2) + ((l >> 4) * 16);
    const uint32_t brow  = (l & 7) + ((l >> 4) & 1) * 8;
    const uint32_t bcsel = ((l >> 3) & 1) * 16;

    uint32_t qfh[8][4], qfl[8][4];
    #pragma unroll
    for (int kc = 0; kc < 8; kc++) {
        ldsm4(qfh[kc], qoff + OFF_QH + kc * 32);
        ldsm4(qfl[kc], qoff + OFF_QL + kc * 32);
    }

    float sfA[8][4], sfB[8][4];
    compute_S(sfA, qfh, qfl, smem + OFF_K, brow, bcsel);
    __syncthreads();

    #pragma unroll 1
    for (int t = 0; t < NTILE; t += 2) {
        flash_iter(t,     sfA, sfB, of, ofl, qfh, qfl, m0, m1, smem, b, tid, brow, bcsel);
        flash_iter(t + 1, sfB, sfA, of, ofl, qfh, qfl, m0, m1, smem, b, tid, brow, bcsel);
    }

    // ---- epilogue: l lives in accumulator col 128 (lane l&~3, c0/c2) ----
    float lt0 = __shfl_sync(0xffffffffu, ofl[0], l & 28);
    float lt1 = __shfl_sync(0xffffffffu, ofl[2], l & 28);

    const int row0 = w*16 + (l >> 2);
    const float inv0 = 1.0f / lt0, inv1 = 1.0f / lt1;
    long long base0 = ((long long)b * SS + qi0 + row0) * DD;
    long long base1 = base0 + 8LL * DD;
    #pragma unroll
    for (int n = 0; n < 16; n++) {
        int cc = n*8 + (l & 3)*2;
        *(float2*)(out + base0 + cc) = make_float2(of[n][0]*inv0, of[n][1]*inv0);
        *(float2*)(out + base1 + cc) = make_float2(of[n][2]*inv1, of[n][3]*inv1);
    }
}

// ============================================================================
// launch
// ============================================================================
extern "C" void kernel_launch(void* const* d_in, const int* in_sizes, int n_in,
                              void* d_out, int out_size)
{
    const float* x  = (const float*)d_in[0];
    const float* Wq = (const float*)d_in[1];
    const float* bq = (const float*)d_in[2];
    const float* Wk = (const float*)d_in[3];
    const float* bk = (const float*)d_in[4];
    const float* Wv = (const float*)d_in[5];
    const float* bv = (const float*)d_in[6];
    float* out = (float*)d_out;

    split_w<<<(3*DD*EE)/256, 256>>>(Wq, Wk, Wv);

    cudaFuncSetAttribute(qkv_mma, cudaFuncAttributeMaxDynamicSharedMemorySize,
                         QKV_SMEM);
    qkv_mma<<<MM/64, QKV_THR, QKV_SMEM>>>(x, bq, bk, bv);

    cudaFuncSetAttribute(flash_attn, cudaFuncAttributeMaxDynamicSharedMemorySize,
                         FLASH_SMEM);
    flash_attn<<<dim3(SS / QT, BB), 256, FLASH_SMEM>>>(out);
}

// round 16
// speedup vs baseline: 1.1937x; 1.0020x over previous
#include <cuda_runtime.h>
#include <cuda_fp16.h>
#include <math.h>
#include <stdint.h>

#define BB 8
#define SS 4096
#define EE 2048
#define DD 128
#define MM (BB*SS)   // 32768

#define LOG2E 1.44269504088896340736f

// fp16 scratch (allocation-free __device__ globals)
__device__ __half g_qh[MM*DD];    // q scaled by log2e
__device__ __half g_ql[MM*DD];
__device__ __half g_kh[MM*DD];
__device__ __half g_kl[MM*DD];
__device__ __half g_vth[MM*DD];   // v transposed [b][d][s]
__device__ __half g_wth[3*DD*EE]; // W transposed hi (Wq pre-scaled by log2e)
__device__ __half g_wtl[3*DD*EE];

typedef unsigned long long u64;

__device__ __forceinline__ uint32_t pack_h2(float a, float b) {
    __half ha = __float2half_rn(a), hb = __float2half_rn(b);
    return ((uint32_t)__half_as_ushort(hb) << 16) | (uint32_t)__half_as_ushort(ha);
}
__device__ __forceinline__ uint32_t cvt_h2(float a, float b) {
    uint32_t r;
    asm("cvt.rn.f16x2.f32 %0, %1, %2;" : "=r"(r) : "f"(b), "f"(a));
    return r;
}
__device__ __forceinline__ uint32_t ex2h2(uint32_t a) {
    uint32_t d;
    asm("ex2.approx.f16x2 %0, %1;" : "=r"(d) : "r"(a));
    return d;
}
__device__ __forceinline__ uint32_t smem_u32(const void* p) {
    uint32_t a;
    asm("{ .reg .u64 t; cvta.to.shared.u64 t, %1; cvt.u32.u64 %0, t; }" : "=r"(a) : "l"(p));
    return a;
}
__device__ __forceinline__ float ex2(float x) {
    float r; asm("ex2.approx.f32 %0, %1;" : "=f"(r) : "f"(x)); return r;
}

__device__ __forceinline__ void cp16(uint32_t dst, const void* src) {
    asm volatile("cp.async.cg.shared.global [%0], [%1], 16;" :: "r"(dst), "l"(src));
}
#define CP_COMMIT() asm volatile("cp.async.commit_group;" ::: "memory")
#define CP_WAIT0()  asm volatile("cp.async.wait_group 0;" ::: "memory")

__device__ __forceinline__ void ldsm4(uint32_t r[4], uint32_t addr) {
    asm volatile("ldmatrix.sync.aligned.m8n8.x4.shared.b16 {%0,%1,%2,%3}, [%4];"
        : "=r"(r[0]), "=r"(r[1]), "=r"(r[2]), "=r"(r[3]) : "r"(addr));
}
__device__ __forceinline__ void mma16816(float c[4], const uint32_t a[4],
                                          uint32_t b0, uint32_t b1) {
    asm volatile("mma.sync.aligned.m16n8k16.row.col.f32.f16.f16.f32 "
        "{%0,%1,%2,%3}, {%4,%5,%6,%7}, {%8,%9}, {%0,%1,%2,%3};"
        : "+f"(c[0]), "+f"(c[1]), "+f"(c[2]), "+f"(c[3])
        : "r"(a[0]), "r"(a[1]), "r"(a[2]), "r"(a[3]), "r"(b0), "r"(b1));
}

// ============================================================================
// Kernel 0: split W (transposed fp16 hi/lo). Wq pre-scaled by log2e.
// ============================================================================
__global__ __launch_bounds__(256) void split_w(
    const float* __restrict__ Wq, const float* __restrict__ Wk,
    const float* __restrict__ Wv)
{
    int idx = blockIdx.x * 256 + threadIdx.x;
    int y = idx >> 18;
    int rem = idx & ((DD*EE) - 1);
    int d = rem >> 11;
    int e = rem & (EE - 1);
    const float* W = (y == 0) ? Wq : (y == 1) ? Wk : Wv;
    float v = W[(long long)e * DD + d];
    if (y == 0) v *= LOG2E;
    __half h = __float2half_rn(v);
    g_wth[idx] = h;
    g_wtl[idx] = __float2half_rn(v - __half2float(h));
}

// ============================================================================
// Kernel 1: fused QKV projection (round-13 version, best measured).
// ============================================================================
#define BK 64
#define PLN 18432
#define SXH 0
#define SXL 9216
#define SW  18432
#define QBUF (SW + 5*PLN)           // 110592
#define QKV_SMEM (2*QBUF)           // 221184
#define NCHUNK (EE/BK)              // 32
#define QKV_THR 512

__device__ __forceinline__ void qkv_w_ld(uint32_t smem, int bufoff, int kt, int tid) {
    #pragma unroll
    for (int j = 0; j < 10; j++) {
        int idx = tid + j * QKV_THR;
        int p = idx >> 10;
        int rem = idx & 1023;
        int n = rem >> 3, ch = rem & 7;
        int y = (p < 4) ? (p >> 1) : 2;
        const __half* base = ((p < 4) && (p & 1)) ? g_wtl : g_wth;
        const __half* src = base + (long long)y * DD * EE + (long long)n * EE
                            + kt * BK + ch * 8;
        cp16(smem + bufoff + SW + p * PLN + n * 144 + ch * 16, src);
    }
}

__device__ __forceinline__ void qkv_stx(char* sm, int bufoff, const float4* xr, int tid) {
    int boff = (tid >> 3) * 144 + (tid & 7) * 16;
    #pragma unroll
    for (int i = 0; i < 2; i++) {
        float4 v = xr[i];
        float h0 = __half2float(__float2half_rn(v.x));
        float h1 = __half2float(__float2half_rn(v.y));
        float h2 = __half2float(__float2half_rn(v.z));
        float h3 = __half2float(__float2half_rn(v.w));
        uint2 uh = make_uint2(pack_h2(h0, h1), pack_h2(h2, h3));
        uint2 ul = make_uint2(pack_h2(v.x - h0, v.y - h1), pack_h2(v.z - h2, v.w - h3));
        *(uint2*)(sm + bufoff + SXH + boff + 8 * i) = uh;
        *(uint2*)(sm + bufoff + SXL + boff + 8 * i) = ul;
    }
}

__global__ void __launch_bounds__(QKV_THR, 1) qkv_mma(
    const float* __restrict__ x,
    const float* __restrict__ bq, const float* __restrict__ bk,
    const float* __restrict__ bv)
{
    extern __shared__ char sm[];
    const uint32_t smem = smem_u32(sm);
    const int tid = threadIdx.x;
    const int w = tid >> 5;
    const int l = tid & 31;
    const int m0 = blockIdx.x * 64;

    const int wm = (w >> 2) * 16;
    const int wn = (w & 3) * 32;
    const uint32_t brow  = (l & 7) + ((l >> 4) & 1) * 8;
    const uint32_t bcsel = ((l >> 3) & 1) * 16;

    const float* xg = x + (long long)(m0 + (tid >> 3)) * EE + (tid & 7) * 8;

    float of[3][4][4];
    #pragma unroll
    for (int y = 0; y < 3; y++)
        #pragma unroll
        for (int n = 0; n < 4; n++)
            #pragma unroll
            for (int c = 0; c < 4; c++) of[y][n][c] = 0.f;

    float4 xr[2];
    xr[0] = *(const float4*)xg;
    xr[1] = *(const float4*)(xg + 4);
    qkv_w_ld(smem, 0, 0, tid);
    CP_COMMIT();
    qkv_stx(sm, 0, xr, tid);
    CP_WAIT0();
    __syncthreads();

    int buf = 0;
    for (int kt = 0; kt < NCHUNK; kt++) {
        const int nb = buf ^ 1;
        if (kt + 1 < NCHUNK) {
            xr[0] = *(const float4*)(xg + (kt + 1) * BK);
            xr[1] = *(const float4*)(xg + (kt + 1) * BK + 4);
            qkv_w_ld(smem, nb * QBUF, kt + 1, tid);
            CP_COMMIT();
        }

        const uint32_t aoff = smem + buf * QBUF + SXH
                            + (wm + (l & 15)) * 144 + (l >> 4) * 16;
        const uint32_t wb = smem + buf * QBUF + SW;
        #pragma unroll
        for (int kc = 0; kc < 4; kc++) {
            uint32_t ah[4], al[4];
            ldsm4(ah, aoff + kc * 32);
            ldsm4(al, aoff + (SXL - SXH) + kc * 32);
            #pragma unroll
            for (int y = 0; y < 3; y++) {
                const uint32_t wby = wb + ((y < 2) ? (y * 2) * PLN : 4 * PLN);
                #pragma unroll
                for (int nf = 0; nf < 2; nf++) {
                    uint32_t baddr = wby + (wn + nf*16 + brow) * 144 + kc * 32 + bcsel;
                    uint32_t bh[4];
                    ldsm4(bh, baddr);
                    mma16816(of[y][2*nf],   ah, bh[0], bh[1]);
                    mma16816(of[y][2*nf+1], ah, bh[2], bh[3]);
                    if (y < 2) {
                        mma16816(of[y][2*nf],   al, bh[0], bh[1]);
                        mma16816(of[y][2*nf+1], al, bh[2], bh[3]);
                        uint32_t bl2[4];
                        ldsm4(bl2, baddr + PLN);
                        mma16816(of[y][2*nf],   ah, bl2[0], bl2[1]);
                        mma16816(of[y][2*nf+1], ah, bl2[2], bl2[3]);
                    }
                }
            }
        }

        if (kt + 1 < NCHUNK) {
            qkv_stx(sm, nb * QBUF, xr, tid);
            CP_WAIT0();
        }
        __syncthreads();
        buf = nb;
    }

    const int row0 = m0 + wm + (l >> 2);
    const int row1 = row0 + 8;
    #pragma unroll
    for (int y = 0; y < 3; y++) {
        const float* bias = (y == 0) ? bq : (y == 1) ? bk : bv;
        const float bscale = (y == 0) ? LOG2E : 1.0f;
        #pragma unroll
        for (int nn = 0; nn < 4; nn++) {
            int col = wn + nn * 8 + (l & 3) * 2;
            float b0 = bias[col] * bscale, b1 = bias[col + 1] * bscale;
            float v00 = of[y][nn][0] + b0, v01 = of[y][nn][1] + b1;
            float v10 = of[y][nn][2] + b0, v11 = of[y][nn][3] + b1;
            float h00 = __half2float(__float2half_rn(v00));
            float h01 = __half2float(__float2half_rn(v01));
            float h10 = __half2float(__float2half_rn(v10));
            float h11 = __half2float(__float2half_rn(v11));

            if (y < 2) {
                __half* ph = (y == 0) ? g_qh : g_kh;
                __half* pl = (y == 0) ? g_ql : g_kl;
                *(uint32_t*)&ph[(long long)row0 * DD + col] = pack_h2(h00, h01);
                *(uint32_t*)&ph[(long long)row1 * DD + col] = pack_h2(h10, h11);
                *(uint32_t*)&pl[(long long)row0 * DD + col] = pack_h2(v00 - h00, v01 - h01);
                *(uint32_t*)&pl[(long long)row1 * DD + col] = pack_h2(v10 - h10, v11 - h11);
            } else {
                int bbx0 = row0 >> 12, s0 = row0 & 4095;
                int bbx1 = row1 >> 12, s1 = row1 & 4095;
                g_vth[((long long)bbx0 * DD + col) * SS + s0]     = __float2half_rn(h00);
                g_vth[((long long)bbx0 * DD + col + 1) * SS + s0] = __float2half_rn(h01);
                g_vth[((long long)bbx1 * DD + col) * SS + s1]     = __float2half_rn(h10);
                g_vth[((long long)bbx1 * DD + col + 1) * SS + s1] = __float2half_rn(h11);
            }
        }
    }
}

// ============================================================================
// Kernel 2: flash attention.
//   - qfh register-resident; qfl reloaded once per kc (frees registers).
//   - B-fragments (K and V) REGISTER DOUBLE-BUFFERED: each mma's operands
//     were loaded one step earlier -> LDSM latency hidden inside mma burst.
//   - P via ex2.approx.f16x2; l via tensor-core ones-column.
// ============================================================================
#define QT 128
#define KT 64
#define NTILE (SS/KT)   // 64
#define QSTR 136
#define KSTR 136
#define VROWS 144

#define OFF_QH 0
#define OFF_QL (128*QSTR*2)
#define OFF_K  (OFF_QL + 128*QSTR*2)
#define KBUF   (64*KSTR*2*2)
#define KLOFF  (64*KSTR*2)
#define OFF_V  (OFF_K + 2*KBUF)
#define VBUF   (VROWS*144)               // 20736
#define FLASH_SMEM (OFF_V + 2*VBUF)      // 180736

__device__ __forceinline__ void load_k(uint32_t smem, int b, int kt, int buf, int tid) {
    long long tok0 = (long long)b * SS + (long long)kt * KT;
    #pragma unroll
    for (int it = 0; it < 8; it++) {
        int ci = tid + it * 256;
        int c = ci & 15;
        int row = (ci >> 4) & 63;
        const __half* src = ((ci < 1024) ? g_kh : g_kl) + (tok0 + row) * DD + c * 8;
        uint32_t dst = smem + OFF_K + buf * KBUF + ((ci < 1024) ? 0 : KLOFF)
                       + row * (KSTR*2) + c * 16;
        cp16(dst, src);
    }
}
__device__ __forceinline__ void load_v(uint32_t smem, int b, int kt, int buf, int tid) {
    long long vbase = (long long)b * DD * SS + (long long)kt * KT;
    #pragma unroll
    for (int it = 0; it < 4; it++) {
        int ci = tid + it * 256;
        int c = ci & 7;
        int d = (ci >> 3) & 127;
        const __half* src = g_vth + vbase + (long long)d * SS + c * 8;
        uint32_t dst = smem + OFF_V + buf * VBUF + d * 144 + c * 16;
        cp16(dst, src);
    }
}

__device__ __forceinline__ uint32_t kaddr(uint32_t kb, int kc, int jp,
                                          uint32_t brow, uint32_t bcsel) {
    return kb + (uint32_t)(jp*16 + brow) * (KSTR*2) + kc * 32 + bcsel;
}

// S = Qh*Kh + Ql*Kh + Qh*Kl. B fragments double-buffered in registers.
__device__ __forceinline__ void compute_S(float sf[8][4],
                                          const uint32_t qfh[8][4],
                                          uint32_t qoff, uint32_t kb,
                                          uint32_t brow, uint32_t bcsel) {
    #pragma unroll
    for (int j = 0; j < 8; j++)
        #pragma unroll
        for (int c = 0; c < 4; c++) sf[j][c] = 0.f;

    uint32_t bh[2][4], bl[2][4], qfl[4];
    ldsm4(bh[0], kaddr(kb, 0, 0, brow, bcsel));
    ldsm4(bl[0], kaddr(kb, 0, 0, brow, bcsel) + KLOFF);
    ldsm4(qfl, qoff + OFF_QL);

    #pragma unroll
    for (int i = 0; i < 32; i++) {           // i = kc*4 + jp
        const int kc = i >> 2, jp = i & 3;
        const int cur = i & 1, nxt = cur ^ 1;
        if (i + 1 < 32) {
            const int nk = (i + 1) >> 2, nj = (i + 1) & 3;
            ldsm4(bh[nxt], kaddr(kb, nk, nj, brow, bcsel));
            ldsm4(bl[nxt], kaddr(kb, nk, nj, brow, bcsel) + KLOFF);
        }
        mma16816(sf[2*jp],   qfh[kc], bh[cur][0], bh[cur][1]);
        mma16816(sf[2*jp+1], qfh[kc], bh[cur][2], bh[cur][3]);
        mma16816(sf[2*jp],   qfl,     bh[cur][0], bh[cur][1]);
        mma16816(sf[2*jp+1], qfl,     bh[cur][2], bh[cur][3]);
        mma16816(sf[2*jp],   qfh[kc], bl[cur][0], bl[cur][1]);
        mma16816(sf[2*jp+1], qfh[kc], bl[cur][2], bl[cur][3]);
        if (jp == 3 && kc < 7)               // qfl for the next kc group
            ldsm4(qfl, qoff + OFF_QL + (kc + 1) * 32);
    }
}

__device__ __forceinline__ void flash_iter(
    int t, float sfA[8][4], float sfB[8][4], float of[16][4], float ofl[4],
    const uint32_t qfh[8][4], uint32_t qoff,
    float& m0, float& m1,
    uint32_t smem, int b, int tid, uint32_t brow, uint32_t bcsel)
{
    if (t + 2 < NTILE) load_k(smem, b, t + 2, t & 1, tid);
    if (t + 1 < NTILE) load_v(smem, b, t + 1, (t + 1) & 1, tid);
    CP_COMMIT();

    if (t + 1 < NTILE)
        compute_S(sfB, qfh, qoff, smem + OFF_K + ((t + 1) & 1) * KBUF, brow, bcsel);

    // ---- lazy max ----
    float mx0 = sfA[0][0], mx1 = sfA[0][2];
    #pragma unroll
    for (int j = 0; j < 8; j++) {
        mx0 = fmaxf(mx0, fmaxf(sfA[j][0], sfA[j][1]));
        mx1 = fmaxf(mx1, fmaxf(sfA[j][2], sfA[j][3]));
    }
    mx0 = fmaxf(mx0, __shfl_xor_sync(0xffffffffu, mx0, 1));
    mx0 = fmaxf(mx0, __shfl_xor_sync(0xffffffffu, mx0, 2));
    mx1 = fmaxf(mx1, __shfl_xor_sync(0xffffffffu, mx1, 1));
    mx1 = fmaxf(mx1, __shfl_xor_sync(0xffffffffu, mx1, 2));

    if (mx0 > m0) {
        float a = ex2(m0 - mx0);
        m0 = mx0;
        #pragma unroll
        for (int n = 0; n < 16; n++) { of[n][0] *= a; of[n][1] *= a; }
        ofl[0] *= a; ofl[1] *= a;
    }
    if (mx1 > m1) {
        float a = ex2(m1 - mx1);
        m1 = mx1;
        #pragma unroll
        for (int n = 0; n < 16; n++) { of[n][2] *= a; of[n][3] *= a; }
        ofl[2] *= a; ofl[3] *= a;
    }

    // ---- PV(t): P inline via packed fp16 ex2; V frags double-buffered ----
    const uint32_t vb = smem + OFF_V + (t & 1) * VBUF;
    #pragma unroll
    for (int jk = 0; jk < 4; jk++) {
        uint32_t ph[4];
        ph[0] = ex2h2(cvt_h2(sfA[2*jk][0]   - m0, sfA[2*jk][1]   - m0));
        ph[1] = ex2h2(cvt_h2(sfA[2*jk][2]   - m1, sfA[2*jk][3]   - m1));
        ph[2] = ex2h2(cvt_h2(sfA[2*jk+1][0] - m0, sfA[2*jk+1][1] - m0));
        ph[3] = ex2h2(cvt_h2(sfA[2*jk+1][2] - m1, sfA[2*jk+1][3] - m1));

        uint32_t vl[4], vh[2][4];
        ldsm4(vl, vb + (128 + brow) * 144 + jk * 32 + bcsel);
        ldsm4(vh[0], vb + brow * 144 + jk * 32 + bcsel);
        mma16816(ofl, ph, vl[0], vl[1]);
        #pragma unroll
        for (int np = 0; np < 8; np++) {
            const int cur = np & 1, nxt = cur ^ 1;
            if (np + 1 < 8)
                ldsm4(vh[nxt], vb + ((np+1)*16 + brow) * 144 + jk * 32 + bcsel);
            mma16816(of[2*np],   ph, vh[cur][0], vh[cur][1]);
            mma16816(of[2*np+1], ph, vh[cur][2], vh[cur][3]);
        }
    }

    CP_WAIT0();
    __syncthreads();
}

__global__ __launch_bounds__(256, 1) void flash_attn(float* __restrict__ out)
{
    extern __shared__ char sm[];
    const uint32_t smem = smem_u32(sm);
    const int tid = threadIdx.x;
    const int w = tid >> 5;
    const int l = tid & 31;
    const int b = blockIdx.y;
    const int qi0 = blockIdx.x * QT;

    {
        long long tok0 = (long long)b * SS + qi0;
        #pragma unroll
        for (int it = 0; it < 16; it++) {
            int ci = tid + it * 256;
            int c = ci & 15;
            int row = (ci >> 4) & 127;
            const __half* src = ((ci < 2048) ? g_qh : g_ql) + (tok0 + row) * DD + c * 8;
            uint32_t dst = smem + ((ci < 2048) ? OFF_QH : OFF_QL) + row * (QSTR*2) + c * 16;
            cp16(dst, src);
        }
    }
    for (int i = tid; i < 16 * 72; i += 256) {
        int r = 128 + i / 72, c = i % 72;
        __half v = (r == 128) ? __float2half_rn(1.0f) : __ushort_as_half(0);
        *(__half*)(sm + OFF_V + r * 144 + c * 2) = v;
        *(__half*)(sm + OFF_V + VBUF + r * 144 + c * 2) = v;
    }
    load_k(smem, b, 0, 0, tid);
    load_v(smem, b, 0, 0, tid);
    load_k(smem, b, 1, 1, tid);
    CP_COMMIT();
    CP_WAIT0();
    __syncthreads();

    float of[16][4], ofl[4];
    #pragma unroll
    for (int n = 0; n < 16; n++)
        #pragma unroll
        for (int c = 0; c < 4; c++) of[n][c] = 0.f;
    #pragma unroll
    for (int c = 0; c < 4; c++) ofl[c] = 0.f;
    float m0 = -INFINITY, m1 = -INFINITY;

    const uint32_t qoff  = smem + (w*16 + (l & 15)) * (QSTR*2) + ((l >> 4) * 16);
    const uint32_t brow  = (l & 7) + ((l >> 4) & 1) * 8;
    const uint32_t bcsel = ((l >> 3) & 1) * 16;

    uint32_t qfh[8][4];
    #pragma unroll
    for (int kc = 0; kc < 8; kc++)
        ldsm4(qfh[kc], qoff + OFF_QH + kc * 32);

    float sfA[8][4], sfB[8][4];
    compute_S(sfA, qfh, qoff, smem + OFF_K, brow, bcsel);
    __syncthreads();

    #pragma unroll 1
    for (int t = 0; t < NTILE; t += 2) {
        flash_iter(t,     sfA, sfB, of, ofl, qfh, qoff, m0, m1, smem, b, tid, brow, bcsel);
        flash_iter(t + 1, sfB, sfA, of, ofl, qfh, qoff, m0, m1, smem, b, tid, brow, bcsel);
    }

    float lt0 = __shfl_sync(0xffffffffu, ofl[0], l & 28);
    float lt1 = __shfl_sync(0xffffffffu, ofl[2], l & 28);

    const int row0 = w*16 + (l >> 2);
    const float inv0 = 1.0f / lt0, inv1 = 1.0f / lt1;
    long long base0 = ((long long)b * SS + qi0 + row0) * DD;
    long long base1 = base0 + 8LL * DD;
    #pragma unroll
    for (int n = 0; n < 16; n++) {
        int cc = n*8 + (l & 3)*2;
        *(float2*)(out + base0 + cc) = make_float2(of[n][0]*inv0, of[n][1]*inv0);
        *(float2*)(out + base1 + cc) = make_float2(of[n][2]*inv1, of[n][3]*inv1);
    }
}

// ============================================================================
// launch
// ============================================================================
extern "C" void kernel_launch(void* const* d_in, const int* in_sizes, int n_in,
                              void* d_out, int out_size)
{
    const float* x  = (const float*)d_in[0];
    const float* Wq = (const float*)d_in[1];
    const float* bq = (const float*)d_in[2];
    const float* Wk = (const float*)d_in[3];
    const float* bk = (const float*)d_in[4];
    const float* Wv = (const float*)d_in[5];
    const float* bv = (const float*)d_in[6];
    float* out = (float*)d_out;

    split_w<<<(3*DD*EE)/256, 256>>>(Wq, Wk, Wv);

    cudaFuncSetAttribute(qkv_mma, cudaFuncAttributeMaxDynamicSharedMemorySize,
                         QKV_SMEM);
    qkv_mma<<<MM/64, QKV_THR, QKV_SMEM>>>(x, bq, bk, bv);

    cudaFuncSetAttribute(flash_attn, cudaFuncAttributeMaxDynamicSharedMemorySize,
                         FLASH_SMEM);
    flash_attn<<<dim3(SS / QT, BB), 256, FLASH_SMEM>>>(out);
}

// round 17
// speedup vs baseline: 1.2151x; 1.0179x over previous
#include <cuda_runtime.h>
#include <cuda_fp16.h>
#include <math.h>
#include <stdint.h>

#define BB 8
#define SS 4096
#define EE 2048
#define DD 128
#define MM (BB*SS)   // 32768

#define LOG2E 1.44269504088896340736f

// fp16 scratch (allocation-free __device__ globals)
__device__ __half g_qh[MM*DD];    // q scaled by log2e
__device__ __half g_ql[MM*DD];
__device__ __half g_kh[MM*DD];
__device__ __half g_kl[MM*DD];
__device__ __half g_vth[MM*DD];   // v transposed [b][d][s]
__device__ __half g_wth[3*DD*EE]; // W transposed hi (Wq pre-scaled by log2e)
__device__ __half g_wtl[3*DD*EE];

typedef unsigned long long u64;

__device__ __forceinline__ uint32_t pack_h2(float a, float b) {
    __half ha = __float2half_rn(a), hb = __float2half_rn(b);
    return ((uint32_t)__half_as_ushort(hb) << 16) | (uint32_t)__half_as_ushort(ha);
}
__device__ __forceinline__ uint32_t cvt_h2(float a, float b) {
    uint32_t r;
    asm("cvt.rn.f16x2.f32 %0, %1, %2;" : "=r"(r) : "f"(b), "f"(a));
    return r;
}
__device__ __forceinline__ uint32_t ex2h2(uint32_t a) {
    uint32_t d;
    asm("ex2.approx.f16x2 %0, %1;" : "=r"(d) : "r"(a));
    return d;
}
__device__ __forceinline__ uint32_t smem_u32(const void* p) {
    uint32_t a;
    asm("{ .reg .u64 t; cvta.to.shared.u64 t, %1; cvt.u32.u64 %0, t; }" : "=r"(a) : "l"(p));
    return a;
}
__device__ __forceinline__ float ex2(float x) {
    float r; asm("ex2.approx.f32 %0, %1;" : "=f"(r) : "f"(x)); return r;
}

__device__ __forceinline__ void cp16(uint32_t dst, const void* src) {
    asm volatile("cp.async.cg.shared.global [%0], [%1], 16;" :: "r"(dst), "l"(src));
}
#define CP_COMMIT() asm volatile("cp.async.commit_group;" ::: "memory")
#define CP_WAIT0()  asm volatile("cp.async.wait_group 0;" ::: "memory")

__device__ __forceinline__ void ldsm4(uint32_t r[4], uint32_t addr) {
    asm volatile("ldmatrix.sync.aligned.m8n8.x4.shared.b16 {%0,%1,%2,%3}, [%4];"
        : "=r"(r[0]), "=r"(r[1]), "=r"(r[2]), "=r"(r[3]) : "r"(addr));
}
__device__ __forceinline__ void mma16816(float c[4], const uint32_t a[4],
                                          uint32_t b0, uint32_t b1) {
    asm volatile("mma.sync.aligned.m16n8k16.row.col.f32.f16.f16.f32 "
        "{%0,%1,%2,%3}, {%4,%5,%6,%7}, {%8,%9}, {%0,%1,%2,%3};"
        : "+f"(c[0]), "+f"(c[1]), "+f"(c[2]), "+f"(c[3])
        : "r"(a[0]), "r"(a[1]), "r"(a[2]), "r"(a[3]), "r"(b0), "r"(b1));
}

// ============================================================================
// Kernel 0: split W (transposed fp16 hi/lo). Wq pre-scaled by log2e.
// ============================================================================
__global__ __launch_bounds__(256) void split_w(
    const float* __restrict__ Wq, const float* __restrict__ Wk,
    const float* __restrict__ Wv)
{
    int idx = blockIdx.x * 256 + threadIdx.x;
    int y = idx >> 18;
    int rem = idx & ((DD*EE) - 1);
    int d = rem >> 11;
    int e = rem & (EE - 1);
    const float* W = (y == 0) ? Wq : (y == 1) ? Wk : Wv;
    float v = W[(long long)e * DD + d];
    if (y == 0) v *= LOG2E;
    __half h = __float2half_rn(v);
    g_wth[idx] = h;
    g_wtl[idx] = __float2half_rn(v - __half2float(h));
}

// ============================================================================
// Kernel 1: fused QKV projection.
// SINGLE-buffered smem (108KB) -> 2 CTAs/SM; 2M x 4N warp layout keeps the
// crossbar demand (~2650 cyc/chunk) under the mma floor (3584), so the
// co-resident CTA covers the load-phase latency and the SM runs mma-bound.
//   q,k: 3 terms (xh*Wh + xl*Wh + xh*Wl);  v: 1 term (xh*Wvh).
// ============================================================================
#define BK 64
#define PLN 18432                   // one W plane: 128 rows x 144B
#define SXH 0                       // x hi: 64 x 144B = 9216
#define SXL 9216
#define SW  18432                   // planes: [qh,ql,kh,kl,vh]
#define QKV_SMEM (SW + 5*PLN)       // 110592
#define NCHUNK (EE/BK)              // 32

__device__ __forceinline__ void qkv_w_ld(uint32_t smem, int kt, int tid) {
    #pragma unroll
    for (int j = 0; j < 20; j++) {
        int idx = tid + j * 256;            // 0..5119
        int p = idx >> 10;                  // plane 0..4
        int rem = idx & 1023;
        int n = rem >> 3, ch = rem & 7;
        int y = (p < 4) ? (p >> 1) : 2;
        const __half* base = ((p < 4) && (p & 1)) ? g_wtl : g_wth;
        const __half* src = base + (long long)y * DD * EE + (long long)n * EE
                            + kt * BK + ch * 8;
        cp16(smem + SW + p * PLN + n * 144 + ch * 16, src);
    }
}

__global__ void __launch_bounds__(256, 2) qkv_mma(
    const float* __restrict__ x,
    const float* __restrict__ bq, const float* __restrict__ bk,
    const float* __restrict__ bv)
{
    extern __shared__ char sm[];
    const uint32_t smem = smem_u32(sm);
    const int tid = threadIdx.x;
    const int w = tid >> 5;
    const int l = tid & 31;
    const int m0 = blockIdx.x * 64;

    const int wm = (w >> 2) * 32;        // 2 M-groups of 32 rows
    const int wn = (w & 3) * 32;         // 4 N-groups of 32 cols
    const uint32_t brow  = (l & 7) + ((l >> 4) & 1) * 8;
    const uint32_t bcsel = ((l >> 3) & 1) * 16;

    const float* xrow = x + (long long)(m0 + (tid >> 2)) * EE + (tid & 3) * 4;
    const int xboff = (tid >> 2) * 144 + (tid & 3) * 8;

    // of[y][mfrag][n8][acc4] = 96 floats
    float of[3][2][4][4];
    #pragma unroll
    for (int y = 0; y < 3; y++)
        #pragma unroll
        for (int m = 0; m < 2; m++)
            #pragma unroll
            for (int n = 0; n < 4; n++)
                #pragma unroll
                for (int c = 0; c < 4; c++) of[y][m][n][c] = 0.f;

    for (int kt = 0; kt < NCHUNK; kt++) {
        __syncthreads();   // previous chunk's mma done reading smem

        // ---- load phase ----
        qkv_w_ld(smem, kt, tid);
        CP_COMMIT();
        #pragma unroll
        for (int i = 0; i < 4; i++) {
            float4 v = *(const float4*)(xrow + kt * BK + 16 * i);
            float h0 = __half2float(__float2half_rn(v.x));
            float h1 = __half2float(__float2half_rn(v.y));
            float h2 = __half2float(__float2half_rn(v.z));
            float h3 = __half2float(__float2half_rn(v.w));
            uint2 uh = make_uint2(pack_h2(h0, h1), pack_h2(h2, h3));
            uint2 ul = make_uint2(pack_h2(v.x - h0, v.y - h1),
                                  pack_h2(v.z - h2, v.w - h3));
            *(uint2*)(sm + SXH + xboff + 32 * i) = uh;
            *(uint2*)(sm + SXL + xboff + 32 * i) = ul;
        }
        CP_WAIT0();
        __syncthreads();   // tile complete

        // ---- mma phase (2M x 4N) ----
        const uint32_t aoff = smem + SXH + (wm + (l & 15)) * 144 + (l >> 4) * 16;
        const uint32_t wb = smem + SW;
        #pragma unroll
        for (int kc = 0; kc < 4; kc++) {
            uint32_t ah[2][4], al[2][4];
            ldsm4(ah[0], aoff + kc * 32);
            ldsm4(ah[1], aoff + 16 * 144 + kc * 32);
            ldsm4(al[0], aoff + (SXL - SXH) + kc * 32);
            ldsm4(al[1], aoff + (SXL - SXH) + 16 * 144 + kc * 32);
            #pragma unroll
            for (int y = 0; y < 3; y++) {
                const uint32_t wby = wb + ((y < 2) ? (y * 2) * PLN : 4 * PLN);
                #pragma unroll
                for (int nf = 0; nf < 2; nf++) {
                    uint32_t baddr = wby + (wn + nf*16 + brow) * 144 + kc * 32 + bcsel;
                    uint32_t bh[4];
                    ldsm4(bh, baddr);
                    #pragma unroll
                    for (int m = 0; m < 2; m++) {
                        mma16816(of[y][m][2*nf],   ah[m], bh[0], bh[1]);
                        mma16816(of[y][m][2*nf+1], ah[m], bh[2], bh[3]);
                        if (y < 2) {
                            mma16816(of[y][m][2*nf],   al[m], bh[0], bh[1]);
                            mma16816(of[y][m][2*nf+1], al[m], bh[2], bh[3]);
                        }
                    }
                    if (y < 2) {
                        uint32_t bl2[4];
                        ldsm4(bl2, baddr + PLN);
                        #pragma unroll
                        for (int m = 0; m < 2; m++) {
                            mma16816(of[y][m][2*nf],   ah[m], bl2[0], bl2[1]);
                            mma16816(of[y][m][2*nf+1], ah[m], bl2[2], bl2[3]);
                        }
                    }
                }
            }
        }
    }

    // ---- epilogue: all three outputs ----
    #pragma unroll
    for (int y = 0; y < 3; y++) {
        const float* bias = (y == 0) ? bq : (y == 1) ? bk : bv;
        const float bscale = (y == 0) ? LOG2E : 1.0f;
        #pragma unroll
        for (int m = 0; m < 2; m++) {
            const int row0 = m0 + wm + m * 16 + (l >> 2);
            const int row1 = row0 + 8;
            #pragma unroll
            for (int nn = 0; nn < 4; nn++) {
                int col = wn + nn * 8 + (l & 3) * 2;
                float b0 = bias[col] * bscale, b1 = bias[col + 1] * bscale;
                float v00 = of[y][m][nn][0] + b0, v01 = of[y][m][nn][1] + b1;
                float v10 = of[y][m][nn][2] + b0, v11 = of[y][m][nn][3] + b1;
                float h00 = __half2float(__float2half_rn(v00));
                float h01 = __half2float(__float2half_rn(v01));
                float h10 = __half2float(__float2half_rn(v10));
                float h11 = __half2float(__float2half_rn(v11));

                if (y < 2) {
                    __half* ph = (y == 0) ? g_qh : g_kh;
                    __half* pl = (y == 0) ? g_ql : g_kl;
                    *(uint32_t*)&ph[(long long)row0 * DD + col] = pack_h2(h00, h01);
                    *(uint32_t*)&ph[(long long)row1 * DD + col] = pack_h2(h10, h11);
                    *(uint32_t*)&pl[(long long)row0 * DD + col] = pack_h2(v00 - h00, v01 - h01);
                    *(uint32_t*)&pl[(long long)row1 * DD + col] = pack_h2(v10 - h10, v11 - h11);
                } else {
                    int bbx0 = row0 >> 12, s0 = row0 & 4095;
                    int bbx1 = row1 >> 12, s1 = row1 & 4095;
                    g_vth[((long long)bbx0 * DD + col) * SS + s0]     = __float2half_rn(h00);
                    g_vth[((long long)bbx0 * DD + col + 1) * SS + s0] = __float2half_rn(h01);
                    g_vth[((long long)bbx1 * DD + col) * SS + s1]     = __float2half_rn(h10);
                    g_vth[((long long)bbx1 * DD + col + 1) * SS + s1] = __float2half_rn(h11);
                }
            }
        }
    }
}

// ============================================================================
// Kernel 2: flash attention (round-16 version — best measured; unchanged).
// ============================================================================
#define QT 128
#define KT 64
#define NTILE (SS/KT)   // 64
#define QSTR 136
#define KSTR 136
#define VROWS 144

#define OFF_QH 0
#define OFF_QL (128*QSTR*2)
#define OFF_K  (OFF_QL + 128*QSTR*2)
#define KBUF   (64*KSTR*2*2)
#define KLOFF  (64*KSTR*2)
#define OFF_V  (OFF_K + 2*KBUF)
#define VBUF   (VROWS*144)               // 20736
#define FLASH_SMEM (OFF_V + 2*VBUF)      // 180736

__device__ __forceinline__ void load_k(uint32_t smem, int b, int kt, int buf, int tid) {
    long long tok0 = (long long)b * SS + (long long)kt * KT;
    #pragma unroll
    for (int it = 0; it < 8; it++) {
        int ci = tid + it * 256;
        int c = ci & 15;
        int row = (ci >> 4) & 63;
        const __half* src = ((ci < 1024) ? g_kh : g_kl) + (tok0 + row) * DD + c * 8;
        uint32_t dst = smem + OFF_K + buf * KBUF + ((ci < 1024) ? 0 : KLOFF)
                       + row * (KSTR*2) + c * 16;
        cp16(dst, src);
    }
}
__device__ __forceinline__ void load_v(uint32_t smem, int b, int kt, int buf, int tid) {
    long long vbase = (long long)b * DD * SS + (long long)kt * KT;
    #pragma unroll
    for (int it = 0; it < 4; it++) {
        int ci = tid + it * 256;
        int c = ci & 7;
        int d = (ci >> 3) & 127;
        const __half* src = g_vth + vbase + (long long)d * SS + c * 8;
        uint32_t dst = smem + OFF_V + buf * VBUF + d * 144 + c * 16;
        cp16(dst, src);
    }
}

__device__ __forceinline__ uint32_t kaddr(uint32_t kb, int kc, int jp,
                                          uint32_t brow, uint32_t bcsel) {
    return kb + (uint32_t)(jp*16 + brow) * (KSTR*2) + kc * 32 + bcsel;
}

__device__ __forceinline__ void compute_S(float sf[8][4],
                                          const uint32_t qfh[8][4],
                                          uint32_t qoff, uint32_t kb,
                                          uint32_t brow, uint32_t bcsel) {
    #pragma unroll
    for (int j = 0; j < 8; j++)
        #pragma unroll
        for (int c = 0; c < 4; c++) sf[j][c] = 0.f;

    uint32_t bh[2][4], bl[2][4], qfl[4];
    ldsm4(bh[0], kaddr(kb, 0, 0, brow, bcsel));
    ldsm4(bl[0], kaddr(kb, 0, 0, brow, bcsel) + KLOFF);
    ldsm4(qfl, qoff + OFF_QL);

    #pragma unroll
    for (int i = 0; i < 32; i++) {
        const int kc = i >> 2, jp = i & 3;
        const int cur = i & 1, nxt = cur ^ 1;
        if (i + 1 < 32) {
            const int nk = (i + 1) >> 2, nj = (i + 1) & 3;
            ldsm4(bh[nxt], kaddr(kb, nk, nj, brow, bcsel));
            ldsm4(bl[nxt], kaddr(kb, nk, nj, brow, bcsel) + KLOFF);
        }
        mma16816(sf[2*jp],   qfh[kc], bh[cur][0], bh[cur][1]);
        mma16816(sf[2*jp+1], qfh[kc], bh[cur][2], bh[cur][3]);
        mma16816(sf[2*jp],   qfl,     bh[cur][0], bh[cur][1]);
        mma16816(sf[2*jp+1], qfl,     bh[cur][2], bh[cur][3]);
        mma16816(sf[2*jp],   qfh[kc], bl[cur][0], bl[cur][1]);
        mma16816(sf[2*jp+1], qfh[kc], bl[cur][2], bl[cur][3]);
        if (jp == 3 && kc < 7)
            ldsm4(qfl, qoff + OFF_QL + (kc + 1) * 32);
    }
}

__device__ __forceinline__ void flash_iter(
    int t, float sfA[8][4], float sfB[8][4], float of[16][4], float ofl[4],
    const uint32_t qfh[8][4], uint32_t qoff,
    float& m0, float& m1,
    uint32_t smem, int b, int tid, uint32_t brow, uint32_t bcsel)
{
    if (t + 2 < NTILE) load_k(smem, b, t + 2, t & 1, tid);
    if (t + 1 < NTILE) load_v(smem, b, t + 1, (t + 1) & 1, tid);
    CP_COMMIT();

    if (t + 1 < NTILE)
        compute_S(sfB, qfh, qoff, smem + OFF_K + ((t + 1) & 1) * KBUF, brow, bcsel);

    float mx0 = sfA[0][0], mx1 = sfA[0][2];
    #pragma unroll
    for (int j = 0; j < 8; j++) {
        mx0 = fmaxf(mx0, fmaxf(sfA[j][0], sfA[j][1]));
        mx1 = fmaxf(mx1, fmaxf(sfA[j][2], sfA[j][3]));
    }
    mx0 = fmaxf(mx0, __shfl_xor_sync(0xffffffffu, mx0, 1));
    mx0 = fmaxf(mx0, __shfl_xor_sync(0xffffffffu, mx0, 2));
    mx1 = fmaxf(mx1, __shfl_xor_sync(0xffffffffu, mx1, 1));
    mx1 = fmaxf(mx1, __shfl_xor_sync(0xffffffffu, mx1, 2));

    if (mx0 > m0) {
        float a = ex2(m0 - mx0);
        m0 = mx0;
        #pragma unroll
        for (int n = 0; n < 16; n++) { of[n][0] *= a; of[n][1] *= a; }
        ofl[0] *= a; ofl[1] *= a;
    }
    if (mx1 > m1) {
        float a = ex2(m1 - mx1);
        m1 = mx1;
        #pragma unroll
        for (int n = 0; n < 16; n++) { of[n][2] *= a; of[n][3] *= a; }
        ofl[2] *= a; ofl[3] *= a;
    }

    const uint32_t vb = smem + OFF_V + (t & 1) * VBUF;
    #pragma unroll
    for (int jk = 0; jk < 4; jk++) {
        uint32_t ph[4];
        ph[0] = ex2h2(cvt_h2(sfA[2*jk][0]   - m0, sfA[2*jk][1]   - m0));
        ph[1] = ex2h2(cvt_h2(sfA[2*jk][2]   - m1, sfA[2*jk][3]   - m1));
        ph[2] = ex2h2(cvt_h2(sfA[2*jk+1][0] - m0, sfA[2*jk+1][1] - m0));
        ph[3] = ex2h2(cvt_h2(sfA[2*jk+1][2] - m1, sfA[2*jk+1][3] - m1));

        uint32_t vl[4], vh[2][4];
        ldsm4(vl, vb + (128 + brow) * 144 + jk * 32 + bcsel);
        ldsm4(vh[0], vb + brow * 144 + jk * 32 + bcsel);
        mma16816(ofl, ph, vl[0], vl[1]);
        #pragma unroll
        for (int np = 0; np < 8; np++) {
            const int cur = np & 1, nxt = cur ^ 1;
            if (np + 1 < 8)
                ldsm4(vh[nxt], vb + ((np+1)*16 + brow) * 144 + jk * 32 + bcsel);
            mma16816(of[2*np],   ph, vh[cur][0], vh[cur][1]);
            mma16816(of[2*np+1], ph, vh[cur][2], vh[cur][3]);
        }
    }

    CP_WAIT0();
    __syncthreads();
}

__global__ __launch_bounds__(256, 1) void flash_attn(float* __restrict__ out)
{
    extern __shared__ char sm[];
    const uint32_t smem = smem_u32(sm);
    const int tid = threadIdx.x;
    const int w = tid >> 5;
    const int l = tid & 31;
    const int b = blockIdx.y;
    const int qi0 = blockIdx.x * QT;

    {
        long long tok0 = (long long)b * SS + qi0;
        #pragma unroll
        for (int it = 0; it < 16; it++) {
            int ci = tid + it * 256;
            int c = ci & 15;
            int row = (ci >> 4) & 127;
            const __half* src = ((ci < 2048) ? g_qh : g_ql) + (tok0 + row) * DD + c * 8;
            uint32_t dst = smem + ((ci < 2048) ? OFF_QH : OFF_QL) + row * (QSTR*2) + c * 16;
            cp16(dst, src);
        }
    }
    for (int i = tid; i < 16 * 72; i += 256) {
        int r = 128 + i / 72, c = i % 72;
        __half v = (r == 128) ? __float2half_rn(1.0f) : __ushort_as_half(0);
        *(__half*)(sm + OFF_V + r * 144 + c * 2) = v;
        *(__half*)(sm + OFF_V + VBUF + r * 144 + c * 2) = v;
    }
    load_k(smem, b, 0, 0, tid);
    load_v(smem, b, 0, 0, tid);
    load_k(smem, b, 1, 1, tid);
    CP_COMMIT();
    CP_WAIT0();
    __syncthreads();

    float of[16][4], ofl[4];
    #pragma unroll
    for (int n = 0; n < 16; n++)
        #pragma unroll
        for (int c = 0; c < 4; c++) of[n][c] = 0.f;
    #pragma unroll
    for (int c = 0; c < 4; c++) ofl[c] = 0.f;
    float m0 = -INFINITY, m1 = -INFINITY;

    const uint32_t qoff  = smem + (w*16 + (l & 15)) * (QSTR*2) + ((l >> 4) * 16);
    const uint32_t brow  = (l & 7) + ((l >> 4) & 1) * 8;
    const uint32_t bcsel = ((l >> 3) & 1) * 16;

    uint32_t qfh[8][4];
    #pragma unroll
    for (int kc = 0; kc < 8; kc++)
        ldsm4(qfh[kc], qoff + OFF_QH + kc * 32);

    float sfA[8][4], sfB[8][4];
    compute_S(sfA, qfh, qoff, smem + OFF_K, brow, bcsel);
    __syncthreads();

    #pragma unroll 1
    for (int t = 0; t < NTILE; t += 2) {
        flash_iter(t,     sfA, sfB, of, ofl, qfh, qoff, m0, m1, smem, b, tid, brow, bcsel);
        flash_iter(t + 1, sfB, sfA, of, ofl, qfh, qoff, m0, m1, smem, b, tid, brow, bcsel);
    }

    float lt0 = __shfl_sync(0xffffffffu, ofl[0], l & 28);
    float lt1 = __shfl_sync(0xffffffffu, ofl[2], l & 28);

    const int row0 = w*16 + (l >> 2);
    const float inv0 = 1.0f / lt0, inv1 = 1.0f / lt1;
    long long base0 = ((long long)b * SS + qi0 + row0) * DD;
    long long base1 = base0 + 8LL * DD;
    #pragma unroll
    for (int n = 0; n < 16; n++) {
        int cc = n*8 + (l & 3)*2;
        *(float2*)(out + base0 + cc) = make_float2(of[n][0]*inv0, of[n][1]*inv0);
        *(float2*)(out + base1 + cc) = make_float2(of[n][2]*inv1, of[n][3]*inv1);
    }
}

// ============================================================================
// launch
// ============================================================================
extern "C" void kernel_launch(void* const* d_in, const int* in_sizes, int n_in,
                              void* d_out, int out_size)
{
    const float* x  = (const float*)d_in[0];
    const float* Wq = (const float*)d_in[1];
    const float* bq = (const float*)d_in[2];
    const float* Wk = (const float*)d_in[3];
    const float* bk = (const float*)d_in[4];
    const float* Wv = (const float*)d_in[5];
    const float* bv = (const float*)d_in[6];
    float* out = (float*)d_out;

    split_w<<<(3*DD*EE)/256, 256>>>(Wq, Wk, Wv);

    cudaFuncSetAttribute(qkv_mma, cudaFuncAttributeMaxDynamicSharedMemorySize,
                         QKV_SMEM);
    qkv_mma<<<MM/64, 256, QKV_SMEM>>>(x, bq, bk, bv);

    cudaFuncSetAttribute(flash_attn, cudaFuncAttributeMaxDynamicSharedMemorySize,
                         FLASH_SMEM);
    flash_attn<<<dim3(SS / QT, BB), 256, FLASH_SMEM>>>(out);
}